// round 1
// baseline (speedup 1.0000x reference)
#include <cuda_runtime.h>
#include <math.h>

// ---------------------------------------------------------------------------
// Problem constants
// ---------------------------------------------------------------------------
#define NROWS 4096          // B*SLEN = 4*1024
#define DIM   512           // ISIZE
#define MS    (4096*512)    // elements per activation buffer
#define NHEAD 8
#define DH    64
#define SLEN  1024
#define BB    4
#define EPSLN 1e-6f

// ---------------------------------------------------------------------------
// Device-resident input pointer table + route table
// ---------------------------------------------------------------------------
struct Ptrs {
    const float *inpute, *inputo, *node_p, *edge_p;
    const float *edge_W, *edge_b, *edge_g, *edge_beta;
    const float *node_W, *node_b, *node_g, *node_beta;
    const float *out_g, *out_beta;
};
__device__ Ptrs g_ptrs;

struct NR {
    int act; float aw;
    int q_in, q_op, q_e; float q_w;
    int k_valid, k_in, k_op, k_e; float k_w;
    int v_valid, v_in, v_op, v_e; float v_w;
};
__device__ NR  g_nr[8];
__device__ int g_processed[8];

// ---------------------------------------------------------------------------
// Scratch (device globals; no allocations allowed)
// ---------------------------------------------------------------------------
__device__ float g_outs[8 * MS];
__device__ float g_qv[MS], g_kv[MS], g_vv[MS], g_t0[MS];
__device__ float g_h0[MS], g_h1[MS], g_h2[MS];
__device__ float g_scores[32 * 1024 * 1024];  // B*H x S x S

// ---------------------------------------------------------------------------
// Small helpers
// ---------------------------------------------------------------------------
__device__ __forceinline__ const float* buf_in(int idx) {
    if (idx == 0) return g_ptrs.inpute;
    if (idx == 1) return g_ptrs.inputo;
    return g_outs + (size_t)(idx - 2) * MS;
}

__device__ __forceinline__ float geluf(float x) {
    float x3 = x * x * x;
    return 0.5f * x * (1.0f + tanhf(0.7978845608028654f * (x + 0.044715f * x3)));
}
__device__ __forceinline__ float sigmoidf_(float x) {
    return 1.0f / (1.0f + expf(-x));
}

__device__ __forceinline__ float blk_sum(float v) {
    __shared__ float sh[8];
    int lane = threadIdx.x & 31, w = threadIdx.x >> 5;
#pragma unroll
    for (int o = 16; o; o >>= 1) v += __shfl_xor_sync(0xffffffffu, v, o);
    if (lane == 0) sh[w] = v;
    __syncthreads();
    if (w == 0) {
        float r = (lane < 8) ? sh[lane] : 0.f;
#pragma unroll
        for (int o = 4; o; o >>= 1) r += __shfl_xor_sync(0xffffffffu, r, o);
        if (lane == 0) sh[0] = r;
    }
    __syncthreads();
    float out = sh[0];
    __syncthreads();
    return out;
}

__device__ __forceinline__ float blk_max(float v) {
    __shared__ float sh[8];
    int lane = threadIdx.x & 31, w = threadIdx.x >> 5;
#pragma unroll
    for (int o = 16; o; o >>= 1) v = fmaxf(v, __shfl_xor_sync(0xffffffffu, v, o));
    if (lane == 0) sh[w] = v;
    __syncthreads();
    if (w == 0) {
        float r = (lane < 8) ? sh[lane] : -3.4e38f;
#pragma unroll
        for (int o = 4; o; o >>= 1) r = fmaxf(r, __shfl_xor_sync(0xffffffffu, r, o));
        if (lane == 0) sh[0] = r;
    }
    __syncthreads();
    float out = sh[0];
    __syncthreads();
    return out;
}

// 256 threads: thread t owns elements t and t+256 of a 512-wide row.
__device__ __forceinline__ void ln_row_store(float s0, float s1, float* dst, int row,
                                             const float* gm, const float* bt, float scale) {
    int t = threadIdx.x;
    float mean = blk_sum(s0 + s1) * (1.0f / 512.0f);
    float d0 = s0 - mean, d1 = s1 - mean;
    float var = blk_sum(d0 * d0 + d1 * d1) * (1.0f / 512.0f);
    float inv = rsqrtf(var + EPSLN);
    size_t base = (size_t)row * DIM;
    dst[base + t]       = scale * (d0 * inv * gm[t] + bt[t]);
    dst[base + t + 256] = scale * (d1 * inv * gm[t + 256] + bt[t + 256]);
}

// ---------------------------------------------------------------------------
// Setup + routing
// ---------------------------------------------------------------------------
__global__ void setup_k(const float* a0, const float* a1, const float* a2, const float* a3,
                        const float* a4, const float* a5, const float* a6, const float* a7,
                        const float* a8, const float* a9, const float* a10, const float* a11,
                        const float* a12, const float* a13) {
    Ptrs p;
    p.inpute = a0; p.inputo = a1; p.node_p = a2; p.edge_p = a3;
    p.edge_W = a4; p.edge_b = a5; p.edge_g = a6; p.edge_beta = a7;
    p.node_W = a8; p.node_b = a9; p.node_g = a10; p.node_beta = a11;
    p.out_g = a12; p.out_beta = a13;
    g_ptrs = p;
}

__device__ int d_amax(const float* x, int n, int lo) {
    int bi = lo; float bv = x[lo];
    for (int i = lo + 1; i < n; i++) { if (x[i] > bv) { bv = x[i]; bi = i; } }
    return bi;
}
__device__ float d_smw(const float* x, int n, int lo, int sel) {
    float mx = x[lo];
    for (int i = lo + 1; i < n; i++) mx = fmaxf(mx, x[i]);
    float s = 0.f;
    for (int i = lo; i < n; i++) s += expf(x[i] - mx);
    return expf(x[sel] - mx) / s;
}

__global__ void routing_k() {
    if (threadIdx.x || blockIdx.x) return;
    const float* np = g_ptrs.node_p;   // (8, 8)
    const float* ep = g_ptrs.edge_p;   // (3, 34, 5) row-major
    for (int i = 0; i < 8; i++) g_processed[i] = 0;
    int lind = 0;
    for (int c = 0; c < 8; c++) {
        int nsrc = (c + 2 < 5) ? c + 2 : 5;
        int snode = c - nsrc;
        int n = nsrc * 5;
        const float* e0 = ep + 0 * 170 + lind * 5;
        const float* e1 = ep + 1 * 170 + lind * 5;
        const float* e2 = ep + 2 * 170 + lind * 5;
        NR r; r.k_valid = 0; r.v_valid = 0;
        r.k_in = 0; r.k_op = 4; r.k_e = 0; r.k_w = 0.f;
        r.v_in = 0; r.v_op = 4; r.v_e = 0; r.v_w = 0.f;

        int nact = d_amax(np + c * 8, 8, 0);
        r.act = nact;
        r.aw = d_smw(np + c * 8, 8, 0, nact);

        // q: source slot 0 (encoder) masked -> lo = 5
        int qs = d_amax(e0, n, 5);
        int qse = qs / 5;
        r.q_in = (qse == 0) ? 0 : (snode + qse + 2);
        r.q_op = qs % 5; r.q_e = lind + qse;
        r.q_w = d_smw(e0, n, 5, qs);
        if (r.q_in >= 2) g_processed[r.q_in - 2] = 1;

        if (nact < 7) {
            int lo = (nact > 0) ? 5 : 0;
            int ks = d_amax(e1, n, lo);
            int kse = ks / 5;
            r.k_valid = 1;
            r.k_in = (kse == 0) ? 0 : (snode + kse + 2);
            r.k_op = ks % 5; r.k_e = lind + kse;
            r.k_w = d_smw(e1, n, lo, ks);
            if (r.k_in >= 2) g_processed[r.k_in - 2] = 1;
            int ktype = (kse == 0) ? -2 : -1;
            if (nact < 5) {
                r.v_valid = 1;
                int vs, vlo, vn;
                if (nact == 0 && ktype == -2) { vlo = 0; vn = 5; }
                else if (nact > 0)            { vlo = 5; vn = n; }
                else                          { vlo = 0; vn = n; }
                vs = d_amax(e2, vn, vlo);
                int vse = vs / 5;
                r.v_in = (vse == 0) ? 0 : (snode + vse + 2);
                r.v_op = vs % 5; r.v_e = lind + vse;
                r.v_w = d_smw(e2, vn, vlo, vs);
                if (r.v_in >= 2) g_processed[r.v_in - 2] = 1;
            }
        }
        g_nr[c] = r;
        lind += nsrc;
    }
}

// ---------------------------------------------------------------------------
// Edge pre (LN for ops 0-2, copy*w for op 4)
// ---------------------------------------------------------------------------
__global__ void edge_pre(int node, int role) {
    NR r = g_nr[node];
    int valid, in, op, e; float w; float* out;
    if (role == 0)      { valid = 1;         in = r.q_in; op = r.q_op; e = r.q_e; w = r.q_w; out = g_qv; }
    else if (role == 1) { valid = r.k_valid; in = r.k_in; op = r.k_op; e = r.k_e; w = r.k_w; out = g_kv; }
    else                { valid = r.v_valid; in = r.v_in; op = r.v_op; e = r.v_e; w = r.v_w; out = g_vv; }
    if (!valid) return;
    int row = blockIdx.x, t = threadIdx.x;
    const float* x = buf_in(in);
    size_t p0 = (size_t)row * DIM + t, p1 = p0 + 256;
    if (op <= 2) {
        ln_row_store(x[p0], x[p1], g_t0, row,
                     g_ptrs.edge_g + e * DIM, g_ptrs.edge_beta + e * DIM, 1.0f);
    } else if (op == 4) {
        out[p0] = w * x[p0];
        out[p1] = w * x[p1];
    }
}

// ---------------------------------------------------------------------------
// node prep: act0 -> t0 = LN(qv)
// ---------------------------------------------------------------------------
__global__ void node_prep(int node) {
    NR r = g_nr[node];
    if (r.act != 0) return;
    int row = blockIdx.x, t = threadIdx.x;
    size_t p0 = (size_t)row * DIM + t, p1 = p0 + 256;
    ln_row_store(g_qv[p0], g_qv[p1], g_t0, row,
                 g_ptrs.node_g + node * DIM, g_ptrs.node_beta + node * DIM, 1.0f);
}

// ---------------------------------------------------------------------------
// Generic GEMM: out = scale * (res + act(X @ W + bias))
// M=4096, N=512, K=512 ; 128x128x8 tiles, 256 thr, 8x8/thread
// ---------------------------------------------------------------------------
struct GemmCfg {
    const float* X; const float* W; const float* Bv;
    int act;            // 0 none, 1 relu, 2 gelu
    float scale;
    const float* res;   // residual (added after act, before scale) or null
    float* out;
};

__device__ bool resolve_gemm(int node, int slot, GemmCfg& g) {
    NR r = g_nr[node];
    if (slot < 3) {
        int valid, in, op, e; float w; float* out;
        if (slot == 0)      { valid = 1;         in = r.q_in; op = r.q_op; e = r.q_e; w = r.q_w; out = g_qv; }
        else if (slot == 1) { valid = r.k_valid; in = r.k_in; op = r.k_op; e = r.k_e; w = r.k_w; out = g_kv; }
        else                { valid = r.v_valid; in = r.v_in; op = r.v_op; e = r.v_e; w = r.v_w; out = g_vv; }
        if (!valid || op == 4) return false;
        g.X = (op < 3) ? (const float*)g_t0 : buf_in(in);
        g.W = g_ptrs.edge_W + (size_t)e * DIM * DIM;
        g.Bv = g_ptrs.edge_b + e * DIM;
        g.act = (op == 0) ? 1 : (op == 1) ? 2 : 0;
        g.scale = w; g.res = nullptr; g.out = out;
        return true;
    }
    int a = r.act;
    int j = slot - 3;
    const float* W  = g_ptrs.node_W + ((size_t)node * 4 + j) * DIM * DIM;
    const float* Bv = g_ptrs.node_b + (node * 4 + j) * DIM;
    if (j == 0) {
        if (a == 0) { g = {g_t0, W, Bv,      0, 1.f, nullptr, g_h0}; return true; }
        if (a == 1) { g = {g_qv, W, Bv,      2, 1.f, nullptr, g_h0}; return true; }
        if (a == 3) { g = {g_qv, W, nullptr, 0, 1.f, nullptr, g_h0}; return true; }
        return false;
    }
    if (j == 1) {
        if (a == 0 || a == 1) { g = {g_kv, W, Bv,      0, 1.f, nullptr, g_h1}; return true; }
        if (a == 3)           { g = {g_kv, W, nullptr, 0, 1.f, nullptr, g_h1}; return true; }
        if (a == 5)           { g = {g_kv, W, Bv,      2, 1.f, nullptr, g_h1}; return true; }
        return false;
    }
    if (j == 2) {
        if (a == 0) { g = {g_vv, W, Bv,      0, 1.f, nullptr, g_h2}; return true; }
        if (a == 3) { g = {g_vv, W, nullptr, 0, 1.f, nullptr, g_h2}; return true; }
        return false;
    }
    // j == 3
    if (a == 0)           { g = {g_t0, W, Bv, 0, r.aw, g_qv, g_outs + (size_t)node * MS}; return true; }
    if (a == 1 || a == 3) { g = {g_h0, W, Bv, 0, r.aw, g_qv, g_outs + (size_t)node * MS}; return true; }
    return false;
}

__global__ void __launch_bounds__(256) gemm_big(int node, int slot) {
    GemmCfg g;
    if (!resolve_gemm(node, slot, g)) return;

    __shared__ float As[8][128];
    __shared__ float Bs[8][128];
    int t = threadIdx.x;
    int tx = t % 16, ty = t / 16;
    int m0 = blockIdx.y * 128, n0 = blockIdx.x * 128;

    float acc[8][8];
#pragma unroll
    for (int i = 0; i < 8; i++)
#pragma unroll
        for (int j = 0; j < 8; j++) acc[i][j] = 0.f;

    int ar = t / 2;            // 0..127
    int ac = (t % 2) * 4;      // 0 or 4
    int br = t / 32;           // 0..7
    int bc = (t % 32) * 4;     // 0..124

    const float* X = g.X;
    const float* W = g.W;

    for (int k0 = 0; k0 < DIM; k0 += 8) {
        float4 av = *(const float4*)(X + (size_t)(m0 + ar) * DIM + k0 + ac);
        float4 bv = *(const float4*)(W + (size_t)(k0 + br) * DIM + n0 + bc);
        As[ac + 0][ar] = av.x; As[ac + 1][ar] = av.y;
        As[ac + 2][ar] = av.z; As[ac + 3][ar] = av.w;
        *(float4*)&Bs[br][bc] = bv;
        __syncthreads();
#pragma unroll
        for (int kk = 0; kk < 8; kk++) {
            float4 a0 = *(float4*)&As[kk][ty * 8];
            float4 a1 = *(float4*)&As[kk][ty * 8 + 4];
            float4 b0 = *(float4*)&Bs[kk][tx * 8];
            float4 b1 = *(float4*)&Bs[kk][tx * 8 + 4];
            float a[8] = {a0.x, a0.y, a0.z, a0.w, a1.x, a1.y, a1.z, a1.w};
            float b[8] = {b0.x, b0.y, b0.z, b0.w, b1.x, b1.y, b1.z, b1.w};
#pragma unroll
            for (int i = 0; i < 8; i++)
#pragma unroll
                for (int j = 0; j < 8; j++) acc[i][j] += a[i] * b[j];
        }
        __syncthreads();
    }

#pragma unroll
    for (int i = 0; i < 8; i++) {
        int row = m0 + ty * 8 + i;
        size_t base = (size_t)row * DIM + n0 + tx * 8;
        float o[8];
#pragma unroll
        for (int j = 0; j < 8; j++) {
            int col = n0 + tx * 8 + j;
            float v = acc[i][j];
            if (g.Bv) v += g.Bv[col];
            if (g.act == 1)      v = fmaxf(v, 0.f);
            else if (g.act == 2) v = geluf(v);
            if (g.res) v += g.res[(size_t)row * DIM + col];
            o[j] = v * g.scale;
        }
        *(float4*)(g.out + base)     = make_float4(o[0], o[1], o[2], o[3]);
        *(float4*)(g.out + base + 4) = make_float4(o[4], o[5], o[6], o[7]);
    }
}

// ---------------------------------------------------------------------------
// Attention (act 0 only): scores = Qh Kh^T / 8 ; softmax ; O = P Vh -> g_t0
// ---------------------------------------------------------------------------
__global__ void attn_scores(int node) {
    if (g_nr[node].act != 0) return;
    int bh = blockIdx.z, b = bh >> 3, h = bh & 7;
    int i0 = blockIdx.y * 64, j0 = blockIdx.x * 64;
    int t = threadIdx.x, tx = t % 16, ty = t / 16;
    __shared__ float Qs[64][17], Ks[64][17];
    float acc[4][4];
#pragma unroll
    for (int i = 0; i < 4; i++)
#pragma unroll
        for (int j = 0; j < 4; j++) acc[i][j] = 0.f;

    const float* Q = g_h0 + (size_t)b * SLEN * DIM + h * DH;
    const float* K = g_h1 + (size_t)b * SLEN * DIM + h * DH;
    int r = t / 4, c = (t % 4) * 4;
    for (int d0 = 0; d0 < DH; d0 += 16) {
        float4 qv = *(const float4*)(Q + (size_t)(i0 + r) * DIM + d0 + c);
        float4 kv = *(const float4*)(K + (size_t)(j0 + r) * DIM + d0 + c);
        Qs[r][c] = qv.x; Qs[r][c + 1] = qv.y; Qs[r][c + 2] = qv.z; Qs[r][c + 3] = qv.w;
        Ks[r][c] = kv.x; Ks[r][c + 1] = kv.y; Ks[r][c + 2] = kv.z; Ks[r][c + 3] = kv.w;
        __syncthreads();
#pragma unroll
        for (int kk = 0; kk < 16; kk++) {
            float a[4], bb[4];
#pragma unroll
            for (int i = 0; i < 4; i++) a[i] = Qs[ty * 4 + i][kk];
#pragma unroll
            for (int j = 0; j < 4; j++) bb[j] = Ks[tx * 4 + j][kk];
#pragma unroll
            for (int i = 0; i < 4; i++)
#pragma unroll
                for (int j = 0; j < 4; j++) acc[i][j] += a[i] * bb[j];
        }
        __syncthreads();
    }
    float* S = g_scores + (size_t)bh * SLEN * SLEN;
#pragma unroll
    for (int i = 0; i < 4; i++) {
        size_t base = (size_t)(i0 + ty * 4 + i) * SLEN + j0 + tx * 4;
        *(float4*)(S + base) = make_float4(acc[i][0] * 0.125f, acc[i][1] * 0.125f,
                                           acc[i][2] * 0.125f, acc[i][3] * 0.125f);
    }
}

__global__ void attn_softmax(int node) {
    if (g_nr[node].act != 0) return;
    size_t row = blockIdx.x;
    float* S = g_scores + row * SLEN;
    int t = threadIdx.x;
    float v[4];
#pragma unroll
    for (int l = 0; l < 4; l++) v[l] = S[t + 256 * l];
    float m = fmaxf(fmaxf(v[0], v[1]), fmaxf(v[2], v[3]));
    m = blk_max(m);
    float e[4], s = 0.f;
#pragma unroll
    for (int l = 0; l < 4; l++) { e[l] = expf(v[l] - m); s += e[l]; }
    float tot = blk_sum(s);
    float inv = 1.0f / tot;
#pragma unroll
    for (int l = 0; l < 4; l++) S[t + 256 * l] = e[l] * inv;
}

__global__ void attn_o(int node) {
    if (g_nr[node].act != 0) return;
    int bh = blockIdx.y, b = bh >> 3, h = bh & 7;
    int i0 = blockIdx.x * 64;
    int t = threadIdx.x, tx = t % 16, ty = t / 16;
    __shared__ float Ps[64][17], Vs[16][65];
    float acc[4][4];
#pragma unroll
    for (int i = 0; i < 4; i++)
#pragma unroll
        for (int j = 0; j < 4; j++) acc[i][j] = 0.f;

    const float* S = g_scores + (size_t)bh * SLEN * SLEN;
    const float* V = g_h2 + (size_t)b * SLEN * DIM + h * DH;
    int pr = t / 4, pc = (t % 4) * 4;
    int vr = t / 16, vc = (t % 16) * 4;
    for (int j0 = 0; j0 < SLEN; j0 += 16) {
        float4 pv = *(const float4*)(S + (size_t)(i0 + pr) * SLEN + j0 + pc);
        Ps[pr][pc] = pv.x; Ps[pr][pc + 1] = pv.y; Ps[pr][pc + 2] = pv.z; Ps[pr][pc + 3] = pv.w;
        float4 vv = *(const float4*)(V + (size_t)(j0 + vr) * DIM + vc);
        Vs[vr][vc] = vv.x; Vs[vr][vc + 1] = vv.y; Vs[vr][vc + 2] = vv.z; Vs[vr][vc + 3] = vv.w;
        __syncthreads();
#pragma unroll
        for (int kk = 0; kk < 16; kk++) {
            float a[4], bb[4];
#pragma unroll
            for (int i = 0; i < 4; i++) a[i] = Ps[ty * 4 + i][kk];
#pragma unroll
            for (int j = 0; j < 4; j++) bb[j] = Vs[kk][tx * 4 + j];
#pragma unroll
            for (int i = 0; i < 4; i++)
#pragma unroll
                for (int j = 0; j < 4; j++) acc[i][j] += a[i] * bb[j];
        }
        __syncthreads();
    }
    float* O = g_t0 + (size_t)b * SLEN * DIM + h * DH;
#pragma unroll
    for (int i = 0; i < 4; i++) {
        size_t base = (size_t)(i0 + ty * 4 + i) * DIM + tx * 4;
        *(float4*)(O + base) = make_float4(acc[i][0], acc[i][1], acc[i][2], acc[i][3]);
    }
}

// ---------------------------------------------------------------------------
// Elementwise combine (act1: h0*=h1 ; act3: h0=relu(h0+h1+h2))
// ---------------------------------------------------------------------------
__global__ void combine_k(int node) {
    int a = g_nr[node].act;
    if (a != 1 && a != 3) return;
    size_t stride = (size_t)gridDim.x * blockDim.x;
    for (size_t p = (size_t)blockIdx.x * blockDim.x + threadIdx.x; p < (size_t)MS; p += stride) {
        if (a == 1) g_h0[p] = g_h0[p] * g_h1[p];
        else        g_h0[p] = fmaxf(g_h0[p] + g_h1[p] + g_h2[p], 0.f);
    }
}

// ---------------------------------------------------------------------------
// Elementwise finish (acts 2,4,5,6,7)
// ---------------------------------------------------------------------------
__global__ void finish_k(int node) {
    NR r = g_nr[node];
    int a = r.act;
    if (a == 0 || a == 1 || a == 3) return;
    int row = blockIdx.x, t = threadIdx.x;
    float* out = g_outs + (size_t)node * MS;
    size_t p0 = (size_t)row * DIM + t, p1 = p0 + 256;
    if (a == 2) {
        float s0 = g_qv[p0] + g_kv[p0] + g_vv[p0];
        float s1 = g_qv[p1] + g_kv[p1] + g_vv[p1];
        ln_row_store(s0, s1, out, row,
                     g_ptrs.node_g + node * DIM, g_ptrs.node_beta + node * DIM, r.aw);
    } else if (a == 4) {
        out[p0] = r.aw * (g_qv[p0] * sigmoidf_(g_kv[p0]) + g_vv[p0]);
        out[p1] = r.aw * (g_qv[p1] * sigmoidf_(g_kv[p1]) + g_vv[p1]);
    } else if (a == 5) {
        out[p0] = r.aw * (g_qv[p0] + g_h1[p0]);
        out[p1] = r.aw * (g_qv[p1] + g_h1[p1]);
    } else if (a == 6) {
        out[p0] = r.aw * (g_qv[p0] + g_kv[p0]);
        out[p1] = r.aw * (g_qv[p1] + g_kv[p1]);
    } else { // 7
        ln_row_store(g_qv[p0], g_qv[p1], out, row,
                     g_ptrs.node_g + node * DIM, g_ptrs.node_beta + node * DIM, r.aw);
    }
}

// ---------------------------------------------------------------------------
// Final: sum unprocessed outs, LN with out_g/out_beta -> d_out
// ---------------------------------------------------------------------------
__global__ void final_k(float* dout) {
    int row = blockIdx.x, t = threadIdx.x;
    size_t p0 = (size_t)row * DIM + t, p1 = p0 + 256;
    float s0 = 0.f, s1 = 0.f;
    for (int c = 0; c < 8; c++) {
        if (!g_processed[c]) {
            s0 += g_outs[(size_t)c * MS + p0];
            s1 += g_outs[(size_t)c * MS + p1];
        }
    }
    ln_row_store(s0, s1, dout, row, g_ptrs.out_g, g_ptrs.out_beta, 1.0f);
}

// ---------------------------------------------------------------------------
// Launch
// ---------------------------------------------------------------------------
extern "C" void kernel_launch(void* const* d_in, const int* in_sizes, int n_in,
                              void* d_out, int out_size) {
    (void)in_sizes; (void)n_in; (void)out_size;
    setup_k<<<1, 1>>>(
        (const float*)d_in[0],  (const float*)d_in[1],  (const float*)d_in[2],
        (const float*)d_in[3],  (const float*)d_in[4],  (const float*)d_in[5],
        (const float*)d_in[6],  (const float*)d_in[7],  (const float*)d_in[8],
        (const float*)d_in[9],  (const float*)d_in[10], (const float*)d_in[11],
        (const float*)d_in[12], (const float*)d_in[13]);
    routing_k<<<1, 1>>>();

    dim3 gemm_grid(DIM / 128, NROWS / 128);   // (4, 32)
    for (int c = 0; c < 8; c++) {
        for (int role = 0; role < 3; role++) {
            edge_pre<<<NROWS, 256>>>(c, role);
            gemm_big<<<gemm_grid, 256>>>(c, role);
        }
        node_prep<<<NROWS, 256>>>(c);
        gemm_big<<<gemm_grid, 256>>>(c, 3);
        gemm_big<<<gemm_grid, 256>>>(c, 4);
        gemm_big<<<gemm_grid, 256>>>(c, 5);
        attn_scores<<<dim3(16, 16, 32), 256>>>(c);
        attn_softmax<<<32 * SLEN, 256>>>(c);
        attn_o<<<dim3(16, 32), 256>>>(c);
        combine_k<<<2048, 256>>>(c);
        gemm_big<<<gemm_grid, 256>>>(c, 6);
        finish_k<<<NROWS, 256>>>(c);
    }
    final_k<<<NROWS, 256>>>((float*)d_out);
}

// round 3
// speedup vs baseline: 1.8407x; 1.8407x over previous
#include <cuda_runtime.h>
#include <cuda_bf16.h>
#include <math.h>
#include <stdint.h>

// ---------------------------------------------------------------------------
// Problem constants
// ---------------------------------------------------------------------------
#define NROWS 4096          // B*SLEN = 4*1024
#define DIM   512           // ISIZE
#define MS    (4096*512)    // elements per activation buffer
#define NHEAD 8
#define DH    64
#define SLEN  1024
#define BB    4
#define EPSLN 1e-6f

// ---------------------------------------------------------------------------
// Device-resident input pointer table + route table
// ---------------------------------------------------------------------------
struct Ptrs {
    const float *inpute, *inputo, *node_p, *edge_p;
    const float *edge_W, *edge_b, *edge_g, *edge_beta;
    const float *node_W, *node_b, *node_g, *node_beta;
    const float *out_g, *out_beta;
};
__device__ Ptrs g_ptrs;

struct NR {
    int act; float aw;
    int q_in, q_op, q_e; float q_w;
    int k_valid, k_in, k_op, k_e; float k_w;
    int v_valid, v_in, v_op, v_e; float v_w;
};
__device__ NR  g_nr[8];
__device__ int g_processed[8];

// ---------------------------------------------------------------------------
// Scratch (device globals; no allocations allowed)
// ---------------------------------------------------------------------------
__device__ float g_outs[8 * MS];
__device__ float g_qv[MS], g_kv[MS], g_vv[MS], g_t0[MS];
__device__ float g_h0[MS], g_h1[MS], g_h2[MS];
__device__ float g_e0[MS], g_e1[MS], g_e2[MS];   // per-role edge LN staging
__device__ __align__(16) __nv_bfloat16 g_Wth[8 * 7 * DIM * DIM];  // W^T hi bf16 [node][slot][n][k]
__device__ __align__(16) __nv_bfloat16 g_Wtl[8 * 7 * DIM * DIM];  // W^T lo
__device__ float g_scores[32u * 1024u * 1024u]; // B*H x S x S

// ---------------------------------------------------------------------------
// Small helpers
// ---------------------------------------------------------------------------
__device__ __forceinline__ const float* buf_in(int idx) {
    if (idx == 0) return g_ptrs.inpute;
    if (idx == 1) return g_ptrs.inputo;
    return g_outs + (size_t)(idx - 2) * MS;
}

__device__ __forceinline__ float geluf(float x) {
    float x3 = x * x * x;
    return 0.5f * x * (1.0f + tanhf(0.7978845608028654f * (x + 0.044715f * x3)));
}
__device__ __forceinline__ float sigmoidf_(float x) {
    return 1.0f / (1.0f + expf(-x));
}

__device__ __forceinline__ float blk_sum(float v) {
    __shared__ float sh[8];
    int lane = threadIdx.x & 31, w = threadIdx.x >> 5;
#pragma unroll
    for (int o = 16; o; o >>= 1) v += __shfl_xor_sync(0xffffffffu, v, o);
    if (lane == 0) sh[w] = v;
    __syncthreads();
    if (w == 0) {
        float r = (lane < 8) ? sh[lane] : 0.f;
#pragma unroll
        for (int o = 4; o; o >>= 1) r += __shfl_xor_sync(0xffffffffu, r, o);
        if (lane == 0) sh[0] = r;
    }
    __syncthreads();
    float out = sh[0];
    __syncthreads();
    return out;
}

__device__ __forceinline__ float blk_max(float v) {
    __shared__ float sh[8];
    int lane = threadIdx.x & 31, w = threadIdx.x >> 5;
#pragma unroll
    for (int o = 16; o; o >>= 1) v = fmaxf(v, __shfl_xor_sync(0xffffffffu, v, o));
    if (lane == 0) sh[w] = v;
    __syncthreads();
    if (w == 0) {
        float r = (lane < 8) ? sh[lane] : -3.4e38f;
#pragma unroll
        for (int o = 4; o; o >>= 1) r = fmaxf(r, __shfl_xor_sync(0xffffffffu, r, o));
        if (lane == 0) sh[0] = r;
    }
    __syncthreads();
    float out = sh[0];
    __syncthreads();
    return out;
}

// 256 threads: thread t owns elements t and t+256 of a 512-wide row.
__device__ __forceinline__ void ln_row_store(float s0, float s1, float* dst, int row,
                                             const float* gm, const float* bt, float scale) {
    int t = threadIdx.x;
    float mean = blk_sum(s0 + s1) * (1.0f / 512.0f);
    float d0 = s0 - mean, d1 = s1 - mean;
    float var = blk_sum(d0 * d0 + d1 * d1) * (1.0f / 512.0f);
    float inv = rsqrtf(var + EPSLN);
    size_t base = (size_t)row * DIM;
    dst[base + t]       = scale * (d0 * inv * gm[t] + bt[t]);
    dst[base + t + 256] = scale * (d1 * inv * gm[t + 256] + bt[t + 256]);
}

// ---------------------------------------------------------------------------
// mma.sync / ldmatrix helpers (baseline PTX, sm_80+ -> legal at compute_103)
// ---------------------------------------------------------------------------
__device__ __forceinline__ uint32_t smem_u32(const void* p) {
    uint32_t a;
    asm("{ .reg .u64 t; cvta.to.shared.u64 t, %1; cvt.u32.u64 %0, t; }" : "=r"(a) : "l"(p));
    return a;
}

__device__ __forceinline__ void ldm4(uint32_t addr, uint32_t r[4]) {
    asm volatile("ldmatrix.sync.aligned.m8n8.x4.shared.b16 {%0,%1,%2,%3}, [%4];"
                 : "=r"(r[0]), "=r"(r[1]), "=r"(r[2]), "=r"(r[3]) : "r"(addr));
}
__device__ __forceinline__ void ldm4t(uint32_t addr, uint32_t r[4]) {
    asm volatile("ldmatrix.sync.aligned.m8n8.x4.trans.shared.b16 {%0,%1,%2,%3}, [%4];"
                 : "=r"(r[0]), "=r"(r[1]), "=r"(r[2]), "=r"(r[3]) : "r"(addr));
}
__device__ __forceinline__ void mma16816(float c[4], const uint32_t a[4],
                                         uint32_t b0, uint32_t b1) {
    asm volatile(
        "mma.sync.aligned.m16n8k16.row.col.f32.bf16.bf16.f32 "
        "{%0,%1,%2,%3}, {%4,%5,%6,%7}, {%8,%9}, {%0,%1,%2,%3};"
        : "+f"(c[0]), "+f"(c[1]), "+f"(c[2]), "+f"(c[3])
        : "r"(a[0]), "r"(a[1]), "r"(a[2]), "r"(a[3]), "r"(b0), "r"(b1));
}

#define SW128(o) ((o) ^ (((o) >> 3) & 0x70))

__device__ __forceinline__ uint32_t pack_bf2(float x, float y) {
    __nv_bfloat162 h = __float22bfloat162_rn(make_float2(x, y)); // .x = low half
    return *(uint32_t*)&h;
}
// convert float4 -> hi uint2 / lo uint2
__device__ __forceinline__ void cvt_hilo(float4 v, uint2& hi, uint2& lo) {
    hi = make_uint2(pack_bf2(v.x, v.y), pack_bf2(v.z, v.w));
    __nv_bfloat162 h0 = *(__nv_bfloat162*)&hi.x;
    __nv_bfloat162 h1 = *(__nv_bfloat162*)&hi.y;
    float lx = v.x - __bfloat162float(h0.x);
    float ly = v.y - __bfloat162float(h0.y);
    float lz = v.z - __bfloat162float(h1.x);
    float lw = v.w - __bfloat162float(h1.y);
    lo = make_uint2(pack_bf2(lx, ly), pack_bf2(lz, lw));
}

// ---------------------------------------------------------------------------
// Setup + routing
// ---------------------------------------------------------------------------
__global__ void setup_k(const float* a0, const float* a1, const float* a2, const float* a3,
                        const float* a4, const float* a5, const float* a6, const float* a7,
                        const float* a8, const float* a9, const float* a10, const float* a11,
                        const float* a12, const float* a13) {
    Ptrs p;
    p.inpute = a0; p.inputo = a1; p.node_p = a2; p.edge_p = a3;
    p.edge_W = a4; p.edge_b = a5; p.edge_g = a6; p.edge_beta = a7;
    p.node_W = a8; p.node_b = a9; p.node_g = a10; p.node_beta = a11;
    p.out_g = a12; p.out_beta = a13;
    g_ptrs = p;
}

__device__ int d_amax(const float* x, int n, int lo) {
    int bi = lo; float bv = x[lo];
    for (int i = lo + 1; i < n; i++) { if (x[i] > bv) { bv = x[i]; bi = i; } }
    return bi;
}
__device__ float d_smw(const float* x, int n, int lo, int sel) {
    float mx = x[lo];
    for (int i = lo + 1; i < n; i++) mx = fmaxf(mx, x[i]);
    float s = 0.f;
    for (int i = lo; i < n; i++) s += expf(x[i] - mx);
    return expf(x[sel] - mx) / s;
}

__global__ void routing_k() {
    if (threadIdx.x || blockIdx.x) return;
    const float* np = g_ptrs.node_p;   // (8, 8)
    const float* ep = g_ptrs.edge_p;   // (3, 34, 5)
    for (int i = 0; i < 8; i++) g_processed[i] = 0;
    int lind = 0;
    for (int c = 0; c < 8; c++) {
        int nsrc = (c + 2 < 5) ? c + 2 : 5;
        int snode = c - nsrc;
        int n = nsrc * 5;
        const float* e0 = ep + 0 * 170 + lind * 5;
        const float* e1 = ep + 1 * 170 + lind * 5;
        const float* e2 = ep + 2 * 170 + lind * 5;
        NR r; r.k_valid = 0; r.v_valid = 0;
        r.k_in = 0; r.k_op = 4; r.k_e = 0; r.k_w = 0.f;
        r.v_in = 0; r.v_op = 4; r.v_e = 0; r.v_w = 0.f;

        int nact = d_amax(np + c * 8, 8, 0);
        r.act = nact;
        r.aw = d_smw(np + c * 8, 8, 0, nact);

        int qs = d_amax(e0, n, 5);
        int qse = qs / 5;
        r.q_in = (qse == 0) ? 0 : (snode + qse + 2);
        r.q_op = qs % 5; r.q_e = lind + qse;
        r.q_w = d_smw(e0, n, 5, qs);
        if (r.q_in >= 2) g_processed[r.q_in - 2] = 1;

        if (nact < 7) {
            int lo = (nact > 0) ? 5 : 0;
            int ks = d_amax(e1, n, lo);
            int kse = ks / 5;
            r.k_valid = 1;
            r.k_in = (kse == 0) ? 0 : (snode + kse + 2);
            r.k_op = ks % 5; r.k_e = lind + kse;
            r.k_w = d_smw(e1, n, lo, ks);
            if (r.k_in >= 2) g_processed[r.k_in - 2] = 1;
            int ktype = (kse == 0) ? -2 : -1;
            if (nact < 5) {
                r.v_valid = 1;
                int vs, vlo, vn;
                if (nact == 0 && ktype == -2) { vlo = 0; vn = 5; }
                else if (nact > 0)            { vlo = 5; vn = n; }
                else                          { vlo = 0; vn = n; }
                vs = d_amax(e2, vn, vlo);
                int vse = vs / 5;
                r.v_in = (vse == 0) ? 0 : (snode + vse + 2);
                r.v_op = vs % 5; r.v_e = lind + vse;
                r.v_w = d_smw(e2, vn, vlo, vs);
                if (r.v_in >= 2) g_processed[r.v_in - 2] = 1;
            }
        }
        g_nr[c] = r;
        lind += nsrc;
    }
}

// ---------------------------------------------------------------------------
// Weight selection (routing-only) for slot 0..6
// ---------------------------------------------------------------------------
__device__ const float* resolve_w(int node, int slot) {
    NR r = g_nr[node];
    if (slot < 3) {
        int valid, op, e;
        if (slot == 0)      { valid = 1;         op = r.q_op; e = r.q_e; }
        else if (slot == 1) { valid = r.k_valid; op = r.k_op; e = r.k_e; }
        else                { valid = r.v_valid; op = r.v_op; e = r.v_e; }
        if (valid && op <= 3) return g_ptrs.edge_W + (size_t)e * DIM * DIM;
        return nullptr;
    }
    int a = r.act, j = slot - 3;
    bool need =
        (j == 0 && (a == 0 || a == 1 || a == 3)) ||
        (j == 1 && (a == 0 || a == 1 || a == 3 || a == 5)) ||
        (j == 2 && (a == 0 || a == 3)) ||
        (j == 3 && (a == 0 || a == 1 || a == 3));
    if (need) return g_ptrs.node_W + ((size_t)node * 4 + j) * DIM * DIM;
    return nullptr;
}

// Convert+transpose all needed W into bf16 hi/lo scratch.  grid (16,16,56) block (32,8)
__global__ void conv_w_all() {
    int z = blockIdx.z; int node = z / 7, slot = z % 7;
    const float* W = resolve_w(node, slot);
    if (!W) return;
    __shared__ float tile[32][33];
    int n0 = blockIdx.x * 32, k0 = blockIdx.y * 32;
    int tx = threadIdx.x, ty = threadIdx.y;
#pragma unroll
    for (int dy = 0; dy < 4; dy++)
        tile[ty * 4 + dy][tx] = W[(size_t)(k0 + ty * 4 + dy) * DIM + n0 + tx];
    __syncthreads();
    size_t base = (size_t)z * DIM * DIM;
#pragma unroll
    for (int dy = 0; dy < 4; dy++) {
        int n = n0 + ty * 4 + dy, k = k0 + tx;
        float v = tile[tx][ty * 4 + dy];
        __nv_bfloat16 h = __float2bfloat16_rn(v);
        __nv_bfloat16 l = __float2bfloat16_rn(v - __bfloat162float(h));
        g_Wth[base + (size_t)n * DIM + k] = h;
        g_Wtl[base + (size_t)n * DIM + k] = l;
    }
}

// ---------------------------------------------------------------------------
// Edge pre (LN for ops 0-2 into per-role buffer, copy*w for op 4)  grid (NROWS,3)
// ---------------------------------------------------------------------------
__global__ void edge_pre(int node) {
    int role = blockIdx.y;
    NR r = g_nr[node];
    int valid, in, op, e; float w; float* out; float* lnb;
    if (role == 0)      { valid = 1;         in = r.q_in; op = r.q_op; e = r.q_e; w = r.q_w; out = g_qv; lnb = g_e0; }
    else if (role == 1) { valid = r.k_valid; in = r.k_in; op = r.k_op; e = r.k_e; w = r.k_w; out = g_kv; lnb = g_e1; }
    else                { valid = r.v_valid; in = r.v_in; op = r.v_op; e = r.v_e; w = r.v_w; out = g_vv; lnb = g_e2; }
    if (!valid) return;
    int row = blockIdx.x, t = threadIdx.x;
    const float* x = buf_in(in);
    size_t p0 = (size_t)row * DIM + t, p1 = p0 + 256;
    if (op <= 2) {
        ln_row_store(x[p0], x[p1], lnb, row,
                     g_ptrs.edge_g + e * DIM, g_ptrs.edge_beta + e * DIM, 1.0f);
    } else if (op == 4) {
        out[p0] = w * x[p0];
        out[p1] = w * x[p1];
    }
}

// ---------------------------------------------------------------------------
// node prep: act0 -> t0 = LN(qv)
// ---------------------------------------------------------------------------
__global__ void node_prep(int node) {
    NR r = g_nr[node];
    if (r.act != 0) return;
    int row = blockIdx.x, t = threadIdx.x;
    size_t p0 = (size_t)row * DIM + t, p1 = p0 + 256;
    ln_row_store(g_qv[p0], g_qv[p1], g_t0, row,
                 g_ptrs.node_g + node * DIM, g_ptrs.node_beta + node * DIM, 1.0f);
}

// ---------------------------------------------------------------------------
// GEMM config resolution
// ---------------------------------------------------------------------------
struct GemmCfg {
    const float* X; const float* Bv;
    int act;            // 0 none, 1 relu, 2 gelu
    float scale;
    const float* res;
    float* out;
};

__device__ bool resolve_gemm(int node, int slot, GemmCfg& g) {
    NR r = g_nr[node];
    if (slot < 3) {
        int valid, in, op, e; float w; float* out; const float* lnb;
        if (slot == 0)      { valid = 1;         in = r.q_in; op = r.q_op; e = r.q_e; w = r.q_w; out = g_qv; lnb = g_e0; }
        else if (slot == 1) { valid = r.k_valid; in = r.k_in; op = r.k_op; e = r.k_e; w = r.k_w; out = g_kv; lnb = g_e1; }
        else                { valid = r.v_valid; in = r.v_in; op = r.v_op; e = r.v_e; w = r.v_w; out = g_vv; lnb = g_e2; }
        if (!valid || op == 4) return false;
        g.X = (op < 3) ? lnb : buf_in(in);
        g.Bv = g_ptrs.edge_b + e * DIM;
        g.act = (op == 0) ? 1 : (op == 1) ? 2 : 0;
        g.scale = w; g.res = nullptr; g.out = out;
        return true;
    }
    int a = r.act;
    int j = slot - 3;
    const float* Bv = g_ptrs.node_b + (node * 4 + j) * DIM;
    if (j == 0) {
        if (a == 0) { g = {g_t0, Bv,      0, 1.f, nullptr, g_h0}; return true; }
        if (a == 1) { g = {g_qv, Bv,      2, 1.f, nullptr, g_h0}; return true; }
        if (a == 3) { g = {g_qv, nullptr, 0, 1.f, nullptr, g_h0}; return true; }
        return false;
    }
    if (j == 1) {
        if (a == 0 || a == 1) { g = {g_kv, Bv,      0, 1.f, nullptr, g_h1}; return true; }
        if (a == 3)           { g = {g_kv, nullptr, 0, 1.f, nullptr, g_h1}; return true; }
        if (a == 5)           { g = {g_kv, Bv,      2, 1.f, nullptr, g_h1}; return true; }
        return false;
    }
    if (j == 2) {
        if (a == 0) { g = {g_vv, Bv,      0, 1.f, nullptr, g_h2}; return true; }
        if (a == 3) { g = {g_vv, nullptr, 0, 1.f, nullptr, g_h2}; return true; }
        return false;
    }
    if (a == 0)           { g = {g_t0, Bv, 0, r.aw, g_qv, g_outs + (size_t)node * MS}; return true; }
    if (a == 1 || a == 3) { g = {g_h0, Bv, 0, r.aw, g_qv, g_outs + (size_t)node * MS}; return true; }
    return false;
}

// ---------------------------------------------------------------------------
// mma.sync split-bf16 GEMM: out = scale * (res + act(X @ W + bias))
// M=4096, N=512, K=512 ; CTA tile 128x128 ; 8 warps (32x64 each) ; KC=64
// smem: A_hi 16K | A_lo 16K | B_hi 16K | B_lo 16K = 64KB
// ---------------------------------------------------------------------------
#define GEMM_SMEM 65536

__global__ void __launch_bounds__(256) gemm_mma(int node, int base_slot) {
    int slot = base_slot + blockIdx.z;
    GemmCfg g;
    if (!resolve_gemm(node, slot, g)) return;

    extern __shared__ char smem[];
    uint32_t sA_H = smem_u32(smem);
    uint32_t sA_L = sA_H + 16384, sB_H = sA_H + 32768, sB_L = sA_H + 49152;

    int t = threadIdx.x, lane = t & 31, wid = t >> 5;
    int m0 = blockIdx.y * 128, n0 = blockIdx.x * 128;
    int wm = (wid & 3) * 32, wn = (wid >> 2) * 64;

    size_t wbase = ((size_t)node * 7 + slot) * DIM * DIM;
    const __nv_bfloat16* Wh = g_Wth + wbase;
    const __nv_bfloat16* Wl = g_Wtl + wbase;

    float acc[2][8][4];
#pragma unroll
    for (int i = 0; i < 2; i++)
#pragma unroll
        for (int j = 0; j < 8; j++)
#pragma unroll
            for (int l = 0; l < 4; l++) acc[i][j][l] = 0.f;

    // per-thread load coords: row = t>>1 (0..127), colblock = (t&1)*32
    int lrow = t >> 1, lcb = (t & 1) * 32;
    const float* Xr = g.X + (size_t)(m0 + lrow) * DIM + lcb;
    const __nv_bfloat16* Bhr = Wh + (size_t)(n0 + lrow) * DIM + lcb;
    const __nv_bfloat16* Blr = Wl + (size_t)(n0 + lrow) * DIM + lcb;

    // ldmatrix lane-address components
    int a_r  = (lane & 15);                 // row within 16
    int a_k8 = (lane >> 4) << 3;            // 0 or 8 (k offset)
    int b_n  = ((lane & 16) >> 1) + (lane & 7);  // 0..15 (n offset within group)
    int b_k8 = (lane & 8);                  // 0 or 8

    for (int kc = 0; kc < 8; kc++) {
        int k0 = kc * 64;
        // --- A fill (fp32 -> bf16 hi/lo, swizzled)
#pragma unroll
        for (int i = 0; i < 8; i++) {
            float4 v = *(const float4*)(Xr + k0 + i * 4);
            uint2 hi, lo; cvt_hilo(v, hi, lo);
            uint32_t off = SW128((uint32_t)(lrow * 128 + (lcb + i * 4) * 2));
            *(uint2*)(smem + off) = hi;                    // A_H region at base
            *(uint2*)(smem + 16384 + off) = lo;            // A_L
        }
        // --- B fill (bf16 copy, swizzled)
#pragma unroll
        for (int i = 0; i < 4; i++) {
            uint4 vh = *(const uint4*)(Bhr + k0 + i * 8);
            uint4 vl = *(const uint4*)(Blr + k0 + i * 8);
            uint32_t off = SW128((uint32_t)(lrow * 128 + (lcb + i * 8) * 2));
            *(uint4*)(smem + 32768 + off) = vh;            // B_H
            *(uint4*)(smem + 49152 + off) = vl;            // B_L
        }
        __syncthreads();

#pragma unroll
        for (int kt = 0; kt < 4; kt++) {
            int kb = kt * 16;
            uint32_t ah[2][4], al[2][4];
#pragma unroll
            for (int mt = 0; mt < 2; mt++) {
                uint32_t off = SW128((uint32_t)((wm + mt * 16 + a_r) * 128 + (kb + a_k8) * 2));
                ldm4(sA_H + off, ah[mt]);
                ldm4(sA_L + off, al[mt]);
            }
#pragma unroll
            for (int ng = 0; ng < 4; ng++) {
                uint32_t boff = SW128((uint32_t)((wn + ng * 16 + b_n) * 128 + (kb + b_k8) * 2));
                uint32_t bh4[4], bl4[4];
                ldm4(sB_H + boff, bh4);
                ldm4(sB_L + boff, bl4);
#pragma unroll
                for (int mt = 0; mt < 2; mt++) {
                    mma16816(acc[mt][2 * ng],     ah[mt], bh4[0], bh4[1]);
                    mma16816(acc[mt][2 * ng + 1], ah[mt], bh4[2], bh4[3]);
                    mma16816(acc[mt][2 * ng],     ah[mt], bl4[0], bl4[1]);
                    mma16816(acc[mt][2 * ng + 1], ah[mt], bl4[2], bl4[3]);
                    mma16816(acc[mt][2 * ng],     al[mt], bh4[0], bh4[1]);
                    mma16816(acc[mt][2 * ng + 1], al[mt], bh4[2], bh4[3]);
                }
            }
        }
        __syncthreads();
    }

    // --- epilogue
#pragma unroll
    for (int mt = 0; mt < 2; mt++) {
        int r0 = m0 + wm + mt * 16 + (lane >> 2);
#pragma unroll
        for (int nt = 0; nt < 8; nt++) {
            int col = n0 + wn + nt * 8 + (lane & 3) * 2;
#pragma unroll
            for (int h = 0; h < 2; h++) {   // h=0: rows r0 ; h=1: r0+8
                int row = r0 + h * 8;
                float v0 = acc[mt][nt][h * 2], v1 = acc[mt][nt][h * 2 + 1];
                if (g.Bv) { v0 += g.Bv[col]; v1 += g.Bv[col + 1]; }
                if (g.act == 1)      { v0 = fmaxf(v0, 0.f); v1 = fmaxf(v1, 0.f); }
                else if (g.act == 2) { v0 = geluf(v0); v1 = geluf(v1); }
                if (g.res) {
                    v0 += g.res[(size_t)row * DIM + col];
                    v1 += g.res[(size_t)row * DIM + col + 1];
                }
                *(float2*)(g.out + (size_t)row * DIM + col) =
                    make_float2(v0 * g.scale, v1 * g.scale);
            }
        }
    }
}

// ---------------------------------------------------------------------------
// Attention scores via mma: S = (Q K^T) / 8  ; CTA tile 128(i)x128(j), K=64
// grid (8, 8, 32) block 256 ; smem 64KB (Q_hi/Q_lo/K_hi/K_lo 16KB each)
// ---------------------------------------------------------------------------
__global__ void __launch_bounds__(256) sc_mma(int node) {
    if (g_nr[node].act != 0) return;
    extern __shared__ char smem[];
    uint32_t sA_H = smem_u32(smem);
    uint32_t sA_L = sA_H + 16384, sB_H = sA_H + 32768, sB_L = sA_H + 49152;

    int t = threadIdx.x, lane = t & 31, wid = t >> 5;
    int bh = blockIdx.z, b = bh >> 3, h = bh & 7;
    int i0 = blockIdx.y * 128, j0 = blockIdx.x * 128;
    int wm = (wid & 3) * 32, wn = (wid >> 2) * 64;

    const float* Q = g_h0 + (size_t)b * SLEN * DIM + h * DH;
    const float* K = g_h1 + (size_t)b * SLEN * DIM + h * DH;

    float acc[2][8][4];
#pragma unroll
    for (int i = 0; i < 2; i++)
#pragma unroll
        for (int j = 0; j < 8; j++)
#pragma unroll
            for (int l = 0; l < 4; l++) acc[i][j][l] = 0.f;

    int lrow = t >> 1, lcb = (t & 1) * 32;   // 128 rows x 64 cols
    {
        const float* qr = Q + (size_t)(i0 + lrow) * DIM + lcb;
        const float* kr = K + (size_t)(j0 + lrow) * DIM + lcb;
#pragma unroll
        for (int i = 0; i < 8; i++) {
            uint32_t off = SW128((uint32_t)(lrow * 128 + (lcb + i * 4) * 2));
            uint2 hi, lo;
            cvt_hilo(*(const float4*)(qr + i * 4), hi, lo);
            *(uint2*)(smem + off) = hi;
            *(uint2*)(smem + 16384 + off) = lo;
            cvt_hilo(*(const float4*)(kr + i * 4), hi, lo);
            *(uint2*)(smem + 32768 + off) = hi;
            *(uint2*)(smem + 49152 + off) = lo;
        }
    }
    __syncthreads();

    int a_r = (lane & 15), a_k8 = (lane >> 4) << 3;
    int b_n = ((lane & 16) >> 1) + (lane & 7), b_k8 = (lane & 8);

#pragma unroll
    for (int kt = 0; kt < 4; kt++) {
        int kb = kt * 16;
        uint32_t ah[2][4], al[2][4];
#pragma unroll
        for (int mt = 0; mt < 2; mt++) {
            uint32_t off = SW128((uint32_t)((wm + mt * 16 + a_r) * 128 + (kb + a_k8) * 2));
            ldm4(sA_H + off, ah[mt]);
            ldm4(sA_L + off, al[mt]);
        }
#pragma unroll
        for (int ng = 0; ng < 4; ng++) {
            uint32_t boff = SW128((uint32_t)((wn + ng * 16 + b_n) * 128 + (kb + b_k8) * 2));
            uint32_t bh4[4], bl4[4];
            ldm4(sB_H + boff, bh4);
            ldm4(sB_L + boff, bl4);
#pragma unroll
            for (int mt = 0; mt < 2; mt++) {
                mma16816(acc[mt][2 * ng],     ah[mt], bh4[0], bh4[1]);
                mma16816(acc[mt][2 * ng + 1], ah[mt], bh4[2], bh4[3]);
                mma16816(acc[mt][2 * ng],     ah[mt], bl4[0], bl4[1]);
                mma16816(acc[mt][2 * ng + 1], ah[mt], bl4[2], bl4[3]);
                mma16816(acc[mt][2 * ng],     al[mt], bh4[0], bh4[1]);
                mma16816(acc[mt][2 * ng + 1], al[mt], bh4[2], bh4[3]);
            }
        }
    }

    float* S = g_scores + (size_t)bh * SLEN * SLEN;
#pragma unroll
    for (int mt = 0; mt < 2; mt++) {
        int r0 = i0 + wm + mt * 16 + (lane >> 2);
#pragma unroll
        for (int nt = 0; nt < 8; nt++) {
            int col = j0 + wn + nt * 8 + (lane & 3) * 2;
#pragma unroll
            for (int hh = 0; hh < 2; hh++) {
                int row = r0 + hh * 8;
                *(float2*)(S + (size_t)row * SLEN + col) =
                    make_float2(acc[mt][nt][hh * 2] * 0.125f, acc[mt][nt][hh * 2 + 1] * 0.125f);
            }
        }
    }
}

__global__ void attn_softmax(int node) {
    if (g_nr[node].act != 0) return;
    size_t row = blockIdx.x;
    float* S = g_scores + row * SLEN;
    int t = threadIdx.x;
    float v[4];
#pragma unroll
    for (int l = 0; l < 4; l++) v[l] = S[t + 256 * l];
    float m = fmaxf(fmaxf(v[0], v[1]), fmaxf(v[2], v[3]));
    m = blk_max(m);
    float e[4], s = 0.f;
#pragma unroll
    for (int l = 0; l < 4; l++) { e[l] = expf(v[l] - m); s += e[l]; }
    float tot = blk_sum(s);
    float inv = 1.0f / tot;
#pragma unroll
    for (int l = 0; l < 4; l++) S[t + 256 * l] = e[l] * inv;
}

// ---------------------------------------------------------------------------
// PV via mma: O = P @ V ; CTA tile 128(i) x 64(d) ; j-chunks of 64
// grid (8, 32) block 256 ; smem: P_hi/P_lo 16KB + V_hi/V_lo 8KB = 48KB
// warp tile 32(m) x 32(n)
// ---------------------------------------------------------------------------
__global__ void __launch_bounds__(256) pv_mma(int node) {
    if (g_nr[node].act != 0) return;
    extern __shared__ char smem[];
    uint32_t sP_H = smem_u32(smem);
    uint32_t sP_L = sP_H + 16384, sV_H = sP_H + 32768, sV_L = sP_H + 40960;

    int t = threadIdx.x, lane = t & 31, wid = t >> 5;
    int bh = blockIdx.y, b = bh >> 3, h = bh & 7;
    int i0 = blockIdx.x * 128;
    int wm = (wid & 3) * 32, wn = (wid >> 2) * 32;

    const float* P = g_scores + (size_t)bh * SLEN * SLEN;
    const float* V = g_h2 + (size_t)b * SLEN * DIM + h * DH;

    float acc[2][4][4];
#pragma unroll
    for (int i = 0; i < 2; i++)
#pragma unroll
        for (int j = 0; j < 4; j++)
#pragma unroll
            for (int l = 0; l < 4; l++) acc[i][j][l] = 0.f;

    int prow = t >> 1, pcb = (t & 1) * 32;   // P: 128 rows x 64 cols
    int vrow = t >> 2, vcb = (t & 3) * 16;   // V: 64 rows x 64 cols

    int a_r = (lane & 15), a_k8 = (lane >> 4) << 3;
    int v_k = (lane & 15), v_n8 = (lane & 16) >> 1;   // trans: k row, n offset 0/8

    for (int jc = 0; jc < 16; jc++) {
        int j0 = jc * 64;
        // P chunk fill
        {
            const float* pr = P + (size_t)(i0 + prow) * SLEN + j0 + pcb;
#pragma unroll
            for (int i = 0; i < 8; i++) {
                uint2 hi, lo; cvt_hilo(*(const float4*)(pr + i * 4), hi, lo);
                uint32_t off = SW128((uint32_t)(prow * 128 + (pcb + i * 4) * 2));
                *(uint2*)(smem + off) = hi;
                *(uint2*)(smem + 16384 + off) = lo;
            }
        }
        // V chunk fill (64 x 64)
        {
            const float* vr = V + (size_t)(j0 + vrow) * DIM + vcb;
#pragma unroll
            for (int i = 0; i < 4; i++) {
                uint2 hi, lo; cvt_hilo(*(const float4*)(vr + i * 4), hi, lo);
                uint32_t off = SW128((uint32_t)(vrow * 128 + (vcb + i * 4) * 2));
                *(uint2*)(smem + 32768 + off) = hi;
                *(uint2*)(smem + 40960 + off) = lo;
            }
        }
        __syncthreads();

#pragma unroll
        for (int kt = 0; kt < 4; kt++) {
            int kb = kt * 16;
            uint32_t ah[2][4], al[2][4];
#pragma unroll
            for (int mt = 0; mt < 2; mt++) {
                uint32_t off = SW128((uint32_t)((wm + mt * 16 + a_r) * 128 + (kb + a_k8) * 2));
                ldm4(sP_H + off, ah[mt]);
                ldm4(sP_L + off, al[mt]);
            }
#pragma unroll
            for (int ng = 0; ng < 2; ng++) {
                // trans ldmatrix on V[k][n]
                uint32_t boff = SW128((uint32_t)((kb + v_k) * 128 + (wn + ng * 16 + v_n8) * 2));
                uint32_t bh4[4], bl4[4];
                ldm4t(sV_H + boff, bh4);
                ldm4t(sV_L + boff, bl4);
#pragma unroll
                for (int mt = 0; mt < 2; mt++) {
                    mma16816(acc[mt][2 * ng],     ah[mt], bh4[0], bh4[1]);
                    mma16816(acc[mt][2 * ng + 1], ah[mt], bh4[2], bh4[3]);
                    mma16816(acc[mt][2 * ng],     ah[mt], bl4[0], bl4[1]);
                    mma16816(acc[mt][2 * ng + 1], ah[mt], bl4[2], bl4[3]);
                    mma16816(acc[mt][2 * ng],     al[mt], bh4[0], bh4[1]);
                    mma16816(acc[mt][2 * ng + 1], al[mt], bh4[2], bh4[3]);
                }
            }
        }
        __syncthreads();
    }

    float* O = g_t0 + (size_t)b * SLEN * DIM + h * DH;
#pragma unroll
    for (int mt = 0; mt < 2; mt++) {
        int r0 = i0 + wm + mt * 16 + (lane >> 2);
#pragma unroll
        for (int nt = 0; nt < 4; nt++) {
            int col = wn + nt * 8 + (lane & 3) * 2;
#pragma unroll
            for (int hh = 0; hh < 2; hh++) {
                int row = r0 + hh * 8;
                *(float2*)(O + (size_t)row * DIM + col) =
                    make_float2(acc[mt][nt][hh * 2], acc[mt][nt][hh * 2 + 1]);
            }
        }
    }
}

// ---------------------------------------------------------------------------
// Elementwise combine (act1: h0*=h1 ; act3: h0=relu(h0+h1+h2))
// ---------------------------------------------------------------------------
__global__ void combine_k(int node) {
    int a = g_nr[node].act;
    if (a != 1 && a != 3) return;
    size_t stride = (size_t)gridDim.x * blockDim.x;
    for (size_t p = (size_t)blockIdx.x * blockDim.x + threadIdx.x; p < (size_t)MS; p += stride) {
        if (a == 1) g_h0[p] = g_h0[p] * g_h1[p];
        else        g_h0[p] = fmaxf(g_h0[p] + g_h1[p] + g_h2[p], 0.f);
    }
}

// ---------------------------------------------------------------------------
// Elementwise finish (acts 2,4,5,6,7)
// ---------------------------------------------------------------------------
__global__ void finish_k(int node) {
    NR r = g_nr[node];
    int a = r.act;
    if (a == 0 || a == 1 || a == 3) return;
    int row = blockIdx.x, t = threadIdx.x;
    float* out = g_outs + (size_t)node * MS;
    size_t p0 = (size_t)row * DIM + t, p1 = p0 + 256;
    if (a == 2) {
        float s0 = g_qv[p0] + g_kv[p0] + g_vv[p0];
        float s1 = g_qv[p1] + g_kv[p1] + g_vv[p1];
        ln_row_store(s0, s1, out, row,
                     g_ptrs.node_g + node * DIM, g_ptrs.node_beta + node * DIM, r.aw);
    } else if (a == 4) {
        out[p0] = r.aw * (g_qv[p0] * sigmoidf_(g_kv[p0]) + g_vv[p0]);
        out[p1] = r.aw * (g_qv[p1] * sigmoidf_(g_kv[p1]) + g_vv[p1]);
    } else if (a == 5) {
        out[p0] = r.aw * (g_qv[p0] + g_h1[p0]);
        out[p1] = r.aw * (g_qv[p1] + g_h1[p1]);
    } else if (a == 6) {
        out[p0] = r.aw * (g_qv[p0] + g_kv[p0]);
        out[p1] = r.aw * (g_qv[p1] + g_kv[p1]);
    } else { // 7
        ln_row_store(g_qv[p0], g_qv[p1], out, row,
                     g_ptrs.node_g + node * DIM, g_ptrs.node_beta + node * DIM, r.aw);
    }
}

// ---------------------------------------------------------------------------
// Final: sum unprocessed outs, LN with out_g/out_beta -> d_out
// ---------------------------------------------------------------------------
__global__ void final_k(float* dout) {
    int row = blockIdx.x, t = threadIdx.x;
    size_t p0 = (size_t)row * DIM + t, p1 = p0 + 256;
    float s0 = 0.f, s1 = 0.f;
    for (int c = 0; c < 8; c++) {
        if (!g_processed[c]) {
            s0 += g_outs[(size_t)c * MS + p0];
            s1 += g_outs[(size_t)c * MS + p1];
        }
    }
    ln_row_store(s0, s1, dout, row, g_ptrs.out_g, g_ptrs.out_beta, 1.0f);
}

// ---------------------------------------------------------------------------
// Launch
// ---------------------------------------------------------------------------
extern "C" void kernel_launch(void* const* d_in, const int* in_sizes, int n_in,
                              void* d_out, int out_size) {
    (void)in_sizes; (void)n_in; (void)out_size;
    cudaFuncSetAttribute(gemm_mma, cudaFuncAttributeMaxDynamicSharedMemorySize, GEMM_SMEM);
    cudaFuncSetAttribute(sc_mma,   cudaFuncAttributeMaxDynamicSharedMemorySize, GEMM_SMEM);
    cudaFuncSetAttribute(pv_mma,   cudaFuncAttributeMaxDynamicSharedMemorySize, 49152);

    setup_k<<<1, 1>>>(
        (const float*)d_in[0],  (const float*)d_in[1],  (const float*)d_in[2],
        (const float*)d_in[3],  (const float*)d_in[4],  (const float*)d_in[5],
        (const float*)d_in[6],  (const float*)d_in[7],  (const float*)d_in[8],
        (const float*)d_in[9],  (const float*)d_in[10], (const float*)d_in[11],
        (const float*)d_in[12], (const float*)d_in[13]);
    routing_k<<<1, 1>>>();
    conv_w_all<<<dim3(16, 16, 56), dim3(32, 8)>>>();

    for (int c = 0; c < 8; c++) {
        edge_pre<<<dim3(NROWS, 3), 256>>>(c);
        gemm_mma<<<dim3(4, 32, 3), 256, GEMM_SMEM>>>(c, 0);   // q/k/v edge GEMMs
        node_prep<<<NROWS, 256>>>(c);
        gemm_mma<<<dim3(4, 32, 3), 256, GEMM_SMEM>>>(c, 3);   // node j0/j1/j2 GEMMs
        sc_mma<<<dim3(8, 8, 32), 256, GEMM_SMEM>>>(c);
        attn_softmax<<<32 * SLEN, 256>>>(c);
        pv_mma<<<dim3(8, 32), 256, 49152>>>(c);
        combine_k<<<2048, 256>>>(c);
        gemm_mma<<<dim3(4, 32, 1), 256, GEMM_SMEM>>>(c, 6);   // node j3 GEMM
        finish_k<<<NROWS, 256>>>(c);
    }
    final_k<<<NROWS, 256>>>((float*)d_out);
}

// round 5
// speedup vs baseline: 2.3674x; 1.2861x over previous
#include <cuda_runtime.h>
#include <cuda_bf16.h>
#include <math.h>
#include <stdint.h>

// ---------------------------------------------------------------------------
// Problem constants
// ---------------------------------------------------------------------------
#define NROWS 4096          // B*SLEN
#define DIM   512
#define MS    (4096*512)
#define NHEAD 8
#define DH    64
#define SLEN  1024
#define EPSLN 1e-6f

// ---------------------------------------------------------------------------
// Device-resident input pointer table + route table
// ---------------------------------------------------------------------------
struct Ptrs {
    const float *inpute, *inputo, *node_p, *edge_p;
    const float *edge_W, *edge_b, *edge_g, *edge_beta;
    const float *node_W, *node_b, *node_g, *node_beta;
    const float *out_g, *out_beta;
};
__device__ Ptrs g_ptrs;

struct NR {
    int act; float aw;
    int q_in, q_op, q_e; float q_w;
    int k_valid, k_in, k_op, k_e; float k_w;
    int v_valid, v_in, v_op, v_e; float v_w;
};
__device__ NR  g_nr[8];
__device__ int g_processed[8];

// ---------------------------------------------------------------------------
// Scratch
// ---------------------------------------------------------------------------
__device__ float g_outs[8 * MS];
__device__ float g_qv[MS], g_kv[MS], g_vv[MS];
__device__ float g_h0[MS], g_h1[MS], g_h2[MS];
__device__ __align__(16) __nv_bfloat16 g_EXh[3 * MS], g_EXl[3 * MS];  // edge GEMM inputs
__device__ __align__(16) __nv_bfloat16 g_NXh[3 * MS], g_NXl[3 * MS];  // node GEMM inputs
__device__ __align__(16) __nv_bfloat16 g_Wth[8 * 7 * DIM * DIM];      // W^T hi [node][slot][n][k]
__device__ __align__(16) __nv_bfloat16 g_Wtl[8 * 7 * DIM * DIM];      // W^T lo
__device__ float g_scores[32u * 1024u * 1024u];

// ---------------------------------------------------------------------------
// Helpers
// ---------------------------------------------------------------------------
__device__ __forceinline__ const float* buf_in(int idx) {
    if (idx == 0) return g_ptrs.inpute;
    if (idx == 1) return g_ptrs.inputo;
    return g_outs + (size_t)(idx - 2) * MS;
}

__device__ __forceinline__ float geluf(float x) {
    float x3 = x * x * x;
    return 0.5f * x * (1.0f + tanhf(0.7978845608028654f * (x + 0.044715f * x3)));
}
__device__ __forceinline__ float sigmoidf_(float x) {
    return 1.0f / (1.0f + expf(-x));
}

__device__ __forceinline__ float blk_sum(float v) {
    __shared__ float sh[8];
    int lane = threadIdx.x & 31, w = threadIdx.x >> 5;
#pragma unroll
    for (int o = 16; o; o >>= 1) v += __shfl_xor_sync(0xffffffffu, v, o);
    if (lane == 0) sh[w] = v;
    __syncthreads();
    if (w == 0) {
        float r = (lane < 8) ? sh[lane] : 0.f;
#pragma unroll
        for (int o = 4; o; o >>= 1) r += __shfl_xor_sync(0xffffffffu, r, o);
        if (lane == 0) sh[0] = r;
    }
    __syncthreads();
    float out = sh[0];
    __syncthreads();
    return out;
}

__device__ __forceinline__ float blk_max(float v) {
    __shared__ float sh[8];
    int lane = threadIdx.x & 31, w = threadIdx.x >> 5;
#pragma unroll
    for (int o = 16; o; o >>= 1) v = fmaxf(v, __shfl_xor_sync(0xffffffffu, v, o));
    if (lane == 0) sh[w] = v;
    __syncthreads();
    if (w == 0) {
        float r = (lane < 8) ? sh[lane] : -3.4e38f;
#pragma unroll
        for (int o = 4; o; o >>= 1) r = fmaxf(r, __shfl_xor_sync(0xffffffffu, r, o));
        if (lane == 0) sh[0] = r;
    }
    __syncthreads();
    float out = sh[0];
    __syncthreads();
    return out;
}

__device__ __forceinline__ void split_bf(float v, __nv_bfloat16& h, __nv_bfloat16& l) {
    h = __float2bfloat16_rn(v);
    l = __float2bfloat16_rn(v - __bfloat162float(h));
}

// 256 threads; thread t owns elements t and t+256 of a 512-wide row.
__device__ __forceinline__ void ln_row_store(float s0, float s1, float* dst, int row,
                                             const float* gm, const float* bt, float scale) {
    int t = threadIdx.x;
    float mean = blk_sum(s0 + s1) * (1.0f / 512.0f);
    float d0 = s0 - mean, d1 = s1 - mean;
    float var = blk_sum(d0 * d0 + d1 * d1) * (1.0f / 512.0f);
    float inv = rsqrtf(var + EPSLN);
    size_t base = (size_t)row * DIM;
    dst[base + t]       = scale * (d0 * inv * gm[t] + bt[t]);
    dst[base + t + 256] = scale * (d1 * inv * gm[t + 256] + bt[t + 256]);
}

// LN -> bf16 hi/lo buffers (unscaled)
__device__ __forceinline__ void ln_row_store_bf(float s0, float s1,
                                                __nv_bfloat16* oh, __nv_bfloat16* ol, int row,
                                                const float* gm, const float* bt) {
    int t = threadIdx.x;
    float mean = blk_sum(s0 + s1) * (1.0f / 512.0f);
    float d0 = s0 - mean, d1 = s1 - mean;
    float var = blk_sum(d0 * d0 + d1 * d1) * (1.0f / 512.0f);
    float inv = rsqrtf(var + EPSLN);
    size_t base = (size_t)row * DIM;
    float y0 = d0 * inv * gm[t] + bt[t];
    float y1 = d1 * inv * gm[t + 256] + bt[t + 256];
    __nv_bfloat16 h, l;
    split_bf(y0, h, l); oh[base + t] = h;       ol[base + t] = l;
    split_bf(y1, h, l); oh[base + t + 256] = h; ol[base + t + 256] = l;
}

// ---------------------------------------------------------------------------
// mma.sync / ldmatrix / cp.async helpers
// ---------------------------------------------------------------------------
__device__ __forceinline__ uint32_t smem_u32(const void* p) {
    uint32_t a;
    asm("{ .reg .u64 t; cvta.to.shared.u64 t, %1; cvt.u32.u64 %0, t; }" : "=r"(a) : "l"(p));
    return a;
}
__device__ __forceinline__ void ldm4(uint32_t addr, uint32_t r[4]) {
    asm volatile("ldmatrix.sync.aligned.m8n8.x4.shared.b16 {%0,%1,%2,%3}, [%4];"
                 : "=r"(r[0]), "=r"(r[1]), "=r"(r[2]), "=r"(r[3]) : "r"(addr));
}
__device__ __forceinline__ void ldm4t(uint32_t addr, uint32_t r[4]) {
    asm volatile("ldmatrix.sync.aligned.m8n8.x4.trans.shared.b16 {%0,%1,%2,%3}, [%4];"
                 : "=r"(r[0]), "=r"(r[1]), "=r"(r[2]), "=r"(r[3]) : "r"(addr));
}
__device__ __forceinline__ void mma16816(float c[4], const uint32_t a[4],
                                         uint32_t b0, uint32_t b1) {
    asm volatile(
        "mma.sync.aligned.m16n8k16.row.col.f32.bf16.bf16.f32 "
        "{%0,%1,%2,%3}, {%4,%5,%6,%7}, {%8,%9}, {%0,%1,%2,%3};"
        : "+f"(c[0]), "+f"(c[1]), "+f"(c[2]), "+f"(c[3])
        : "r"(a[0]), "r"(a[1]), "r"(a[2]), "r"(a[3]), "r"(b0), "r"(b1));
}
__device__ __forceinline__ void cpa16(uint32_t dst, const void* src) {
    asm volatile("cp.async.ca.shared.global [%0], [%1], 16;" :: "r"(dst), "l"(src));
}
#define CPA_COMMIT() asm volatile("cp.async.commit_group;" ::: "memory")
#define CPA_WAIT1()  asm volatile("cp.async.wait_group 1;" ::: "memory")
#define CPA_WAIT0()  asm volatile("cp.async.wait_group 0;" ::: "memory")

#define SW128(o) ((o) ^ (((o) >> 3) & 0x70))

__device__ __forceinline__ uint32_t pack_bf2(float x, float y) {
    __nv_bfloat162 h = __float22bfloat162_rn(make_float2(x, y));
    return *(uint32_t*)&h;
}
__device__ __forceinline__ void cvt_hilo(float4 v, uint2& hi, uint2& lo) {
    hi = make_uint2(pack_bf2(v.x, v.y), pack_bf2(v.z, v.w));
    __nv_bfloat162 h0 = *(__nv_bfloat162*)&hi.x;
    __nv_bfloat162 h1 = *(__nv_bfloat162*)&hi.y;
    float lx = v.x - __bfloat162float(h0.x);
    float ly = v.y - __bfloat162float(h0.y);
    float lz = v.z - __bfloat162float(h1.x);
    float lw = v.w - __bfloat162float(h1.y);
    lo = make_uint2(pack_bf2(lx, ly), pack_bf2(lz, lw));
}

// ---------------------------------------------------------------------------
// Setup + routing
// ---------------------------------------------------------------------------
__global__ void setup_k(const float* a0, const float* a1, const float* a2, const float* a3,
                        const float* a4, const float* a5, const float* a6, const float* a7,
                        const float* a8, const float* a9, const float* a10, const float* a11,
                        const float* a12, const float* a13) {
    Ptrs p;
    p.inpute = a0; p.inputo = a1; p.node_p = a2; p.edge_p = a3;
    p.edge_W = a4; p.edge_b = a5; p.edge_g = a6; p.edge_beta = a7;
    p.node_W = a8; p.node_b = a9; p.node_g = a10; p.node_beta = a11;
    p.out_g = a12; p.out_beta = a13;
    g_ptrs = p;
}

__device__ int d_amax(const float* x, int n, int lo) {
    int bi = lo; float bv = x[lo];
    for (int i = lo + 1; i < n; i++) { if (x[i] > bv) { bv = x[i]; bi = i; } }
    return bi;
}
__device__ float d_smw(const float* x, int n, int lo, int sel) {
    float mx = x[lo];
    for (int i = lo + 1; i < n; i++) mx = fmaxf(mx, x[i]);
    float s = 0.f;
    for (int i = lo; i < n; i++) s += expf(x[i] - mx);
    return expf(x[sel] - mx) / s;
}

__global__ void routing_k() {
    if (threadIdx.x || blockIdx.x) return;
    const float* np = g_ptrs.node_p;
    const float* ep = g_ptrs.edge_p;
    for (int i = 0; i < 8; i++) g_processed[i] = 0;
    int lind = 0;
    for (int c = 0; c < 8; c++) {
        int nsrc = (c + 2 < 5) ? c + 2 : 5;
        int snode = c - nsrc;
        int n = nsrc * 5;
        const float* e0 = ep + 0 * 170 + lind * 5;
        const float* e1 = ep + 1 * 170 + lind * 5;
        const float* e2 = ep + 2 * 170 + lind * 5;
        NR r; r.k_valid = 0; r.v_valid = 0;
        r.k_in = 0; r.k_op = 4; r.k_e = 0; r.k_w = 0.f;
        r.v_in = 0; r.v_op = 4; r.v_e = 0; r.v_w = 0.f;

        int nact = d_amax(np + c * 8, 8, 0);
        r.act = nact;
        r.aw = d_smw(np + c * 8, 8, 0, nact);

        int qs = d_amax(e0, n, 5);
        int qse = qs / 5;
        r.q_in = (qse == 0) ? 0 : (snode + qse + 2);
        r.q_op = qs % 5; r.q_e = lind + qse;
        r.q_w = d_smw(e0, n, 5, qs);
        if (r.q_in >= 2) g_processed[r.q_in - 2] = 1;

        if (nact < 7) {
            int lo = (nact > 0) ? 5 : 0;
            int ks = d_amax(e1, n, lo);
            int kse = ks / 5;
            r.k_valid = 1;
            r.k_in = (kse == 0) ? 0 : (snode + kse + 2);
            r.k_op = ks % 5; r.k_e = lind + kse;
            r.k_w = d_smw(e1, n, lo, ks);
            if (r.k_in >= 2) g_processed[r.k_in - 2] = 1;
            int ktype = (kse == 0) ? -2 : -1;
            if (nact < 5) {
                r.v_valid = 1;
                int vs, vlo, vn;
                if (nact == 0 && ktype == -2) { vlo = 0; vn = 5; }
                else if (nact > 0)            { vlo = 5; vn = n; }
                else                          { vlo = 0; vn = n; }
                vs = d_amax(e2, vn, vlo);
                int vse = vs / 5;
                r.v_in = (vse == 0) ? 0 : (snode + vse + 2);
                r.v_op = vs % 5; r.v_e = lind + vse;
                r.v_w = d_smw(e2, vn, vlo, vs);
                if (r.v_in >= 2) g_processed[r.v_in - 2] = 1;
            }
        }
        g_nr[c] = r;
        lind += nsrc;
    }
}

// role r output feeds node GEMM slot 3+r?
__device__ __forceinline__ bool need_hilo_role(int act, int role) {
    if (role == 0) return act == 1 || act == 3;
    if (role == 1) return act == 0 || act == 1 || act == 3 || act == 5;
    return act == 0 || act == 3;
}

// ---------------------------------------------------------------------------
// Weight selection (routing-only) for slot 0..6
// ---------------------------------------------------------------------------
__device__ const float* resolve_w(int node, int slot) {
    NR r = g_nr[node];
    if (slot < 3) {
        int valid, op, e;
        if (slot == 0)      { valid = 1;         op = r.q_op; e = r.q_e; }
        else if (slot == 1) { valid = r.k_valid; op = r.k_op; e = r.k_e; }
        else                { valid = r.v_valid; op = r.v_op; e = r.v_e; }
        if (valid && op <= 3) return g_ptrs.edge_W + (size_t)e * DIM * DIM;
        return nullptr;
    }
    int a = r.act, j = slot - 3;
    bool need =
        (j == 0 && (a == 0 || a == 1 || a == 3)) ||
        (j == 1 && (a == 0 || a == 1 || a == 3 || a == 5)) ||
        (j == 2 && (a == 0 || a == 3)) ||
        (j == 3 && (a == 0 || a == 1 || a == 3));
    if (need) return g_ptrs.node_W + ((size_t)node * 4 + j) * DIM * DIM;
    return nullptr;
}

// Convert+transpose W -> bf16 hi/lo.  grid (16,16,56) block (32,8)
__global__ void conv_w_all() {
    int z = blockIdx.z; int node = z / 7, slot = z % 7;
    const float* W = resolve_w(node, slot);
    if (!W) return;
    __shared__ float tile[32][33];
    int n0 = blockIdx.x * 32, k0 = blockIdx.y * 32;
    int tx = threadIdx.x, ty = threadIdx.y;
#pragma unroll
    for (int dy = 0; dy < 4; dy++)
        tile[ty * 4 + dy][tx] = W[(size_t)(k0 + ty * 4 + dy) * DIM + n0 + tx];
    __syncthreads();
    size_t base = (size_t)z * DIM * DIM;
#pragma unroll
    for (int dy = 0; dy < 4; dy++) {
        int n = n0 + ty * 4 + dy, k = k0 + tx;
        float v = tile[tx][ty * 4 + dy];
        __nv_bfloat16 h, l; split_bf(v, h, l);
        g_Wth[base + (size_t)n * DIM + k] = h;
        g_Wtl[base + (size_t)n * DIM + k] = l;
    }
}

// ---------------------------------------------------------------------------
// edge_pre: per (row, role).
//   op<=2: LN -> EX hi/lo (unscaled; GEMM applies w)
//   op==3: convert buf_in -> EX hi/lo
//   op==4: qv/kv/vv = w*x (fp32) + NX hi/lo if needed
// ---------------------------------------------------------------------------
__global__ void edge_pre(int node) {
    int role = blockIdx.y;
    NR r = g_nr[node];
    int valid, in, op, e; float w; float* out;
    if (role == 0)      { valid = 1;         in = r.q_in; op = r.q_op; e = r.q_e; w = r.q_w; out = g_qv; }
    else if (role == 1) { valid = r.k_valid; in = r.k_in; op = r.k_op; e = r.k_e; w = r.k_w; out = g_kv; }
    else                { valid = r.v_valid; in = r.v_in; op = r.v_op; e = r.v_e; w = r.v_w; out = g_vv; }
    if (!valid) return;
    int row = blockIdx.x, t = threadIdx.x;
    const float* x = buf_in(in);
    size_t p0 = (size_t)row * DIM + t, p1 = p0 + 256;
    __nv_bfloat16* exh = g_EXh + (size_t)role * MS;
    __nv_bfloat16* exl = g_EXl + (size_t)role * MS;
    if (op <= 2) {
        ln_row_store_bf(x[p0], x[p1], exh, exl, row,
                        g_ptrs.edge_g + e * DIM, g_ptrs.edge_beta + e * DIM);
    } else if (op == 3) {
        __nv_bfloat16 h, l;
        split_bf(x[p0], h, l); exh[p0] = h; exl[p0] = l;
        split_bf(x[p1], h, l); exh[p1] = h; exl[p1] = l;
    } else { // op == 4
        float v0 = w * x[p0], v1 = w * x[p1];
        out[p0] = v0; out[p1] = v1;
        if (need_hilo_role(r.act, role)) {
            __nv_bfloat16* nxh = g_NXh + (size_t)role * MS;
            __nv_bfloat16* nxl = g_NXl + (size_t)role * MS;
            __nv_bfloat16 h, l;
            split_bf(v0, h, l); nxh[p0] = h; nxl[p0] = l;
            split_bf(v1, h, l); nxh[p1] = h; nxl[p1] = l;
        }
    }
}

// node prep (act0): NX0 = LN(qv) hi/lo
__global__ void node_prep(int node) {
    NR r = g_nr[node];
    if (r.act != 0) return;
    int row = blockIdx.x, t = threadIdx.x;
    size_t p0 = (size_t)row * DIM + t, p1 = p0 + 256;
    ln_row_store_bf(g_qv[p0], g_qv[p1], g_NXh, g_NXl, row,
                    g_ptrs.node_g + node * DIM, g_ptrs.node_beta + node * DIM);
}

// ---------------------------------------------------------------------------
// GEMM config
// ---------------------------------------------------------------------------
struct GemmCfg {
    const __nv_bfloat16 *Xh, *Xl, *Wh, *Wl;
    const float* Bv;
    int act;            // 0 none, 1 relu, 2 gelu
    float scale;
    const float* res;
    float* out;
    __nv_bfloat16 *oh, *ol;   // optional hi/lo mirror of output
};

__device__ bool resolve_gemm(int node, int slot, GemmCfg& g) {
    NR r = g_nr[node];
    g.oh = nullptr; g.ol = nullptr; g.res = nullptr;
    size_t wbase = ((size_t)node * 7 + slot) * DIM * DIM;
    g.Wh = g_Wth + wbase; g.Wl = g_Wtl + wbase;
    if (slot < 3) {
        int valid, op, e; float w; float* out;
        if (slot == 0)      { valid = 1;         op = r.q_op; e = r.q_e; w = r.q_w; out = g_qv; }
        else if (slot == 1) { valid = r.k_valid; op = r.k_op; e = r.k_e; w = r.k_w; out = g_kv; }
        else                { valid = r.v_valid; op = r.v_op; e = r.v_e; w = r.v_w; out = g_vv; }
        if (!valid || op == 4) return false;
        g.Xh = g_EXh + (size_t)slot * MS;
        g.Xl = g_EXl + (size_t)slot * MS;
        g.Bv = g_ptrs.edge_b + e * DIM;
        g.act = (op == 0) ? 1 : (op == 1) ? 2 : 0;
        g.scale = w; g.out = out;
        if (need_hilo_role(r.act, slot)) {
            g.oh = g_NXh + (size_t)slot * MS;
            g.ol = g_NXl + (size_t)slot * MS;
        }
        return true;
    }
    int a = r.act;
    int j = slot - 3;
    const float* Bv = g_ptrs.node_b + (node * 4 + j) * DIM;
    if (j == 0) {
        if (a != 0 && a != 1 && a != 3) return false;
        g.Xh = g_NXh; g.Xl = g_NXl;
        g.Bv = (a == 3) ? nullptr : Bv;
        g.act = (a == 1) ? 2 : 0;
        g.scale = 1.f; g.out = g_h0;
        return true;
    }
    if (j == 1) {
        if (a != 0 && a != 1 && a != 3 && a != 5) return false;
        g.Xh = g_NXh + (size_t)1 * MS; g.Xl = g_NXl + (size_t)1 * MS;
        g.Bv = (a == 3) ? nullptr : Bv;
        g.act = (a == 5) ? 2 : 0;
        g.scale = 1.f; g.out = g_h1;
        return true;
    }
    if (j == 2) {
        if (a != 0 && a != 3) return false;
        g.Xh = g_NXh + (size_t)2 * MS; g.Xl = g_NXl + (size_t)2 * MS;
        g.Bv = (a == 3) ? nullptr : Bv;
        g.act = 0; g.scale = 1.f; g.out = g_h2;
        return true;
    }
    // j == 3
    if (a != 0 && a != 1 && a != 3) return false;
    g.Xh = g_NXh; g.Xl = g_NXl;
    g.Bv = Bv; g.act = 0; g.scale = r.aw;
    g.res = g_qv; g.out = g_outs + (size_t)node * MS;
    return true;
}

// ---------------------------------------------------------------------------
// Pipelined mma GEMM: out = scale * (res + act(X @ W^T + bias))
// CTA 128x128, 8 warps (32x64), K-chunk 64, 2-stage cp.async double buffer
// smem = 2 stages x 4 arrays x 16KB = 128KB
// ---------------------------------------------------------------------------
#define GEMM_SMEM 131072

__global__ void __launch_bounds__(256) gemm_mma(int node, int base_slot) {
    int slot = base_slot + blockIdx.z;
    GemmCfg g;
    if (!resolve_gemm(node, slot, g)) return;

    extern __shared__ char smem[];
    uint32_t sbase = smem_u32(smem);
    int t = threadIdx.x, lane = t & 31, wid = t >> 5;
    int m0 = blockIdx.y * 128, n0 = blockIdx.x * 128;
    int wm = (wid & 3) * 32, wn = (wid >> 2) * 64;

    float acc[2][8][4];
#pragma unroll
    for (int i = 0; i < 2; i++)
#pragma unroll
        for (int j = 0; j < 8; j++)
#pragma unroll
            for (int l = 0; l < 4; l++) acc[i][j][l] = 0.f;

    // loader: thread t -> row t>>1 (0..127), col block (t&1)*32 bf16
    int lrow = t >> 1, lcb = (t & 1) * 32;
    const __nv_bfloat16* pAh = g.Xh + (size_t)(m0 + lrow) * DIM + lcb;
    const __nv_bfloat16* pAl = g.Xl + (size_t)(m0 + lrow) * DIM + lcb;
    const __nv_bfloat16* pBh = g.Wh + (size_t)(n0 + lrow) * DIM + lcb;
    const __nv_bfloat16* pBl = g.Wl + (size_t)(n0 + lrow) * DIM + lcb;
    uint32_t doff[4];
#pragma unroll
    for (int i = 0; i < 4; i++)
        doff[i] = SW128((uint32_t)(lrow * 128 + (lcb + i * 8) * 2));

    // ldmatrix lane addressing
    int a_r = (lane & 15), a_k8 = (lane >> 4) << 3;
    int b_n = ((lane & 16) >> 1) + (lane & 7), b_k8 = (lane & 8);

    // prologue: stage 0 <- chunk 0
    {
        uint32_t sb = sbase;
#pragma unroll
        for (int i = 0; i < 4; i++) {
            cpa16(sb + doff[i],         pAh + i * 8);
            cpa16(sb + 16384 + doff[i], pAl + i * 8);
            cpa16(sb + 32768 + doff[i], pBh + i * 8);
            cpa16(sb + 49152 + doff[i], pBl + i * 8);
        }
        CPA_COMMIT();
    }

    for (int c = 0; c < 8; c++) {
        if (c < 7) {
            int k0 = (c + 1) * 64;
            uint32_t sb = sbase + ((c + 1) & 1) * 65536;
#pragma unroll
            for (int i = 0; i < 4; i++) {
                cpa16(sb + doff[i],         pAh + k0 + i * 8);
                cpa16(sb + 16384 + doff[i], pAl + k0 + i * 8);
                cpa16(sb + 32768 + doff[i], pBh + k0 + i * 8);
                cpa16(sb + 49152 + doff[i], pBl + k0 + i * 8);
            }
            CPA_COMMIT();
            CPA_WAIT1();
        } else {
            CPA_WAIT0();
        }
        __syncthreads();

        uint32_t sA_H = sbase + (c & 1) * 65536;
        uint32_t sA_L = sA_H + 16384, sB_H = sA_H + 32768, sB_L = sA_H + 49152;
#pragma unroll
        for (int kt = 0; kt < 4; kt++) {
            int kb = kt * 16;
            uint32_t ah[2][4], al[2][4];
#pragma unroll
            for (int mt = 0; mt < 2; mt++) {
                uint32_t off = SW128((uint32_t)((wm + mt * 16 + a_r) * 128 + (kb + a_k8) * 2));
                ldm4(sA_H + off, ah[mt]);
                ldm4(sA_L + off, al[mt]);
            }
#pragma unroll
            for (int ng = 0; ng < 4; ng++) {
                uint32_t boff = SW128((uint32_t)((wn + ng * 16 + b_n) * 128 + (kb + b_k8) * 2));
                uint32_t bh4[4], bl4[4];
                ldm4(sB_H + boff, bh4);
                ldm4(sB_L + boff, bl4);
#pragma unroll
                for (int mt = 0; mt < 2; mt++) {
                    mma16816(acc[mt][2 * ng],     ah[mt], bh4[0], bh4[1]);
                    mma16816(acc[mt][2 * ng + 1], ah[mt], bh4[2], bh4[3]);
                    mma16816(acc[mt][2 * ng],     ah[mt], bl4[0], bl4[1]);
                    mma16816(acc[mt][2 * ng + 1], ah[mt], bl4[2], bl4[3]);
                    mma16816(acc[mt][2 * ng],     al[mt], bh4[0], bh4[1]);
                    mma16816(acc[mt][2 * ng + 1], al[mt], bh4[2], bh4[3]);
                }
            }
        }
        __syncthreads();
    }

    // epilogue
#pragma unroll
    for (int mt = 0; mt < 2; mt++) {
        int r0 = m0 + wm + mt * 16 + (lane >> 2);
#pragma unroll
        for (int nt = 0; nt < 8; nt++) {
            int col = n0 + wn + nt * 8 + (lane & 3) * 2;
#pragma unroll
            for (int h = 0; h < 2; h++) {
                int row = r0 + h * 8;
                float v0 = acc[mt][nt][h * 2], v1 = acc[mt][nt][h * 2 + 1];
                if (g.Bv) { v0 += g.Bv[col]; v1 += g.Bv[col + 1]; }
                if (g.act == 1)      { v0 = fmaxf(v0, 0.f); v1 = fmaxf(v1, 0.f); }
                else if (g.act == 2) { v0 = geluf(v0); v1 = geluf(v1); }
                if (g.res) {
                    v0 += g.res[(size_t)row * DIM + col];
                    v1 += g.res[(size_t)row * DIM + col + 1];
                }
                v0 *= g.scale; v1 *= g.scale;
                size_t p = (size_t)row * DIM + col;
                *(float2*)(g.out + p) = make_float2(v0, v1);
                if (g.oh) {
                    __nv_bfloat16 h0, l0, h1, l1;
                    split_bf(v0, h0, l0); split_bf(v1, h1, l1);
                    *(uint32_t*)(g.oh + p) =
                        (uint32_t)__bfloat16_as_ushort(h0) | ((uint32_t)__bfloat16_as_ushort(h1) << 16);
                    *(uint32_t*)(g.ol + p) =
                        (uint32_t)__bfloat16_as_ushort(l0) | ((uint32_t)__bfloat16_as_ushort(l1) << 16);
                }
            }
        }
    }
}

// ---------------------------------------------------------------------------
// Attention scores: S = (Q K^T)/8 ; CTA 128x128 ; grid (8,8,32)
// ---------------------------------------------------------------------------
__global__ void __launch_bounds__(256) sc_mma(int node) {
    if (g_nr[node].act != 0) return;
    extern __shared__ char smem[];
    uint32_t sA_H = smem_u32(smem);
    uint32_t sA_L = sA_H + 16384, sB_H = sA_H + 32768, sB_L = sA_H + 49152;

    int t = threadIdx.x, lane = t & 31, wid = t >> 5;
    int bh = blockIdx.z, b = bh >> 3, h = bh & 7;
    int i0 = blockIdx.y * 128, j0 = blockIdx.x * 128;
    int wm = (wid & 3) * 32, wn = (wid >> 2) * 64;

    const float* Q = g_h0 + (size_t)b * SLEN * DIM + h * DH;
    const float* K = g_h1 + (size_t)b * SLEN * DIM + h * DH;

    float acc[2][8][4];
#pragma unroll
    for (int i = 0; i < 2; i++)
#pragma unroll
        for (int j = 0; j < 8; j++)
#pragma unroll
            for (int l = 0; l < 4; l++) acc[i][j][l] = 0.f;

    int lrow = t >> 1, lcb = (t & 1) * 32;
    {
        const float* qr = Q + (size_t)(i0 + lrow) * DIM + lcb;
        const float* kr = K + (size_t)(j0 + lrow) * DIM + lcb;
#pragma unroll
        for (int i = 0; i < 8; i++) {
            uint32_t off = SW128((uint32_t)(lrow * 128 + (lcb + i * 4) * 2));
            uint2 hi, lo;
            cvt_hilo(*(const float4*)(qr + i * 4), hi, lo);
            *(uint2*)(smem + off) = hi;
            *(uint2*)(smem + 16384 + off) = lo;
            cvt_hilo(*(const float4*)(kr + i * 4), hi, lo);
            *(uint2*)(smem + 32768 + off) = hi;
            *(uint2*)(smem + 49152 + off) = lo;
        }
    }
    __syncthreads();

    int a_r = (lane & 15), a_k8 = (lane >> 4) << 3;
    int b_n = ((lane & 16) >> 1) + (lane & 7), b_k8 = (lane & 8);

#pragma unroll
    for (int kt = 0; kt < 4; kt++) {
        int kb = kt * 16;
        uint32_t ah[2][4], al[2][4];
#pragma unroll
        for (int mt = 0; mt < 2; mt++) {
            uint32_t off = SW128((uint32_t)((wm + mt * 16 + a_r) * 128 + (kb + a_k8) * 2));
            ldm4(sA_H + off, ah[mt]);
            ldm4(sA_L + off, al[mt]);
        }
#pragma unroll
        for (int ng = 0; ng < 4; ng++) {
            uint32_t boff = SW128((uint32_t)((wn + ng * 16 + b_n) * 128 + (kb + b_k8) * 2));
            uint32_t bh4[4], bl4[4];
            ldm4(sB_H + boff, bh4);
            ldm4(sB_L + boff, bl4);
#pragma unroll
            for (int mt = 0; mt < 2; mt++) {
                mma16816(acc[mt][2 * ng],     ah[mt], bh4[0], bh4[1]);
                mma16816(acc[mt][2 * ng + 1], ah[mt], bh4[2], bh4[3]);
                mma16816(acc[mt][2 * ng],     ah[mt], bl4[0], bl4[1]);
                mma16816(acc[mt][2 * ng + 1], ah[mt], bl4[2], bl4[3]);
                mma16816(acc[mt][2 * ng],     al[mt], bh4[0], bh4[1]);
                mma16816(acc[mt][2 * ng + 1], al[mt], bh4[2], bh4[3]);
            }
        }
    }

    float* S = g_scores + (size_t)bh * SLEN * SLEN;
#pragma unroll
    for (int mt = 0; mt < 2; mt++) {
        int r0 = i0 + wm + mt * 16 + (lane >> 2);
#pragma unroll
        for (int nt = 0; nt < 8; nt++) {
            int col = j0 + wn + nt * 8 + (lane & 3) * 2;
#pragma unroll
            for (int hh = 0; hh < 2; hh++) {
                int row = r0 + hh * 8;
                *(float2*)(S + (size_t)row * SLEN + col) =
                    make_float2(acc[mt][nt][hh * 2] * 0.125f, acc[mt][nt][hh * 2 + 1] * 0.125f);
            }
        }
    }
}

// softmax over 1024-wide rows ; grid 4096 x 256thr, 8 rows/block
__global__ void attn_softmax(int node) {
    if (g_nr[node].act != 0) return;
    int t = threadIdx.x;
    for (int rr = 0; rr < 8; rr++) {
        size_t row = (size_t)blockIdx.x * 8 + rr;
        float* S = g_scores + row * SLEN;
        float v[4];
#pragma unroll
        for (int l = 0; l < 4; l++) v[l] = S[t + 256 * l];
        float m = fmaxf(fmaxf(v[0], v[1]), fmaxf(v[2], v[3]));
        m = blk_max(m);
        float e[4], s = 0.f;
#pragma unroll
        for (int l = 0; l < 4; l++) { e[l] = expf(v[l] - m); s += e[l]; }
        float tot = blk_sum(s);
        float inv = 1.0f / tot;
#pragma unroll
        for (int l = 0; l < 4; l++) S[t + 256 * l] = e[l] * inv;
    }
}

// PV: O = P @ V -> NX0 hi/lo ; grid (8,32)
__global__ void __launch_bounds__(256) pv_mma(int node) {
    if (g_nr[node].act != 0) return;
    extern __shared__ char smem[];
    uint32_t sP_H = smem_u32(smem);
    uint32_t sP_L = sP_H + 16384, sV_H = sP_H + 32768, sV_L = sP_H + 40960;

    int t = threadIdx.x, lane = t & 31, wid = t >> 5;
    int bh = blockIdx.y, b = bh >> 3, h = bh & 7;
    int i0 = blockIdx.x * 128;
    int wm = (wid & 3) * 32, wn = (wid >> 2) * 32;

    const float* P = g_scores + (size_t)bh * SLEN * SLEN;
    const float* V = g_h2 + (size_t)b * SLEN * DIM + h * DH;

    float acc[2][4][4];
#pragma unroll
    for (int i = 0; i < 2; i++)
#pragma unroll
        for (int j = 0; j < 4; j++)
#pragma unroll
            for (int l = 0; l < 4; l++) acc[i][j][l] = 0.f;

    int prow = t >> 1, pcb = (t & 1) * 32;
    int vrow = t >> 2, vcb = (t & 3) * 16;
    int a_r = (lane & 15), a_k8 = (lane >> 4) << 3;
    int v_k = (lane & 15), v_n8 = (lane & 16) >> 1;

    for (int jc = 0; jc < 16; jc++) {
        int j0 = jc * 64;
        {
            const float* pr = P + (size_t)(i0 + prow) * SLEN + j0 + pcb;
#pragma unroll
            for (int i = 0; i < 8; i++) {
                uint2 hi, lo; cvt_hilo(*(const float4*)(pr + i * 4), hi, lo);
                uint32_t off = SW128((uint32_t)(prow * 128 + (pcb + i * 4) * 2));
                *(uint2*)(smem + off) = hi;
                *(uint2*)(smem + 16384 + off) = lo;
            }
        }
        {
            const float* vr = V + (size_t)(j0 + vrow) * DIM + vcb;
#pragma unroll
            for (int i = 0; i < 4; i++) {
                uint2 hi, lo; cvt_hilo(*(const float4*)(vr + i * 4), hi, lo);
                uint32_t off = SW128((uint32_t)(vrow * 128 + (vcb + i * 4) * 2));
                *(uint2*)(smem + 32768 + off) = hi;
                *(uint2*)(smem + 40960 + off) = lo;
            }
        }
        __syncthreads();

#pragma unroll
        for (int kt = 0; kt < 4; kt++) {
            int kb = kt * 16;
            uint32_t ah[2][4], al[2][4];
#pragma unroll
            for (int mt = 0; mt < 2; mt++) {
                uint32_t off = SW128((uint32_t)((wm + mt * 16 + a_r) * 128 + (kb + a_k8) * 2));
                ldm4(sP_H + off, ah[mt]);
                ldm4(sP_L + off, al[mt]);
            }
#pragma unroll
            for (int ng = 0; ng < 2; ng++) {
                uint32_t boff = SW128((uint32_t)((kb + v_k) * 128 + (wn + ng * 16 + v_n8) * 2));
                uint32_t bh4[4], bl4[4];
                ldm4t(sV_H + boff, bh4);
                ldm4t(sV_L + boff, bl4);
#pragma unroll
                for (int mt = 0; mt < 2; mt++) {
                    mma16816(acc[mt][2 * ng],     ah[mt], bh4[0], bh4[1]);
                    mma16816(acc[mt][2 * ng + 1], ah[mt], bh4[2], bh4[3]);
                    mma16816(acc[mt][2 * ng],     ah[mt], bl4[0], bl4[1]);
                    mma16816(acc[mt][2 * ng + 1], ah[mt], bl4[2], bl4[3]);
                    mma16816(acc[mt][2 * ng],     al[mt], bh4[0], bh4[1]);
                    mma16816(acc[mt][2 * ng + 1], al[mt], bh4[2], bh4[3]);
                }
            }
        }
        __syncthreads();
    }

    // write O -> NX0 hi/lo  (PV output only feeds slot-6 GEMM)
    __nv_bfloat16* Oh = g_NXh + (size_t)b * SLEN * DIM + h * DH;
    __nv_bfloat16* Ol = g_NXl + (size_t)b * SLEN * DIM + h * DH;
#pragma unroll
    for (int mt = 0; mt < 2; mt++) {
        int r0 = i0 + wm + mt * 16 + (lane >> 2);
#pragma unroll
        for (int nt = 0; nt < 4; nt++) {
            int col = wn + nt * 8 + (lane & 3) * 2;
#pragma unroll
            for (int hh = 0; hh < 2; hh++) {
                int row = r0 + hh * 8;
                float v0 = acc[mt][nt][hh * 2], v1 = acc[mt][nt][hh * 2 + 1];
                __nv_bfloat16 h0, l0, h1, l1;
                split_bf(v0, h0, l0); split_bf(v1, h1, l1);
                size_t p = (size_t)row * DIM + col;
                *(uint32_t*)(Oh + p) =
                    (uint32_t)__bfloat16_as_ushort(h0) | ((uint32_t)__bfloat16_as_ushort(h1) << 16);
                *(uint32_t*)(Ol + p) =
                    (uint32_t)__bfloat16_as_ushort(l0) | ((uint32_t)__bfloat16_as_ushort(l1) << 16);
            }
        }
    }
}

// combine (act1: h0*h1 ; act3: relu(h0+h1+h2)) -> NX0 hi/lo
__global__ void combine_k(int node) {
    int a = g_nr[node].act;
    if (a != 1 && a != 3) return;
    size_t stride = (size_t)gridDim.x * blockDim.x;
    for (size_t p = (size_t)blockIdx.x * blockDim.x + threadIdx.x; p < (size_t)MS; p += stride) {
        float v = (a == 1) ? g_h0[p] * g_h1[p]
                           : fmaxf(g_h0[p] + g_h1[p] + g_h2[p], 0.f);
        __nv_bfloat16 h, l; split_bf(v, h, l);
        g_NXh[p] = h; g_NXl[p] = l;
    }
}

// finish (acts 2,4,5,6,7)
__global__ void finish_k(int node) {
    NR r = g_nr[node];
    int a = r.act;
    if (a == 0 || a == 1 || a == 3) return;
    int row = blockIdx.x, t = threadIdx.x;
    float* out = g_outs + (size_t)node * MS;
    size_t p0 = (size_t)row * DIM + t, p1 = p0 + 256;
    if (a == 2) {
        float s0 = g_qv[p0] + g_kv[p0] + g_vv[p0];
        float s1 = g_qv[p1] + g_kv[p1] + g_vv[p1];
        ln_row_store(s0, s1, out, row,
                     g_ptrs.node_g + node * DIM, g_ptrs.node_beta + node * DIM, r.aw);
    } else if (a == 4) {
        out[p0] = r.aw * (g_qv[p0] * sigmoidf_(g_kv[p0]) + g_vv[p0]);
        out[p1] = r.aw * (g_qv[p1] * sigmoidf_(g_kv[p1]) + g_vv[p1]);
    } else if (a == 5) {
        out[p0] = r.aw * (g_qv[p0] + g_h1[p0]);
        out[p1] = r.aw * (g_qv[p1] + g_h1[p1]);
    } else if (a == 6) {
        out[p0] = r.aw * (g_qv[p0] + g_kv[p0]);
        out[p1] = r.aw * (g_qv[p1] + g_kv[p1]);
    } else { // 7
        ln_row_store(g_qv[p0], g_qv[p1], out, row,
                     g_ptrs.node_g + node * DIM, g_ptrs.node_beta + node * DIM, r.aw);
    }
}

// final sum + LN
__global__ void final_k(float* dout) {
    int row = blockIdx.x, t = threadIdx.x;
    size_t p0 = (size_t)row * DIM + t, p1 = p0 + 256;
    float s0 = 0.f, s1 = 0.f;
    for (int c = 0; c < 8; c++) {
        if (!g_processed[c]) {
            s0 += g_outs[(size_t)c * MS + p0];
            s1 += g_outs[(size_t)c * MS + p1];
        }
    }
    ln_row_store(s0, s1, dout, row, g_ptrs.out_g, g_ptrs.out_beta, 1.0f);
}

// ---------------------------------------------------------------------------
// Launch
// ---------------------------------------------------------------------------
extern "C" void kernel_launch(void* const* d_in, const int* in_sizes, int n_in,
                              void* d_out, int out_size) {
    (void)in_sizes; (void)n_in; (void)out_size;
    cudaFuncSetAttribute(gemm_mma, cudaFuncAttributeMaxDynamicSharedMemorySize, GEMM_SMEM);
    cudaFuncSetAttribute(sc_mma,   cudaFuncAttributeMaxDynamicSharedMemorySize, 65536);
    cudaFuncSetAttribute(pv_mma,   cudaFuncAttributeMaxDynamicSharedMemorySize, 49152);

    setup_k<<<1, 1>>>(
        (const float*)d_in[0],  (const float*)d_in[1],  (const float*)d_in[2],
        (const float*)d_in[3],  (const float*)d_in[4],  (const float*)d_in[5],
        (const float*)d_in[6],  (const float*)d_in[7],  (const float*)d_in[8],
        (const float*)d_in[9],  (const float*)d_in[10], (const float*)d_in[11],
        (const float*)d_in[12], (const float*)d_in[13]);
    routing_k<<<1, 1>>>();
    conv_w_all<<<dim3(16, 16, 56), dim3(32, 8)>>>();

    for (int c = 0; c < 8; c++) {
        edge_pre<<<dim3(NROWS, 3), 256>>>(c);
        gemm_mma<<<dim3(4, 32, 3), 256, GEMM_SMEM>>>(c, 0);   // edge q/k/v
        node_prep<<<NROWS, 256>>>(c);
        gemm_mma<<<dim3(4, 32, 3), 256, GEMM_SMEM>>>(c, 3);   // node j0/j1/j2
        sc_mma<<<dim3(8, 8, 32), 256, 65536>>>(c);
        attn_softmax<<<4096, 256>>>(c);
        pv_mma<<<dim3(8, 32), 256, 49152>>>(c);
        combine_k<<<2048, 256>>>(c);
        gemm_mma<<<dim3(4, 32, 1), 256, GEMM_SMEM>>>(c, 6);   // node j3
        finish_k<<<NROWS, 256>>>(c);
    }
    final_k<<<NROWS, 256>>>((float*)d_out);
}

// round 6
// speedup vs baseline: 2.5255x; 1.0668x over previous
#include <cuda_runtime.h>
#include <cuda_bf16.h>
#include <math.h>
#include <stdint.h>

// ---------------------------------------------------------------------------
// Problem constants
// ---------------------------------------------------------------------------
#define NROWS 4096          // B*SLEN
#define DIM   512
#define MS    (4096*512)
#define NHEAD 8
#define DH    64
#define SLEN  1024
#define EPSLN 1e-6f

// ---------------------------------------------------------------------------
// Device-resident input pointer table + route table
// ---------------------------------------------------------------------------
struct Ptrs {
    const float *inpute, *inputo, *node_p, *edge_p;
    const float *edge_W, *edge_b, *edge_g, *edge_beta;
    const float *node_W, *node_b, *node_g, *node_beta;
    const float *out_g, *out_beta;
};
__device__ Ptrs g_ptrs;

struct NR {
    int act; float aw;
    int q_in, q_op, q_e; float q_w;
    int k_valid, k_in, k_op, k_e; float k_w;
    int v_valid, v_in, v_op, v_e; float v_w;
};
__device__ NR  g_nr[8];
__device__ int g_processed[8];

// ---------------------------------------------------------------------------
// Scratch
// ---------------------------------------------------------------------------
__device__ float g_outs[8 * MS];
__device__ float g_qv[MS], g_kv[MS], g_vv[MS];
__device__ float g_h0[MS], g_h1[MS], g_h2[MS];
__device__ __align__(16) __nv_bfloat16 g_EXh[3 * MS], g_EXl[3 * MS];  // edge GEMM inputs
__device__ __align__(16) __nv_bfloat16 g_NXh[3 * MS], g_NXl[3 * MS];  // node GEMM inputs
__device__ __align__(16) __nv_bfloat16 g_Wth[8 * 7 * DIM * DIM];      // W^T hi [node][slot][n][k]
__device__ __align__(16) __nv_bfloat16 g_Wtl[8 * 7 * DIM * DIM];      // W^T lo

// ---------------------------------------------------------------------------
// Helpers
// ---------------------------------------------------------------------------
__device__ __forceinline__ const float* buf_in(int idx) {
    if (idx == 0) return g_ptrs.inpute;
    if (idx == 1) return g_ptrs.inputo;
    return g_outs + (size_t)(idx - 2) * MS;
}

__device__ __forceinline__ float geluf(float x) {
    float x3 = x * x * x;
    return 0.5f * x * (1.0f + tanhf(0.7978845608028654f * (x + 0.044715f * x3)));
}
__device__ __forceinline__ float sigmoidf_(float x) {
    return 1.0f / (1.0f + expf(-x));
}

__device__ __forceinline__ float wsum(float v) {
#pragma unroll
    for (int o = 16; o; o >>= 1) v += __shfl_xor_sync(0xffffffffu, v, o);
    return v;
}

__device__ __forceinline__ void split_bf(float v, __nv_bfloat16& h, __nv_bfloat16& l) {
    h = __float2bfloat16_rn(v);
    l = __float2bfloat16_rn(v - __bfloat162float(h));
}

// ---------------------------------------------------------------------------
// mma.sync / ldmatrix / cp.async helpers
// ---------------------------------------------------------------------------
__device__ __forceinline__ uint32_t smem_u32(const void* p) {
    uint32_t a;
    asm("{ .reg .u64 t; cvta.to.shared.u64 t, %1; cvt.u32.u64 %0, t; }" : "=r"(a) : "l"(p));
    return a;
}
__device__ __forceinline__ void ldm4(uint32_t addr, uint32_t r[4]) {
    asm volatile("ldmatrix.sync.aligned.m8n8.x4.shared.b16 {%0,%1,%2,%3}, [%4];"
                 : "=r"(r[0]), "=r"(r[1]), "=r"(r[2]), "=r"(r[3]) : "r"(addr));
}
__device__ __forceinline__ void ldm4t(uint32_t addr, uint32_t r[4]) {
    asm volatile("ldmatrix.sync.aligned.m8n8.x4.trans.shared.b16 {%0,%1,%2,%3}, [%4];"
                 : "=r"(r[0]), "=r"(r[1]), "=r"(r[2]), "=r"(r[3]) : "r"(addr));
}
__device__ __forceinline__ void mma16816(float c[4], const uint32_t a[4],
                                         uint32_t b0, uint32_t b1) {
    asm volatile(
        "mma.sync.aligned.m16n8k16.row.col.f32.bf16.bf16.f32 "
        "{%0,%1,%2,%3}, {%4,%5,%6,%7}, {%8,%9}, {%0,%1,%2,%3};"
        : "+f"(c[0]), "+f"(c[1]), "+f"(c[2]), "+f"(c[3])
        : "r"(a[0]), "r"(a[1]), "r"(a[2]), "r"(a[3]), "r"(b0), "r"(b1));
}
__device__ __forceinline__ void cpa16(uint32_t dst, const void* src) {
    asm volatile("cp.async.ca.shared.global [%0], [%1], 16;" :: "r"(dst), "l"(src));
}
#define CPA_COMMIT() asm volatile("cp.async.commit_group;" ::: "memory")
#define CPA_WAIT1()  asm volatile("cp.async.wait_group 1;" ::: "memory")
#define CPA_WAIT0()  asm volatile("cp.async.wait_group 0;" ::: "memory")

#define SW128(o) ((o) ^ (((o) >> 3) & 0x70))

__device__ __forceinline__ uint32_t pack_bf2(float x, float y) {
    __nv_bfloat162 h = __float22bfloat162_rn(make_float2(x, y));
    return *(uint32_t*)&h;
}
__device__ __forceinline__ void cvt_hilo(float4 v, uint2& hi, uint2& lo) {
    hi = make_uint2(pack_bf2(v.x, v.y), pack_bf2(v.z, v.w));
    __nv_bfloat162 h0 = *(__nv_bfloat162*)&hi.x;
    __nv_bfloat162 h1 = *(__nv_bfloat162*)&hi.y;
    float lx = v.x - __bfloat162float(h0.x);
    float ly = v.y - __bfloat162float(h0.y);
    float lz = v.z - __bfloat162float(h1.x);
    float lw = v.w - __bfloat162float(h1.y);
    lo = make_uint2(pack_bf2(lx, ly), pack_bf2(lz, lw));
}

// ---------------------------------------------------------------------------
// Setup + routing
// ---------------------------------------------------------------------------
__global__ void setup_k(const float* a0, const float* a1, const float* a2, const float* a3,
                        const float* a4, const float* a5, const float* a6, const float* a7,
                        const float* a8, const float* a9, const float* a10, const float* a11,
                        const float* a12, const float* a13) {
    Ptrs p;
    p.inpute = a0; p.inputo = a1; p.node_p = a2; p.edge_p = a3;
    p.edge_W = a4; p.edge_b = a5; p.edge_g = a6; p.edge_beta = a7;
    p.node_W = a8; p.node_b = a9; p.node_g = a10; p.node_beta = a11;
    p.out_g = a12; p.out_beta = a13;
    g_ptrs = p;
}

__device__ int d_amax(const float* x, int n, int lo) {
    int bi = lo; float bv = x[lo];
    for (int i = lo + 1; i < n; i++) { if (x[i] > bv) { bv = x[i]; bi = i; } }
    return bi;
}
__device__ float d_smw(const float* x, int n, int lo, int sel) {
    float mx = x[lo];
    for (int i = lo + 1; i < n; i++) mx = fmaxf(mx, x[i]);
    float s = 0.f;
    for (int i = lo; i < n; i++) s += expf(x[i] - mx);
    return expf(x[sel] - mx) / s;
}

__global__ void routing_k() {
    if (threadIdx.x || blockIdx.x) return;
    const float* np = g_ptrs.node_p;
    const float* ep = g_ptrs.edge_p;
    for (int i = 0; i < 8; i++) g_processed[i] = 0;
    int lind = 0;
    for (int c = 0; c < 8; c++) {
        int nsrc = (c + 2 < 5) ? c + 2 : 5;
        int snode = c - nsrc;
        int n = nsrc * 5;
        const float* e0 = ep + 0 * 170 + lind * 5;
        const float* e1 = ep + 1 * 170 + lind * 5;
        const float* e2 = ep + 2 * 170 + lind * 5;
        NR r; r.k_valid = 0; r.v_valid = 0;
        r.k_in = 0; r.k_op = 4; r.k_e = 0; r.k_w = 0.f;
        r.v_in = 0; r.v_op = 4; r.v_e = 0; r.v_w = 0.f;

        int nact = d_amax(np + c * 8, 8, 0);
        r.act = nact;
        r.aw = d_smw(np + c * 8, 8, 0, nact);

        int qs = d_amax(e0, n, 5);
        int qse = qs / 5;
        r.q_in = (qse == 0) ? 0 : (snode + qse + 2);
        r.q_op = qs % 5; r.q_e = lind + qse;
        r.q_w = d_smw(e0, n, 5, qs);
        if (r.q_in >= 2) g_processed[r.q_in - 2] = 1;

        if (nact < 7) {
            int lo = (nact > 0) ? 5 : 0;
            int ks = d_amax(e1, n, lo);
            int kse = ks / 5;
            r.k_valid = 1;
            r.k_in = (kse == 0) ? 0 : (snode + kse + 2);
            r.k_op = ks % 5; r.k_e = lind + kse;
            r.k_w = d_smw(e1, n, lo, ks);
            if (r.k_in >= 2) g_processed[r.k_in - 2] = 1;
            int ktype = (kse == 0) ? -2 : -1;
            if (nact < 5) {
                r.v_valid = 1;
                int vs, vlo, vn;
                if (nact == 0 && ktype == -2) { vlo = 0; vn = 5; }
                else if (nact > 0)            { vlo = 5; vn = n; }
                else                          { vlo = 0; vn = n; }
                vs = d_amax(e2, vn, vlo);
                int vse = vs / 5;
                r.v_in = (vse == 0) ? 0 : (snode + vse + 2);
                r.v_op = vs % 5; r.v_e = lind + vse;
                r.v_w = d_smw(e2, vn, vlo, vs);
                if (r.v_in >= 2) g_processed[r.v_in - 2] = 1;
            }
        }
        g_nr[c] = r;
        lind += nsrc;
    }
}

// role r output feeds node GEMM slot 3+r?
__device__ __forceinline__ bool need_hilo_role(int act, int role) {
    if (role == 0) return act == 1 || act == 3;
    if (role == 1) return act == 0 || act == 1 || act == 3 || act == 5;
    return act == 0 || act == 3;
}

// ---------------------------------------------------------------------------
// Weight selection for slot 0..6
// ---------------------------------------------------------------------------
__device__ const float* resolve_w(int node, int slot) {
    NR r = g_nr[node];
    if (slot < 3) {
        int valid, op, e;
        if (slot == 0)      { valid = 1;         op = r.q_op; e = r.q_e; }
        else if (slot == 1) { valid = r.k_valid; op = r.k_op; e = r.k_e; }
        else                { valid = r.v_valid; op = r.v_op; e = r.v_e; }
        if (valid && op <= 3) return g_ptrs.edge_W + (size_t)e * DIM * DIM;
        return nullptr;
    }
    int a = r.act, j = slot - 3;
    bool need =
        (j == 0 && (a == 0 || a == 1 || a == 3)) ||
        (j == 1 && (a == 0 || a == 1 || a == 3 || a == 5)) ||
        (j == 2 && (a == 0 || a == 3)) ||
        (j == 3 && (a == 0 || a == 1 || a == 3));
    if (need) return g_ptrs.node_W + ((size_t)node * 4 + j) * DIM * DIM;
    return nullptr;
}

// Convert+transpose W -> bf16 hi/lo.  grid (16,16,56) block (32,8)
__global__ void conv_w_all() {
    int z = blockIdx.z; int node = z / 7, slot = z % 7;
    const float* W = resolve_w(node, slot);
    if (!W) return;
    __shared__ float tile[32][33];
    int n0 = blockIdx.x * 32, k0 = blockIdx.y * 32;
    int tx = threadIdx.x, ty = threadIdx.y;
#pragma unroll
    for (int dy = 0; dy < 4; dy++)
        tile[ty * 4 + dy][tx] = W[(size_t)(k0 + ty * 4 + dy) * DIM + n0 + tx];
    __syncthreads();
    size_t base = (size_t)z * DIM * DIM;
#pragma unroll
    for (int dy = 0; dy < 4; dy++) {
        int n = n0 + ty * 4 + dy, k = k0 + tx;
        float v = tile[tx][ty * 4 + dy];
        __nv_bfloat16 h, l; split_bf(v, h, l);
        g_Wth[base + (size_t)n * DIM + k] = h;
        g_Wtl[base + (size_t)n * DIM + k] = l;
    }
}

// ---------------------------------------------------------------------------
// edge_pre: warp-per-row. grid (512, 3) block 256 (8 rows/block per role)
// ---------------------------------------------------------------------------
__global__ void edge_pre(int node) {
    int role = blockIdx.y;
    NR r = g_nr[node];
    int valid, in, op, e; float w; float* out;
    if (role == 0)      { valid = 1;         in = r.q_in; op = r.q_op; e = r.q_e; w = r.q_w; out = g_qv; }
    else if (role == 1) { valid = r.k_valid; in = r.k_in; op = r.k_op; e = r.k_e; w = r.k_w; out = g_kv; }
    else                { valid = r.v_valid; in = r.v_in; op = r.v_op; e = r.v_e; w = r.v_w; out = g_vv; }
    if (!valid) return;
    int warp = threadIdx.x >> 5, lane = threadIdx.x & 31;
    int row = blockIdx.x * 8 + warp;
    size_t rb = (size_t)row * DIM;
    const float* x = buf_in(in) + rb;
    float v[16];
#pragma unroll
    for (int i = 0; i < 16; i++) v[i] = x[lane + i * 32];

    __nv_bfloat16* exh = g_EXh + (size_t)role * MS + rb;
    __nv_bfloat16* exl = g_EXl + (size_t)role * MS + rb;
    if (op <= 2) {
        const float* gm = g_ptrs.edge_g + e * DIM;
        const float* bt = g_ptrs.edge_beta + e * DIM;
        float s = 0.f;
#pragma unroll
        for (int i = 0; i < 16; i++) s += v[i];
        float mean = wsum(s) * (1.0f / 512.0f);
        float q = 0.f;
#pragma unroll
        for (int i = 0; i < 16; i++) { float d = v[i] - mean; q += d * d; }
        float inv = rsqrtf(wsum(q) * (1.0f / 512.0f) + EPSLN);
#pragma unroll
        for (int i = 0; i < 16; i++) {
            int c = lane + i * 32;
            float y = (v[i] - mean) * inv * gm[c] + bt[c];
            __nv_bfloat16 h, l; split_bf(y, h, l);
            exh[c] = h; exl[c] = l;
        }
    } else if (op == 3) {
#pragma unroll
        for (int i = 0; i < 16; i++) {
            int c = lane + i * 32;
            __nv_bfloat16 h, l; split_bf(v[i], h, l);
            exh[c] = h; exl[c] = l;
        }
    } else { // op == 4
        bool nh = need_hilo_role(r.act, role);
        __nv_bfloat16* nxh = g_NXh + (size_t)role * MS + rb;
        __nv_bfloat16* nxl = g_NXl + (size_t)role * MS + rb;
#pragma unroll
        for (int i = 0; i < 16; i++) {
            int c = lane + i * 32;
            float y = w * v[i];
            out[rb + c] = y;
            if (nh) {
                __nv_bfloat16 h, l; split_bf(y, h, l);
                nxh[c] = h; nxl[c] = l;
            }
        }
    }
}

// node prep (act0): NX0 = LN(qv) hi/lo ; warp-per-row, grid 512
__global__ void node_prep(int node) {
    NR r = g_nr[node];
    if (r.act != 0) return;
    int warp = threadIdx.x >> 5, lane = threadIdx.x & 31;
    int row = blockIdx.x * 8 + warp;
    size_t rb = (size_t)row * DIM;
    const float* gm = g_ptrs.node_g + node * DIM;
    const float* bt = g_ptrs.node_beta + node * DIM;
    float v[16];
#pragma unroll
    for (int i = 0; i < 16; i++) v[i] = g_qv[rb + lane + i * 32];
    float s = 0.f;
#pragma unroll
    for (int i = 0; i < 16; i++) s += v[i];
    float mean = wsum(s) * (1.0f / 512.0f);
    float q = 0.f;
#pragma unroll
    for (int i = 0; i < 16; i++) { float d = v[i] - mean; q += d * d; }
    float inv = rsqrtf(wsum(q) * (1.0f / 512.0f) + EPSLN);
#pragma unroll
    for (int i = 0; i < 16; i++) {
        int c = lane + i * 32;
        float y = (v[i] - mean) * inv * gm[c] + bt[c];
        __nv_bfloat16 h, l; split_bf(y, h, l);
        g_NXh[rb + c] = h; g_NXl[rb + c] = l;
    }
}

// ---------------------------------------------------------------------------
// GEMM config
// ---------------------------------------------------------------------------
struct GemmCfg {
    const __nv_bfloat16 *Xh, *Xl, *Wh, *Wl;
    const float* Bv;
    int act;            // 0 none, 1 relu, 2 gelu
    float scale;
    const float* res;
    float* out;
    __nv_bfloat16 *oh, *ol;
};

__device__ bool resolve_gemm(int node, int slot, GemmCfg& g) {
    NR r = g_nr[node];
    g.oh = nullptr; g.ol = nullptr; g.res = nullptr;
    size_t wbase = ((size_t)node * 7 + slot) * DIM * DIM;
    g.Wh = g_Wth + wbase; g.Wl = g_Wtl + wbase;
    if (slot < 3) {
        int valid, op, e; float w; float* out;
        if (slot == 0)      { valid = 1;         op = r.q_op; e = r.q_e; w = r.q_w; out = g_qv; }
        else if (slot == 1) { valid = r.k_valid; op = r.k_op; e = r.k_e; w = r.k_w; out = g_kv; }
        else                { valid = r.v_valid; op = r.v_op; e = r.v_e; w = r.v_w; out = g_vv; }
        if (!valid || op == 4) return false;
        g.Xh = g_EXh + (size_t)slot * MS;
        g.Xl = g_EXl + (size_t)slot * MS;
        g.Bv = g_ptrs.edge_b + e * DIM;
        g.act = (op == 0) ? 1 : (op == 1) ? 2 : 0;
        g.scale = w; g.out = out;
        if (need_hilo_role(r.act, slot)) {
            g.oh = g_NXh + (size_t)slot * MS;
            g.ol = g_NXl + (size_t)slot * MS;
        }
        return true;
    }
    int a = r.act;
    int j = slot - 3;
    const float* Bv = g_ptrs.node_b + (node * 4 + j) * DIM;
    if (j == 0) {
        if (a != 0 && a != 1 && a != 3) return false;
        g.Xh = g_NXh; g.Xl = g_NXl;
        g.Bv = (a == 3) ? nullptr : Bv;
        g.act = (a == 1) ? 2 : 0;
        g.scale = 1.f; g.out = g_h0;
        return true;
    }
    if (j == 1) {
        if (a != 0 && a != 1 && a != 3 && a != 5) return false;
        g.Xh = g_NXh + (size_t)1 * MS; g.Xl = g_NXl + (size_t)1 * MS;
        g.Bv = (a == 3) ? nullptr : Bv;
        g.act = (a == 5) ? 2 : 0;
        g.scale = 1.f; g.out = g_h1;
        return true;
    }
    if (j == 2) {
        if (a != 0 && a != 3) return false;
        g.Xh = g_NXh + (size_t)2 * MS; g.Xl = g_NXl + (size_t)2 * MS;
        g.Bv = (a == 3) ? nullptr : Bv;
        g.act = 0; g.scale = 1.f; g.out = g_h2;
        return true;
    }
    if (a != 0 && a != 1 && a != 3) return false;
    g.Xh = g_NXh; g.Xl = g_NXl;
    g.Bv = Bv; g.act = 0; g.scale = r.aw;
    g.res = g_qv; g.out = g_outs + (size_t)node * MS;
    return true;
}

// ---------------------------------------------------------------------------
// Pipelined mma GEMM (unchanged from R5)
// ---------------------------------------------------------------------------
#define GEMM_SMEM 131072

__global__ void __launch_bounds__(256) gemm_mma(int node, int base_slot) {
    int slot = base_slot + blockIdx.z;
    GemmCfg g;
    if (!resolve_gemm(node, slot, g)) return;

    extern __shared__ char smem[];
    uint32_t sbase = smem_u32(smem);
    int t = threadIdx.x, lane = t & 31, wid = t >> 5;
    int m0 = blockIdx.y * 128, n0 = blockIdx.x * 128;
    int wm = (wid & 3) * 32, wn = (wid >> 2) * 64;

    float acc[2][8][4];
#pragma unroll
    for (int i = 0; i < 2; i++)
#pragma unroll
        for (int j = 0; j < 8; j++)
#pragma unroll
            for (int l = 0; l < 4; l++) acc[i][j][l] = 0.f;

    int lrow = t >> 1, lcb = (t & 1) * 32;
    const __nv_bfloat16* pAh = g.Xh + (size_t)(m0 + lrow) * DIM + lcb;
    const __nv_bfloat16* pAl = g.Xl + (size_t)(m0 + lrow) * DIM + lcb;
    const __nv_bfloat16* pBh = g.Wh + (size_t)(n0 + lrow) * DIM + lcb;
    const __nv_bfloat16* pBl = g.Wl + (size_t)(n0 + lrow) * DIM + lcb;
    uint32_t doff[4];
#pragma unroll
    for (int i = 0; i < 4; i++)
        doff[i] = SW128((uint32_t)(lrow * 128 + (lcb + i * 8) * 2));

    int a_r = (lane & 15), a_k8 = (lane >> 4) << 3;
    int b_n = ((lane & 16) >> 1) + (lane & 7), b_k8 = (lane & 8);

    {
        uint32_t sb = sbase;
#pragma unroll
        for (int i = 0; i < 4; i++) {
            cpa16(sb + doff[i],         pAh + i * 8);
            cpa16(sb + 16384 + doff[i], pAl + i * 8);
            cpa16(sb + 32768 + doff[i], pBh + i * 8);
            cpa16(sb + 49152 + doff[i], pBl + i * 8);
        }
        CPA_COMMIT();
    }

    for (int c = 0; c < 8; c++) {
        if (c < 7) {
            int k0 = (c + 1) * 64;
            uint32_t sb = sbase + ((c + 1) & 1) * 65536;
#pragma unroll
            for (int i = 0; i < 4; i++) {
                cpa16(sb + doff[i],         pAh + k0 + i * 8);
                cpa16(sb + 16384 + doff[i], pAl + k0 + i * 8);
                cpa16(sb + 32768 + doff[i], pBh + k0 + i * 8);
                cpa16(sb + 49152 + doff[i], pBl + k0 + i * 8);
            }
            CPA_COMMIT();
            CPA_WAIT1();
        } else {
            CPA_WAIT0();
        }
        __syncthreads();

        uint32_t sA_H = sbase + (c & 1) * 65536;
        uint32_t sA_L = sA_H + 16384, sB_H = sA_H + 32768, sB_L = sA_H + 49152;
#pragma unroll
        for (int kt = 0; kt < 4; kt++) {
            int kb = kt * 16;
            uint32_t ah[2][4], al[2][4];
#pragma unroll
            for (int mt = 0; mt < 2; mt++) {
                uint32_t off = SW128((uint32_t)((wm + mt * 16 + a_r) * 128 + (kb + a_k8) * 2));
                ldm4(sA_H + off, ah[mt]);
                ldm4(sA_L + off, al[mt]);
            }
#pragma unroll
            for (int ng = 0; ng < 4; ng++) {
                uint32_t boff = SW128((uint32_t)((wn + ng * 16 + b_n) * 128 + (kb + b_k8) * 2));
                uint32_t bh4[4], bl4[4];
                ldm4(sB_H + boff, bh4);
                ldm4(sB_L + boff, bl4);
#pragma unroll
                for (int mt = 0; mt < 2; mt++) {
                    mma16816(acc[mt][2 * ng],     ah[mt], bh4[0], bh4[1]);
                    mma16816(acc[mt][2 * ng + 1], ah[mt], bh4[2], bh4[3]);
                    mma16816(acc[mt][2 * ng],     ah[mt], bl4[0], bl4[1]);
                    mma16816(acc[mt][2 * ng + 1], ah[mt], bl4[2], bl4[3]);
                    mma16816(acc[mt][2 * ng],     al[mt], bh4[0], bh4[1]);
                    mma16816(acc[mt][2 * ng + 1], al[mt], bh4[2], bh4[3]);
                }
            }
        }
        __syncthreads();
    }

#pragma unroll
    for (int mt = 0; mt < 2; mt++) {
        int r0 = m0 + wm + mt * 16 + (lane >> 2);
#pragma unroll
        for (int nt = 0; nt < 8; nt++) {
            int col = n0 + wn + nt * 8 + (lane & 3) * 2;
#pragma unroll
            for (int h = 0; h < 2; h++) {
                int row = r0 + h * 8;
                float v0 = acc[mt][nt][h * 2], v1 = acc[mt][nt][h * 2 + 1];
                if (g.Bv) { v0 += g.Bv[col]; v1 += g.Bv[col + 1]; }
                if (g.act == 1)      { v0 = fmaxf(v0, 0.f); v1 = fmaxf(v1, 0.f); }
                else if (g.act == 2) { v0 = geluf(v0); v1 = geluf(v1); }
                if (g.res) {
                    v0 += g.res[(size_t)row * DIM + col];
                    v1 += g.res[(size_t)row * DIM + col + 1];
                }
                v0 *= g.scale; v1 *= g.scale;
                size_t p = (size_t)row * DIM + col;
                *(float2*)(g.out + p) = make_float2(v0, v1);
                if (g.oh) {
                    __nv_bfloat16 h0, l0, h1, l1;
                    split_bf(v0, h0, l0); split_bf(v1, h1, l1);
                    *(uint32_t*)(g.oh + p) =
                        (uint32_t)__bfloat16_as_ushort(h0) | ((uint32_t)__bfloat16_as_ushort(h1) << 16);
                    *(uint32_t*)(g.ol + p) =
                        (uint32_t)__bfloat16_as_ushort(l0) | ((uint32_t)__bfloat16_as_ushort(l1) << 16);
                }
            }
        }
    }
}

// ---------------------------------------------------------------------------
// Flash attention (act0): O = softmax(QK^T/8) V  -> NX0 hi/lo
// grid (SLEN/128=8, BH=32), 256 thr (8 warps), warp w owns rows w*16..w*16+15
// smem: Qh 16K | Ql 16K | Kh 8K | Kl 8K | Vh 8K | Vl 8K = 64KB
// ---------------------------------------------------------------------------
__global__ void __launch_bounds__(256) flash_k(int node) {
    if (g_nr[node].act != 0) return;
    extern __shared__ char smem[];
    uint32_t sQ_H = smem_u32(smem);
    uint32_t sQ_L = sQ_H + 16384;
    uint32_t sK_H = sQ_H + 32768, sK_L = sQ_H + 40960;
    uint32_t sV_H = sQ_H + 49152, sV_L = sQ_H + 57344;

    int t = threadIdx.x, lane = t & 31, wid = t >> 5;
    int bh = blockIdx.y, b = bh >> 3, head = bh & 7;
    int i0 = blockIdx.x * 128;

    const float* Q = g_h0 + (size_t)b * SLEN * DIM + head * DH;
    const float* K = g_h1 + (size_t)b * SLEN * DIM + head * DH;
    const float* V = g_h2 + (size_t)b * SLEN * DIM + head * DH;

    // load Q tile 128x64 -> hi/lo (once)
    {
        int lrow = t >> 1, lcb = (t & 1) * 32;
        const float* qr = Q + (size_t)(i0 + lrow) * DIM + lcb;
#pragma unroll
        for (int i = 0; i < 8; i++) {
            uint2 hi, lo; cvt_hilo(*(const float4*)(qr + i * 4), hi, lo);
            uint32_t off = SW128((uint32_t)(lrow * 128 + (lcb + i * 4) * 2));
            *(uint2*)(smem + off) = hi;
            *(uint2*)(smem + 16384 + off) = lo;
        }
    }

    float O[8][4];
#pragma unroll
    for (int d = 0; d < 8; d++)
#pragma unroll
        for (int l = 0; l < 4; l++) O[d][l] = 0.f;
    float mrow[2] = {-3.4e38f, -3.4e38f};
    float lrow_[2] = {0.f, 0.f};

    int a_r = (lane & 15), a_k8 = (lane >> 4) << 3;
    int b_n = ((lane & 16) >> 1) + (lane & 7), b_k8 = (lane & 8);
    int v_k = (lane & 15), v_n8 = (lane & 16) >> 1;
    int kvrow = t >> 2, kvcb = (t & 3) * 16;

    for (int jc = 0; jc < 16; jc++) {
        int j0 = jc * 64;
        // load K,V chunk 64x64 -> hi/lo
        {
            const float* kr = K + (size_t)(j0 + kvrow) * DIM + kvcb;
            const float* vr = V + (size_t)(j0 + kvrow) * DIM + kvcb;
#pragma unroll
            for (int i = 0; i < 4; i++) {
                uint32_t off = SW128((uint32_t)(kvrow * 128 + (kvcb + i * 4) * 2));
                uint2 hi, lo;
                cvt_hilo(*(const float4*)(kr + i * 4), hi, lo);
                *(uint2*)(smem + 32768 + off) = hi;
                *(uint2*)(smem + 40960 + off) = lo;
                cvt_hilo(*(const float4*)(vr + i * 4), hi, lo);
                *(uint2*)(smem + 49152 + off) = hi;
                *(uint2*)(smem + 57344 + off) = lo;
            }
        }
        __syncthreads();

        // S = Q K^T  (16 rows x 64 j per warp)
        float s[8][4];
#pragma unroll
        for (int j = 0; j < 8; j++)
#pragma unroll
            for (int l = 0; l < 4; l++) s[j][l] = 0.f;
#pragma unroll
        for (int kt = 0; kt < 4; kt++) {
            int kb = kt * 16;
            uint32_t qh[4], ql[4];
            uint32_t qoff = SW128((uint32_t)((wid * 16 + a_r) * 128 + (kb + a_k8) * 2));
            ldm4(sQ_H + qoff, qh);
            ldm4(sQ_L + qoff, ql);
#pragma unroll
            for (int ng = 0; ng < 4; ng++) {
                uint32_t boff = SW128((uint32_t)((ng * 16 + b_n) * 128 + (kb + b_k8) * 2));
                uint32_t kh4[4], kl4[4];
                ldm4(sK_H + boff, kh4);
                ldm4(sK_L + boff, kl4);
                mma16816(s[2 * ng],     qh, kh4[0], kh4[1]);
                mma16816(s[2 * ng + 1], qh, kh4[2], kh4[3]);
                mma16816(s[2 * ng],     qh, kl4[0], kl4[1]);
                mma16816(s[2 * ng + 1], qh, kl4[2], kl4[3]);
                mma16816(s[2 * ng],     ql, kh4[0], kh4[1]);
                mma16816(s[2 * ng + 1], ql, kh4[2], kh4[3]);
            }
        }
        // scale
#pragma unroll
        for (int j = 0; j < 8; j++)
#pragma unroll
            for (int l = 0; l < 4; l++) s[j][l] *= 0.125f;

        // online softmax per row-half (h=0: c0,c1 row r ; h=1: c2,c3 row r+8)
#pragma unroll
        for (int h = 0; h < 2; h++) {
            float mj = -3.4e38f;
#pragma unroll
            for (int j = 0; j < 8; j++) mj = fmaxf(mj, fmaxf(s[j][h * 2], s[j][h * 2 + 1]));
            mj = fmaxf(mj, __shfl_xor_sync(0xffffffffu, mj, 1));
            mj = fmaxf(mj, __shfl_xor_sync(0xffffffffu, mj, 2));
            float mnew = fmaxf(mrow[h], mj);
            float alpha = expf(mrow[h] - mnew);
            float ps = 0.f;
#pragma unroll
            for (int j = 0; j < 8; j++) {
                s[j][h * 2]     = expf(s[j][h * 2] - mnew);
                s[j][h * 2 + 1] = expf(s[j][h * 2 + 1] - mnew);
                ps += s[j][h * 2] + s[j][h * 2 + 1];
            }
            ps += __shfl_xor_sync(0xffffffffu, ps, 1);
            ps += __shfl_xor_sync(0xffffffffu, ps, 2);
            lrow_[h] = lrow_[h] * alpha + ps;
            mrow[h] = mnew;
#pragma unroll
            for (int d = 0; d < 8; d++) {
                O[d][h * 2]     *= alpha;
                O[d][h * 2 + 1] *= alpha;
            }
        }

        // O += P V   (P from s frags, hi/lo split)
#pragma unroll
        for (int g4 = 0; g4 < 4; g4++) {
            uint32_t ah[4], al[4];
            {
                float p0 = s[2 * g4][0], p1 = s[2 * g4][1], p2 = s[2 * g4][2], p3 = s[2 * g4][3];
                float q0 = s[2 * g4 + 1][0], q1 = s[2 * g4 + 1][1], q2 = s[2 * g4 + 1][2], q3 = s[2 * g4 + 1][3];
                uint2 hi, lo;
                cvt_hilo(make_float4(p0, p1, p2, p3), hi, lo);
                ah[0] = hi.x; ah[1] = hi.y; al[0] = lo.x; al[1] = lo.y;
                cvt_hilo(make_float4(q0, q1, q2, q3), hi, lo);
                ah[2] = hi.x; ah[3] = hi.y; al[2] = lo.x; al[3] = lo.y;
            }
            int kb = g4 * 16;
#pragma unroll
            for (int ng = 0; ng < 4; ng++) {
                uint32_t boff = SW128((uint32_t)((kb + v_k) * 128 + (ng * 16 + v_n8) * 2));
                uint32_t vh4[4], vl4[4];
                ldm4t(sV_H + boff, vh4);
                ldm4t(sV_L + boff, vl4);
                mma16816(O[2 * ng],     ah, vh4[0], vh4[1]);
                mma16816(O[2 * ng + 1], ah, vh4[2], vh4[3]);
                mma16816(O[2 * ng],     ah, vl4[0], vl4[1]);
                mma16816(O[2 * ng + 1], ah, vl4[2], vl4[3]);
                mma16816(O[2 * ng],     al, vh4[0], vh4[1]);
                mma16816(O[2 * ng + 1], al, vh4[2], vh4[3]);
            }
        }
        __syncthreads();
    }

    // normalize + write -> NX0 hi/lo
    float inv0 = 1.0f / lrow_[0], inv1 = 1.0f / lrow_[1];
    __nv_bfloat16* Oh = g_NXh + ((size_t)b * SLEN) * DIM + head * DH;
    __nv_bfloat16* Ol = g_NXl + ((size_t)b * SLEN) * DIM + head * DH;
    int r0 = i0 + wid * 16 + (lane >> 2);
#pragma unroll
    for (int d = 0; d < 8; d++) {
        int col = d * 8 + (lane & 3) * 2;
#pragma unroll
        for (int h = 0; h < 2; h++) {
            int row = r0 + h * 8;
            float inv = h ? inv1 : inv0;
            float v0 = O[d][h * 2] * inv, v1 = O[d][h * 2 + 1] * inv;
            __nv_bfloat16 h0, l0, h1, l1;
            split_bf(v0, h0, l0); split_bf(v1, h1, l1);
            size_t p = (size_t)row * DIM + col;
            *(uint32_t*)(Oh + p) =
                (uint32_t)__bfloat16_as_ushort(h0) | ((uint32_t)__bfloat16_as_ushort(h1) << 16);
            *(uint32_t*)(Ol + p) =
                (uint32_t)__bfloat16_as_ushort(l0) | ((uint32_t)__bfloat16_as_ushort(l1) << 16);
        }
    }
}

// combine (act1: h0*h1 ; act3: relu(h0+h1+h2)) -> NX0 hi/lo
__global__ void combine_k(int node) {
    int a = g_nr[node].act;
    if (a != 1 && a != 3) return;
    size_t stride = (size_t)gridDim.x * blockDim.x;
    for (size_t p = (size_t)blockIdx.x * blockDim.x + threadIdx.x; p < (size_t)MS; p += stride) {
        float v = (a == 1) ? g_h0[p] * g_h1[p]
                           : fmaxf(g_h0[p] + g_h1[p] + g_h2[p], 0.f);
        __nv_bfloat16 h, l; split_bf(v, h, l);
        g_NXh[p] = h; g_NXl[p] = l;
    }
}

// finish (acts 2,4,5,6,7) warp-per-row ; grid 512
__global__ void finish_k(int node) {
    NR r = g_nr[node];
    int a = r.act;
    if (a == 0 || a == 1 || a == 3) return;
    int warp = threadIdx.x >> 5, lane = threadIdx.x & 31;
    int row = blockIdx.x * 8 + warp;
    size_t rb = (size_t)row * DIM;
    float* out = g_outs + (size_t)node * MS + rb;
    if (a == 4 || a == 5 || a == 6) {
#pragma unroll
        for (int i = 0; i < 16; i++) {
            int c = lane + i * 32;
            float y;
            if (a == 4)      y = g_qv[rb + c] * sigmoidf_(g_kv[rb + c]) + g_vv[rb + c];
            else if (a == 5) y = g_qv[rb + c] + g_h1[rb + c];
            else             y = g_qv[rb + c] + g_kv[rb + c];
            out[c] = r.aw * y;
        }
        return;
    }
    // a == 2 or 7: LN
    float v[16];
#pragma unroll
    for (int i = 0; i < 16; i++) {
        int c = lane + i * 32;
        v[i] = (a == 2) ? (g_qv[rb + c] + g_kv[rb + c] + g_vv[rb + c]) : g_qv[rb + c];
    }
    float s = 0.f;
#pragma unroll
    for (int i = 0; i < 16; i++) s += v[i];
    float mean = wsum(s) * (1.0f / 512.0f);
    float q = 0.f;
#pragma unroll
    for (int i = 0; i < 16; i++) { float d = v[i] - mean; q += d * d; }
    float inv = rsqrtf(wsum(q) * (1.0f / 512.0f) + EPSLN);
    const float* gm = g_ptrs.node_g + node * DIM;
    const float* bt = g_ptrs.node_beta + node * DIM;
#pragma unroll
    for (int i = 0; i < 16; i++) {
        int c = lane + i * 32;
        out[c] = r.aw * ((v[i] - mean) * inv * gm[c] + bt[c]);
    }
}

// final: sum unprocessed + LN ; warp-per-row, grid 512
__global__ void final_k(float* dout) {
    int warp = threadIdx.x >> 5, lane = threadIdx.x & 31;
    int row = blockIdx.x * 8 + warp;
    size_t rb = (size_t)row * DIM;
    float v[16];
#pragma unroll
    for (int i = 0; i < 16; i++) v[i] = 0.f;
    for (int c = 0; c < 8; c++) {
        if (!g_processed[c]) {
            const float* o = g_outs + (size_t)c * MS + rb;
#pragma unroll
            for (int i = 0; i < 16; i++) v[i] += o[lane + i * 32];
        }
    }
    float s = 0.f;
#pragma unroll
    for (int i = 0; i < 16; i++) s += v[i];
    float mean = wsum(s) * (1.0f / 512.0f);
    float q = 0.f;
#pragma unroll
    for (int i = 0; i < 16; i++) { float d = v[i] - mean; q += d * d; }
    float inv = rsqrtf(wsum(q) * (1.0f / 512.0f) + EPSLN);
#pragma unroll
    for (int i = 0; i < 16; i++) {
        int c = lane + i * 32;
        dout[rb + c] = (v[i] - mean) * inv * g_ptrs.out_g[c] + g_ptrs.out_beta[c];
    }
}

// ---------------------------------------------------------------------------
// Launch
// ---------------------------------------------------------------------------
extern "C" void kernel_launch(void* const* d_in, const int* in_sizes, int n_in,
                              void* d_out, int out_size) {
    (void)in_sizes; (void)n_in; (void)out_size;
    cudaFuncSetAttribute(gemm_mma, cudaFuncAttributeMaxDynamicSharedMemorySize, GEMM_SMEM);
    cudaFuncSetAttribute(flash_k,  cudaFuncAttributeMaxDynamicSharedMemorySize, 65536);

    setup_k<<<1, 1>>>(
        (const float*)d_in[0],  (const float*)d_in[1],  (const float*)d_in[2],
        (const float*)d_in[3],  (const float*)d_in[4],  (const float*)d_in[5],
        (const float*)d_in[6],  (const float*)d_in[7],  (const float*)d_in[8],
        (const float*)d_in[9],  (const float*)d_in[10], (const float*)d_in[11],
        (const float*)d_in[12], (const float*)d_in[13]);
    routing_k<<<1, 1>>>();
    conv_w_all<<<dim3(16, 16, 56), dim3(32, 8)>>>();

    for (int c = 0; c < 8; c++) {
        edge_pre<<<dim3(512, 3), 256>>>(c);
        gemm_mma<<<dim3(4, 32, 3), 256, GEMM_SMEM>>>(c, 0);   // edge q/k/v
        node_prep<<<512, 256>>>(c);
        gemm_mma<<<dim3(4, 32, 3), 256, GEMM_SMEM>>>(c, 3);   // node j0/j1/j2
        flash_k<<<dim3(8, 32), 256, 65536>>>(c);
        combine_k<<<2048, 256>>>(c);
        gemm_mma<<<dim3(4, 32, 1), 256, GEMM_SMEM>>>(c, 6);   // node j3
        finish_k<<<512, 256>>>(c);
    }
    final_k<<<512, 256>>>((float*)d_out);
}

// round 7
// speedup vs baseline: 2.5946x; 1.0273x over previous
#include <cuda_runtime.h>
#include <cuda_bf16.h>
#include <math.h>
#include <stdint.h>

// ---------------------------------------------------------------------------
// Problem constants
// ---------------------------------------------------------------------------
#define NROWS 4096          // B*SLEN
#define DIM   512
#define MS    (4096*512)
#define NHEAD 8
#define DH    64
#define SLEN  1024
#define EPSLN 1e-6f

// ---------------------------------------------------------------------------
// Device-resident input pointer table + route table
// ---------------------------------------------------------------------------
struct Ptrs {
    const float *inpute, *inputo, *node_p, *edge_p;
    const float *edge_W, *edge_b, *edge_g, *edge_beta;
    const float *node_W, *node_b, *node_g, *node_beta;
    const float *out_g, *out_beta;
};
__device__ Ptrs g_ptrs;

struct NR {
    int act; float aw;
    int q_in, q_op, q_e; float q_w;
    int k_valid, k_in, k_op, k_e; float k_w;
    int v_valid, v_in, v_op, v_e; float v_w;
};
__device__ NR  g_nr[8];
__device__ int g_processed[8];

// ---------------------------------------------------------------------------
// Scratch
// ---------------------------------------------------------------------------
__device__ float g_outs[8 * MS];
__device__ float g_qv[MS], g_kv[MS], g_vv[MS];
__device__ float g_h0[MS], g_h1[MS], g_h2[MS];
__device__ __align__(16) __nv_bfloat16 g_EXh[3 * MS], g_EXl[3 * MS];  // edge GEMM inputs
__device__ __align__(16) __nv_bfloat16 g_NXh[3 * MS], g_NXl[3 * MS];  // node GEMM inputs
__device__ __align__(16) __nv_bfloat16 g_Wth[8 * 7 * DIM * DIM];      // W^T hi [node][slot][n][k]
__device__ __align__(16) __nv_bfloat16 g_Wtl[8 * 7 * DIM * DIM];      // W^T lo

// ---------------------------------------------------------------------------
// Helpers
// ---------------------------------------------------------------------------
__device__ __forceinline__ const float* buf_in(int idx) {
    if (idx == 0) return g_ptrs.inpute;
    if (idx == 1) return g_ptrs.inputo;
    return g_outs + (size_t)(idx - 2) * MS;
}

__device__ __forceinline__ float geluf(float x) {
    float x3 = x * x * x;
    return 0.5f * x * (1.0f + tanhf(0.7978845608028654f * (x + 0.044715f * x3)));
}
__device__ __forceinline__ float sigmoidf_(float x) {
    return 1.0f / (1.0f + expf(-x));
}

__device__ __forceinline__ float wsum(float v) {
#pragma unroll
    for (int o = 16; o; o >>= 1) v += __shfl_xor_sync(0xffffffffu, v, o);
    return v;
}

__device__ __forceinline__ void split_bf(float v, __nv_bfloat16& h, __nv_bfloat16& l) {
    h = __float2bfloat16_rn(v);
    l = __float2bfloat16_rn(v - __bfloat162float(h));
}

// ---------------------------------------------------------------------------
// mma.sync / ldmatrix / cp.async helpers
// ---------------------------------------------------------------------------
__device__ __forceinline__ uint32_t smem_u32(const void* p) {
    uint32_t a;
    asm("{ .reg .u64 t; cvta.to.shared.u64 t, %1; cvt.u32.u64 %0, t; }" : "=r"(a) : "l"(p));
    return a;
}
__device__ __forceinline__ void ldm4(uint32_t addr, uint32_t r[4]) {
    asm volatile("ldmatrix.sync.aligned.m8n8.x4.shared.b16 {%0,%1,%2,%3}, [%4];"
                 : "=r"(r[0]), "=r"(r[1]), "=r"(r[2]), "=r"(r[3]) : "r"(addr));
}
__device__ __forceinline__ void ldm4t(uint32_t addr, uint32_t r[4]) {
    asm volatile("ldmatrix.sync.aligned.m8n8.x4.trans.shared.b16 {%0,%1,%2,%3}, [%4];"
                 : "=r"(r[0]), "=r"(r[1]), "=r"(r[2]), "=r"(r[3]) : "r"(addr));
}
__device__ __forceinline__ void mma16816(float c[4], const uint32_t a[4],
                                         uint32_t b0, uint32_t b1) {
    asm volatile(
        "mma.sync.aligned.m16n8k16.row.col.f32.bf16.bf16.f32 "
        "{%0,%1,%2,%3}, {%4,%5,%6,%7}, {%8,%9}, {%0,%1,%2,%3};"
        : "+f"(c[0]), "+f"(c[1]), "+f"(c[2]), "+f"(c[3])
        : "r"(a[0]), "r"(a[1]), "r"(a[2]), "r"(a[3]), "r"(b0), "r"(b1));
}
__device__ __forceinline__ void cpa16(uint32_t dst, const void* src) {
    asm volatile("cp.async.ca.shared.global [%0], [%1], 16;" :: "r"(dst), "l"(src));
}
#define CPA_COMMIT() asm volatile("cp.async.commit_group;" ::: "memory")
#define CPA_WAIT1()  asm volatile("cp.async.wait_group 1;" ::: "memory")
#define CPA_WAIT0()  asm volatile("cp.async.wait_group 0;" ::: "memory")

#define SW128(o) ((o) ^ (((o) >> 3) & 0x70))

__device__ __forceinline__ uint32_t pack_bf2(float x, float y) {
    __nv_bfloat162 h = __float22bfloat162_rn(make_float2(x, y));
    return *(uint32_t*)&h;
}
__device__ __forceinline__ void cvt_hilo(float4 v, uint2& hi, uint2& lo) {
    hi = make_uint2(pack_bf2(v.x, v.y), pack_bf2(v.z, v.w));
    __nv_bfloat162 h0 = *(__nv_bfloat162*)&hi.x;
    __nv_bfloat162 h1 = *(__nv_bfloat162*)&hi.y;
    float lx = v.x - __bfloat162float(h0.x);
    float ly = v.y - __bfloat162float(h0.y);
    float lz = v.z - __bfloat162float(h1.x);
    float lw = v.w - __bfloat162float(h1.y);
    lo = make_uint2(pack_bf2(lx, ly), pack_bf2(lz, lw));
}

// ---------------------------------------------------------------------------
// Setup + routing
// ---------------------------------------------------------------------------
__global__ void setup_k(const float* a0, const float* a1, const float* a2, const float* a3,
                        const float* a4, const float* a5, const float* a6, const float* a7,
                        const float* a8, const float* a9, const float* a10, const float* a11,
                        const float* a12, const float* a13) {
    Ptrs p;
    p.inpute = a0; p.inputo = a1; p.node_p = a2; p.edge_p = a3;
    p.edge_W = a4; p.edge_b = a5; p.edge_g = a6; p.edge_beta = a7;
    p.node_W = a8; p.node_b = a9; p.node_g = a10; p.node_beta = a11;
    p.out_g = a12; p.out_beta = a13;
    g_ptrs = p;
}

__device__ int d_amax(const float* x, int n, int lo) {
    int bi = lo; float bv = x[lo];
    for (int i = lo + 1; i < n; i++) { if (x[i] > bv) { bv = x[i]; bi = i; } }
    return bi;
}
__device__ float d_smw(const float* x, int n, int lo, int sel) {
    float mx = x[lo];
    for (int i = lo + 1; i < n; i++) mx = fmaxf(mx, x[i]);
    float s = 0.f;
    for (int i = lo; i < n; i++) s += expf(x[i] - mx);
    return expf(x[sel] - mx) / s;
}

__global__ void routing_k() {
    if (threadIdx.x || blockIdx.x) return;
    const float* np = g_ptrs.node_p;
    const float* ep = g_ptrs.edge_p;
    for (int i = 0; i < 8; i++) g_processed[i] = 0;
    int lind = 0;
    for (int c = 0; c < 8; c++) {
        int nsrc = (c + 2 < 5) ? c + 2 : 5;
        int snode = c - nsrc;
        int n = nsrc * 5;
        const float* e0 = ep + 0 * 170 + lind * 5;
        const float* e1 = ep + 1 * 170 + lind * 5;
        const float* e2 = ep + 2 * 170 + lind * 5;
        NR r; r.k_valid = 0; r.v_valid = 0;
        r.k_in = 0; r.k_op = 4; r.k_e = 0; r.k_w = 0.f;
        r.v_in = 0; r.v_op = 4; r.v_e = 0; r.v_w = 0.f;

        int nact = d_amax(np + c * 8, 8, 0);
        r.act = nact;
        r.aw = d_smw(np + c * 8, 8, 0, nact);

        int qs = d_amax(e0, n, 5);
        int qse = qs / 5;
        r.q_in = (qse == 0) ? 0 : (snode + qse + 2);
        r.q_op = qs % 5; r.q_e = lind + qse;
        r.q_w = d_smw(e0, n, 5, qs);
        if (r.q_in >= 2) g_processed[r.q_in - 2] = 1;

        if (nact < 7) {
            int lo = (nact > 0) ? 5 : 0;
            int ks = d_amax(e1, n, lo);
            int kse = ks / 5;
            r.k_valid = 1;
            r.k_in = (kse == 0) ? 0 : (snode + kse + 2);
            r.k_op = ks % 5; r.k_e = lind + kse;
            r.k_w = d_smw(e1, n, lo, ks);
            if (r.k_in >= 2) g_processed[r.k_in - 2] = 1;
            int ktype = (kse == 0) ? -2 : -1;
            if (nact < 5) {
                r.v_valid = 1;
                int vs, vlo, vn;
                if (nact == 0 && ktype == -2) { vlo = 0; vn = 5; }
                else if (nact > 0)            { vlo = 5; vn = n; }
                else                          { vlo = 0; vn = n; }
                vs = d_amax(e2, vn, vlo);
                int vse = vs / 5;
                r.v_in = (vse == 0) ? 0 : (snode + vse + 2);
                r.v_op = vs % 5; r.v_e = lind + vse;
                r.v_w = d_smw(e2, vn, vlo, vs);
                if (r.v_in >= 2) g_processed[r.v_in - 2] = 1;
            }
        }
        g_nr[c] = r;
        lind += nsrc;
    }
}

// role r output feeds node GEMM slot 3+r?
__device__ __forceinline__ bool need_hilo_role(int act, int role) {
    if (role == 0) return act == 1 || act == 3;
    if (role == 1) return act == 0 || act == 1 || act == 3 || act == 5;
    return act == 0 || act == 3;
}

// ---------------------------------------------------------------------------
// Weight selection for slot 0..6
// ---------------------------------------------------------------------------
__device__ const float* resolve_w(int node, int slot) {
    NR r = g_nr[node];
    if (slot < 3) {
        int valid, op, e;
        if (slot == 0)      { valid = 1;         op = r.q_op; e = r.q_e; }
        else if (slot == 1) { valid = r.k_valid; op = r.k_op; e = r.k_e; }
        else                { valid = r.v_valid; op = r.v_op; e = r.v_e; }
        if (valid && op <= 3) return g_ptrs.edge_W + (size_t)e * DIM * DIM;
        return nullptr;
    }
    int a = r.act, j = slot - 3;
    bool need =
        (j == 0 && (a == 0 || a == 1 || a == 3)) ||
        (j == 1 && (a == 0 || a == 1 || a == 3 || a == 5)) ||
        (j == 2 && (a == 0 || a == 3)) ||
        (j == 3 && (a == 0 || a == 1 || a == 3));
    if (need) return g_ptrs.node_W + ((size_t)node * 4 + j) * DIM * DIM;
    return nullptr;
}

// Convert+transpose W -> bf16 hi/lo.  grid (16,16,56) block (32,8)
__global__ void conv_w_all() {
    int z = blockIdx.z; int node = z / 7, slot = z % 7;
    const float* W = resolve_w(node, slot);
    if (!W) return;
    __shared__ float tile[32][33];
    int n0 = blockIdx.x * 32, k0 = blockIdx.y * 32;
    int tx = threadIdx.x, ty = threadIdx.y;
#pragma unroll
    for (int dy = 0; dy < 4; dy++)
        tile[ty * 4 + dy][tx] = W[(size_t)(k0 + ty * 4 + dy) * DIM + n0 + tx];
    __syncthreads();
    size_t base = (size_t)z * DIM * DIM;
#pragma unroll
    for (int dy = 0; dy < 4; dy++) {
        int n = n0 + ty * 4 + dy, k = k0 + tx;
        float v = tile[tx][ty * 4 + dy];
        __nv_bfloat16 h, l; split_bf(v, h, l);
        g_Wth[base + (size_t)n * DIM + k] = h;
        g_Wtl[base + (size_t)n * DIM + k] = l;
    }
}

// ---------------------------------------------------------------------------
// edge_pre: warp-per-row. grid (512, 3) block 256 (8 rows/block per role)
// ---------------------------------------------------------------------------
__global__ void edge_pre(int node) {
    int role = blockIdx.y;
    NR r = g_nr[node];
    int valid, in, op, e; float w; float* out;
    if (role == 0)      { valid = 1;         in = r.q_in; op = r.q_op; e = r.q_e; w = r.q_w; out = g_qv; }
    else if (role == 1) { valid = r.k_valid; in = r.k_in; op = r.k_op; e = r.k_e; w = r.k_w; out = g_kv; }
    else                { valid = r.v_valid; in = r.v_in; op = r.v_op; e = r.v_e; w = r.v_w; out = g_vv; }
    if (!valid) return;
    int warp = threadIdx.x >> 5, lane = threadIdx.x & 31;
    int row = blockIdx.x * 8 + warp;
    size_t rb = (size_t)row * DIM;
    const float* x = buf_in(in) + rb;
    float v[16];
#pragma unroll
    for (int i = 0; i < 16; i++) v[i] = x[lane + i * 32];

    __nv_bfloat16* exh = g_EXh + (size_t)role * MS + rb;
    __nv_bfloat16* exl = g_EXl + (size_t)role * MS + rb;
    if (op <= 2) {
        const float* gm = g_ptrs.edge_g + e * DIM;
        const float* bt = g_ptrs.edge_beta + e * DIM;
        float s = 0.f;
#pragma unroll
        for (int i = 0; i < 16; i++) s += v[i];
        float mean = wsum(s) * (1.0f / 512.0f);
        float q = 0.f;
#pragma unroll
        for (int i = 0; i < 16; i++) { float d = v[i] - mean; q += d * d; }
        float inv = rsqrtf(wsum(q) * (1.0f / 512.0f) + EPSLN);
#pragma unroll
        for (int i = 0; i < 16; i++) {
            int c = lane + i * 32;
            float y = (v[i] - mean) * inv * gm[c] + bt[c];
            __nv_bfloat16 h, l; split_bf(y, h, l);
            exh[c] = h; exl[c] = l;
        }
    } else if (op == 3) {
#pragma unroll
        for (int i = 0; i < 16; i++) {
            int c = lane + i * 32;
            __nv_bfloat16 h, l; split_bf(v[i], h, l);
            exh[c] = h; exl[c] = l;
        }
    } else { // op == 4
        bool nh = need_hilo_role(r.act, role);
        __nv_bfloat16* nxh = g_NXh + (size_t)role * MS + rb;
        __nv_bfloat16* nxl = g_NXl + (size_t)role * MS + rb;
#pragma unroll
        for (int i = 0; i < 16; i++) {
            int c = lane + i * 32;
            float y = w * v[i];
            out[rb + c] = y;
            if (nh) {
                __nv_bfloat16 h, l; split_bf(y, h, l);
                nxh[c] = h; nxl[c] = l;
            }
        }
    }
}

// node prep (act0): NX0 = LN(qv) hi/lo ; warp-per-row, grid 512
__global__ void node_prep(int node) {
    NR r = g_nr[node];
    if (r.act != 0) return;
    int warp = threadIdx.x >> 5, lane = threadIdx.x & 31;
    int row = blockIdx.x * 8 + warp;
    size_t rb = (size_t)row * DIM;
    const float* gm = g_ptrs.node_g + node * DIM;
    const float* bt = g_ptrs.node_beta + node * DIM;
    float v[16];
#pragma unroll
    for (int i = 0; i < 16; i++) v[i] = g_qv[rb + lane + i * 32];
    float s = 0.f;
#pragma unroll
    for (int i = 0; i < 16; i++) s += v[i];
    float mean = wsum(s) * (1.0f / 512.0f);
    float q = 0.f;
#pragma unroll
    for (int i = 0; i < 16; i++) { float d = v[i] - mean; q += d * d; }
    float inv = rsqrtf(wsum(q) * (1.0f / 512.0f) + EPSLN);
#pragma unroll
    for (int i = 0; i < 16; i++) {
        int c = lane + i * 32;
        float y = (v[i] - mean) * inv * gm[c] + bt[c];
        __nv_bfloat16 h, l; split_bf(y, h, l);
        g_NXh[rb + c] = h; g_NXl[rb + c] = l;
    }
}

// ---------------------------------------------------------------------------
// GEMM config
// ---------------------------------------------------------------------------
struct GemmCfg {
    const __nv_bfloat16 *Xh, *Xl, *Wh, *Wl;
    const float* Bv;
    int act;            // 0 none, 1 relu, 2 gelu
    float scale;
    const float* res;
    float* out;
    __nv_bfloat16 *oh, *ol;
};

__device__ bool resolve_gemm(int node, int slot, GemmCfg& g) {
    NR r = g_nr[node];
    g.oh = nullptr; g.ol = nullptr; g.res = nullptr;
    size_t wbase = ((size_t)node * 7 + slot) * DIM * DIM;
    g.Wh = g_Wth + wbase; g.Wl = g_Wtl + wbase;
    if (slot < 3) {
        int valid, op, e; float w; float* out;
        if (slot == 0)      { valid = 1;         op = r.q_op; e = r.q_e; w = r.q_w; out = g_qv; }
        else if (slot == 1) { valid = r.k_valid; op = r.k_op; e = r.k_e; w = r.k_w; out = g_kv; }
        else                { valid = r.v_valid; op = r.v_op; e = r.v_e; w = r.v_w; out = g_vv; }
        if (!valid || op == 4) return false;
        g.Xh = g_EXh + (size_t)slot * MS;
        g.Xl = g_EXl + (size_t)slot * MS;
        g.Bv = g_ptrs.edge_b + e * DIM;
        g.act = (op == 0) ? 1 : (op == 1) ? 2 : 0;
        g.scale = w; g.out = out;
        if (need_hilo_role(r.act, slot)) {
            g.oh = g_NXh + (size_t)slot * MS;
            g.ol = g_NXl + (size_t)slot * MS;
        }
        return true;
    }
    int a = r.act;
    int j = slot - 3;
    const float* Bv = g_ptrs.node_b + (node * 4 + j) * DIM;
    if (j == 0) {
        if (a != 0 && a != 1 && a != 3) return false;
        g.Xh = g_NXh; g.Xl = g_NXl;
        g.Bv = (a == 3) ? nullptr : Bv;
        g.act = (a == 1) ? 2 : 0;
        g.scale = 1.f; g.out = g_h0;
        return true;
    }
    if (j == 1) {
        if (a != 0 && a != 1 && a != 3 && a != 5) return false;
        g.Xh = g_NXh + (size_t)1 * MS; g.Xl = g_NXl + (size_t)1 * MS;
        g.Bv = (a == 3) ? nullptr : Bv;
        g.act = (a == 5) ? 2 : 0;
        g.scale = 1.f; g.out = g_h1;
        return true;
    }
    if (j == 2) {
        if (a != 0 && a != 3) return false;
        g.Xh = g_NXh + (size_t)2 * MS; g.Xl = g_NXl + (size_t)2 * MS;
        g.Bv = (a == 3) ? nullptr : Bv;
        g.act = 0; g.scale = 1.f; g.out = g_h2;
        return true;
    }
    if (a != 0 && a != 1 && a != 3) return false;
    g.Xh = g_NXh; g.Xl = g_NXl;
    g.Bv = Bv; g.act = 0; g.scale = r.aw;
    g.res = g_qv; g.out = g_outs + (size_t)node * MS;
    return true;
}

// ---------------------------------------------------------------------------
// Pipelined mma GEMM: CTA tile 128(M) x 64(N), warp tile 32x32, K-chunk 64
// smem/stage: A_h 16K | A_l 16K | B_h 8K | B_l 8K = 48K ; 2 stages = 96KB
// grid (8, 32, nz) block 256, 2 CTAs/SM
// ---------------------------------------------------------------------------
#define GEMM_SMEM 98304
#define STAGE_STRIDE 49152

__global__ void __launch_bounds__(256, 2) gemm_mma(int node, int base_slot) {
    int slot = base_slot + blockIdx.z;
    GemmCfg g;
    if (!resolve_gemm(node, slot, g)) return;

    extern __shared__ char smem[];
    uint32_t sbase = smem_u32(smem);
    int t = threadIdx.x, lane = t & 31, wid = t >> 5;
    int m0 = blockIdx.y * 128, n0 = blockIdx.x * 64;
    int wm = (wid & 3) * 32, wn = (wid >> 2) * 32;

    float acc[2][4][4];
#pragma unroll
    for (int i = 0; i < 2; i++)
#pragma unroll
        for (int j = 0; j < 4; j++)
#pragma unroll
            for (int l = 0; l < 4; l++) acc[i][j][l] = 0.f;

    // A loader: 2 threads/row (128 rows), 32 bf16 each
    int arow = t >> 1, acb = (t & 1) * 32;
    const __nv_bfloat16* pAh = g.Xh + (size_t)(m0 + arow) * DIM + acb;
    const __nv_bfloat16* pAl = g.Xl + (size_t)(m0 + arow) * DIM + acb;
    uint32_t daoff[4];
#pragma unroll
    for (int i = 0; i < 4; i++)
        daoff[i] = SW128((uint32_t)(arow * 128 + (acb + i * 8) * 2));
    // B loader: 4 threads/row (64 rows), 16 bf16 each
    int brow = t >> 2, bcb = (t & 3) * 16;
    const __nv_bfloat16* pBh = g.Wh + (size_t)(n0 + brow) * DIM + bcb;
    const __nv_bfloat16* pBl = g.Wl + (size_t)(n0 + brow) * DIM + bcb;
    uint32_t dboff[2];
#pragma unroll
    for (int i = 0; i < 2; i++)
        dboff[i] = SW128((uint32_t)(brow * 128 + (bcb + i * 8) * 2));

    // ldmatrix lane addressing
    int a_r = (lane & 15), a_k8 = (lane >> 4) << 3;
    int b_n = ((lane & 16) >> 1) + (lane & 7), b_k8 = (lane & 8);

    // prologue: stage 0 <- chunk 0
    {
        uint32_t sb = sbase;
#pragma unroll
        for (int i = 0; i < 4; i++) {
            cpa16(sb + daoff[i],         pAh + i * 8);
            cpa16(sb + 16384 + daoff[i], pAl + i * 8);
        }
#pragma unroll
        for (int i = 0; i < 2; i++) {
            cpa16(sb + 32768 + dboff[i], pBh + i * 8);
            cpa16(sb + 40960 + dboff[i], pBl + i * 8);
        }
        CPA_COMMIT();
    }

    for (int c = 0; c < 8; c++) {
        if (c < 7) {
            int k0 = (c + 1) * 64;
            uint32_t sb = sbase + ((c + 1) & 1) * STAGE_STRIDE;
#pragma unroll
            for (int i = 0; i < 4; i++) {
                cpa16(sb + daoff[i],         pAh + k0 + i * 8);
                cpa16(sb + 16384 + daoff[i], pAl + k0 + i * 8);
            }
#pragma unroll
            for (int i = 0; i < 2; i++) {
                cpa16(sb + 32768 + dboff[i], pBh + k0 + i * 8);
                cpa16(sb + 40960 + dboff[i], pBl + k0 + i * 8);
            }
            CPA_COMMIT();
            CPA_WAIT1();
        } else {
            CPA_WAIT0();
        }
        __syncthreads();

        uint32_t sA_H = sbase + (c & 1) * STAGE_STRIDE;
        uint32_t sA_L = sA_H + 16384, sB_H = sA_H + 32768, sB_L = sA_H + 40960;
#pragma unroll
        for (int kt = 0; kt < 4; kt++) {
            int kb = kt * 16;
            uint32_t ah[2][4], al[2][4];
#pragma unroll
            for (int mt = 0; mt < 2; mt++) {
                uint32_t off = SW128((uint32_t)((wm + mt * 16 + a_r) * 128 + (kb + a_k8) * 2));
                ldm4(sA_H + off, ah[mt]);
                ldm4(sA_L + off, al[mt]);
            }
#pragma unroll
            for (int ng = 0; ng < 2; ng++) {
                uint32_t boff = SW128((uint32_t)((wn + ng * 16 + b_n) * 128 + (kb + b_k8) * 2));
                uint32_t bh4[4], bl4[4];
                ldm4(sB_H + boff, bh4);
                ldm4(sB_L + boff, bl4);
#pragma unroll
                for (int mt = 0; mt < 2; mt++) {
                    mma16816(acc[mt][2 * ng],     ah[mt], bh4[0], bh4[1]);
                    mma16816(acc[mt][2 * ng + 1], ah[mt], bh4[2], bh4[3]);
                    mma16816(acc[mt][2 * ng],     ah[mt], bl4[0], bl4[1]);
                    mma16816(acc[mt][2 * ng + 1], ah[mt], bl4[2], bl4[3]);
                    mma16816(acc[mt][2 * ng],     al[mt], bh4[0], bh4[1]);
                    mma16816(acc[mt][2 * ng + 1], al[mt], bh4[2], bh4[3]);
                }
            }
        }
        __syncthreads();
    }

    // epilogue
#pragma unroll
    for (int mt = 0; mt < 2; mt++) {
        int r0 = m0 + wm + mt * 16 + (lane >> 2);
#pragma unroll
        for (int nt = 0; nt < 4; nt++) {
            int col = n0 + wn + nt * 8 + (lane & 3) * 2;
#pragma unroll
            for (int h = 0; h < 2; h++) {
                int row = r0 + h * 8;
                float v0 = acc[mt][nt][h * 2], v1 = acc[mt][nt][h * 2 + 1];
                if (g.Bv) { v0 += g.Bv[col]; v1 += g.Bv[col + 1]; }
                if (g.act == 1)      { v0 = fmaxf(v0, 0.f); v1 = fmaxf(v1, 0.f); }
                else if (g.act == 2) { v0 = geluf(v0); v1 = geluf(v1); }
                if (g.res) {
                    v0 += g.res[(size_t)row * DIM + col];
                    v1 += g.res[(size_t)row * DIM + col + 1];
                }
                v0 *= g.scale; v1 *= g.scale;
                size_t p = (size_t)row * DIM + col;
                *(float2*)(g.out + p) = make_float2(v0, v1);
                if (g.oh) {
                    __nv_bfloat16 h0, l0, h1, l1;
                    split_bf(v0, h0, l0); split_bf(v1, h1, l1);
                    *(uint32_t*)(g.oh + p) =
                        (uint32_t)__bfloat16_as_ushort(h0) | ((uint32_t)__bfloat16_as_ushort(h1) << 16);
                    *(uint32_t*)(g.ol + p) =
                        (uint32_t)__bfloat16_as_ushort(l0) | ((uint32_t)__bfloat16_as_ushort(l1) << 16);
                }
            }
        }
    }
}

// ---------------------------------------------------------------------------
// Flash attention (act0): O = softmax(QK^T/8) V  -> NX0 hi/lo
// grid (SLEN/128=8, BH=32), 256 thr (8 warps), warp w owns rows w*16..w*16+15
// smem: Qh 16K | Ql 16K | Kh 8K | Kl 8K | Vh 8K | Vl 8K = 64KB
// ---------------------------------------------------------------------------
__global__ void __launch_bounds__(256) flash_k(int node) {
    if (g_nr[node].act != 0) return;
    extern __shared__ char smem[];
    uint32_t sQ_H = smem_u32(smem);
    uint32_t sQ_L = sQ_H + 16384;
    uint32_t sK_H = sQ_H + 32768, sK_L = sQ_H + 40960;
    uint32_t sV_H = sQ_H + 49152, sV_L = sQ_H + 57344;

    int t = threadIdx.x, lane = t & 31, wid = t >> 5;
    int bh = blockIdx.y, b = bh >> 3, head = bh & 7;
    int i0 = blockIdx.x * 128;

    const float* Q = g_h0 + (size_t)b * SLEN * DIM + head * DH;
    const float* K = g_h1 + (size_t)b * SLEN * DIM + head * DH;
    const float* V = g_h2 + (size_t)b * SLEN * DIM + head * DH;

    // load Q tile 128x64 -> hi/lo (once)
    {
        int lrow = t >> 1, lcb = (t & 1) * 32;
        const float* qr = Q + (size_t)(i0 + lrow) * DIM + lcb;
#pragma unroll
        for (int i = 0; i < 8; i++) {
            uint2 hi, lo; cvt_hilo(*(const float4*)(qr + i * 4), hi, lo);
            uint32_t off = SW128((uint32_t)(lrow * 128 + (lcb + i * 4) * 2));
            *(uint2*)(smem + off) = hi;
            *(uint2*)(smem + 16384 + off) = lo;
        }
    }

    float O[8][4];
#pragma unroll
    for (int d = 0; d < 8; d++)
#pragma unroll
        for (int l = 0; l < 4; l++) O[d][l] = 0.f;
    float mrow[2] = {-3.4e38f, -3.4e38f};
    float lrow_[2] = {0.f, 0.f};

    int a_r = (lane & 15), a_k8 = (lane >> 4) << 3;
    int b_n = ((lane & 16) >> 1) + (lane & 7), b_k8 = (lane & 8);
    int v_k = (lane & 15), v_n8 = (lane & 16) >> 1;
    int kvrow = t >> 2, kvcb = (t & 3) * 16;

    for (int jc = 0; jc < 16; jc++) {
        int j0 = jc * 64;
        // load K,V chunk 64x64 -> hi/lo
        {
            const float* kr = K + (size_t)(j0 + kvrow) * DIM + kvcb;
            const float* vr = V + (size_t)(j0 + kvrow) * DIM + kvcb;
#pragma unroll
            for (int i = 0; i < 4; i++) {
                uint32_t off = SW128((uint32_t)(kvrow * 128 + (kvcb + i * 4) * 2));
                uint2 hi, lo;
                cvt_hilo(*(const float4*)(kr + i * 4), hi, lo);
                *(uint2*)(smem + 32768 + off) = hi;
                *(uint2*)(smem + 40960 + off) = lo;
                cvt_hilo(*(const float4*)(vr + i * 4), hi, lo);
                *(uint2*)(smem + 49152 + off) = hi;
                *(uint2*)(smem + 57344 + off) = lo;
            }
        }
        __syncthreads();

        // S = Q K^T  (16 rows x 64 j per warp)
        float s[8][4];
#pragma unroll
        for (int j = 0; j < 8; j++)
#pragma unroll
            for (int l = 0; l < 4; l++) s[j][l] = 0.f;
#pragma unroll
        for (int kt = 0; kt < 4; kt++) {
            int kb = kt * 16;
            uint32_t qh[4], ql[4];
            uint32_t qoff = SW128((uint32_t)((wid * 16 + a_r) * 128 + (kb + a_k8) * 2));
            ldm4(sQ_H + qoff, qh);
            ldm4(sQ_L + qoff, ql);
#pragma unroll
            for (int ng = 0; ng < 4; ng++) {
                uint32_t boff = SW128((uint32_t)((ng * 16 + b_n) * 128 + (kb + b_k8) * 2));
                uint32_t kh4[4], kl4[4];
                ldm4(sK_H + boff, kh4);
                ldm4(sK_L + boff, kl4);
                mma16816(s[2 * ng],     qh, kh4[0], kh4[1]);
                mma16816(s[2 * ng + 1], qh, kh4[2], kh4[3]);
                mma16816(s[2 * ng],     qh, kl4[0], kl4[1]);
                mma16816(s[2 * ng + 1], qh, kl4[2], kl4[3]);
                mma16816(s[2 * ng],     ql, kh4[0], kh4[1]);
                mma16816(s[2 * ng + 1], ql, kh4[2], kh4[3]);
            }
        }
        // scale
#pragma unroll
        for (int j = 0; j < 8; j++)
#pragma unroll
            for (int l = 0; l < 4; l++) s[j][l] *= 0.125f;

        // online softmax per row-half
#pragma unroll
        for (int h = 0; h < 2; h++) {
            float mj = -3.4e38f;
#pragma unroll
            for (int j = 0; j < 8; j++) mj = fmaxf(mj, fmaxf(s[j][h * 2], s[j][h * 2 + 1]));
            mj = fmaxf(mj, __shfl_xor_sync(0xffffffffu, mj, 1));
            mj = fmaxf(mj, __shfl_xor_sync(0xffffffffu, mj, 2));
            float mnew = fmaxf(mrow[h], mj);
            float alpha = expf(mrow[h] - mnew);
            float ps = 0.f;
#pragma unroll
            for (int j = 0; j < 8; j++) {
                s[j][h * 2]     = expf(s[j][h * 2] - mnew);
                s[j][h * 2 + 1] = expf(s[j][h * 2 + 1] - mnew);
                ps += s[j][h * 2] + s[j][h * 2 + 1];
            }
            ps += __shfl_xor_sync(0xffffffffu, ps, 1);
            ps += __shfl_xor_sync(0xffffffffu, ps, 2);
            lrow_[h] = lrow_[h] * alpha + ps;
            mrow[h] = mnew;
#pragma unroll
            for (int d = 0; d < 8; d++) {
                O[d][h * 2]     *= alpha;
                O[d][h * 2 + 1] *= alpha;
            }
        }

        // O += P V
#pragma unroll
        for (int g4 = 0; g4 < 4; g4++) {
            uint32_t ah[4], al[4];
            {
                uint2 hi, lo;
                cvt_hilo(make_float4(s[2 * g4][0], s[2 * g4][1], s[2 * g4][2], s[2 * g4][3]), hi, lo);
                ah[0] = hi.x; ah[1] = hi.y; al[0] = lo.x; al[1] = lo.y;
                cvt_hilo(make_float4(s[2 * g4 + 1][0], s[2 * g4 + 1][1], s[2 * g4 + 1][2], s[2 * g4 + 1][3]), hi, lo);
                ah[2] = hi.x; ah[3] = hi.y; al[2] = lo.x; al[3] = lo.y;
            }
            int kb = g4 * 16;
#pragma unroll
            for (int ng = 0; ng < 4; ng++) {
                uint32_t boff = SW128((uint32_t)((kb + v_k) * 128 + (ng * 16 + v_n8) * 2));
                uint32_t vh4[4], vl4[4];
                ldm4t(sV_H + boff, vh4);
                ldm4t(sV_L + boff, vl4);
                mma16816(O[2 * ng],     ah, vh4[0], vh4[1]);
                mma16816(O[2 * ng + 1], ah, vh4[2], vh4[3]);
                mma16816(O[2 * ng],     ah, vl4[0], vl4[1]);
                mma16816(O[2 * ng + 1], ah, vl4[2], vl4[3]);
                mma16816(O[2 * ng],     al, vh4[0], vh4[1]);
                mma16816(O[2 * ng + 1], al, vh4[2], vh4[3]);
            }
        }
        __syncthreads();
    }

    // normalize + write -> NX0 hi/lo
    float inv0 = 1.0f / lrow_[0], inv1 = 1.0f / lrow_[1];
    __nv_bfloat16* Oh = g_NXh + ((size_t)b * SLEN) * DIM + head * DH;
    __nv_bfloat16* Ol = g_NXl + ((size_t)b * SLEN) * DIM + head * DH;
    int r0 = i0 + wid * 16 + (lane >> 2);
#pragma unroll
    for (int d = 0; d < 8; d++) {
        int col = d * 8 + (lane & 3) * 2;
#pragma unroll
        for (int h = 0; h < 2; h++) {
            int row = r0 + h * 8;
            float inv = h ? inv1 : inv0;
            float v0 = O[d][h * 2] * inv, v1 = O[d][h * 2 + 1] * inv;
            __nv_bfloat16 h0, l0, h1, l1;
            split_bf(v0, h0, l0); split_bf(v1, h1, l1);
            size_t p = (size_t)row * DIM + col;
            *(uint32_t*)(Oh + p) =
                (uint32_t)__bfloat16_as_ushort(h0) | ((uint32_t)__bfloat16_as_ushort(h1) << 16);
            *(uint32_t*)(Ol + p) =
                (uint32_t)__bfloat16_as_ushort(l0) | ((uint32_t)__bfloat16_as_ushort(l1) << 16);
        }
    }
}

// combine (act1: h0*h1 ; act3: relu(h0+h1+h2)) -> NX0 hi/lo
__global__ void combine_k(int node) {
    int a = g_nr[node].act;
    if (a != 1 && a != 3) return;
    size_t stride = (size_t)gridDim.x * blockDim.x;
    for (size_t p = (size_t)blockIdx.x * blockDim.x + threadIdx.x; p < (size_t)MS; p += stride) {
        float v = (a == 1) ? g_h0[p] * g_h1[p]
                           : fmaxf(g_h0[p] + g_h1[p] + g_h2[p], 0.f);
        __nv_bfloat16 h, l; split_bf(v, h, l);
        g_NXh[p] = h; g_NXl[p] = l;
    }
}

// finish (acts 2,4,5,6,7) warp-per-row ; grid 512
__global__ void finish_k(int node) {
    NR r = g_nr[node];
    int a = r.act;
    if (a == 0 || a == 1 || a == 3) return;
    int warp = threadIdx.x >> 5, lane = threadIdx.x & 31;
    int row = blockIdx.x * 8 + warp;
    size_t rb = (size_t)row * DIM;
    float* out = g_outs + (size_t)node * MS + rb;
    if (a == 4 || a == 5 || a == 6) {
#pragma unroll
        for (int i = 0; i < 16; i++) {
            int c = lane + i * 32;
            float y;
            if (a == 4)      y = g_qv[rb + c] * sigmoidf_(g_kv[rb + c]) + g_vv[rb + c];
            else if (a == 5) y = g_qv[rb + c] + g_h1[rb + c];
            else             y = g_qv[rb + c] + g_kv[rb + c];
            out[c] = r.aw * y;
        }
        return;
    }
    // a == 2 or 7: LN
    float v[16];
#pragma unroll
    for (int i = 0; i < 16; i++) {
        int c = lane + i * 32;
        v[i] = (a == 2) ? (g_qv[rb + c] + g_kv[rb + c] + g_vv[rb + c]) : g_qv[rb + c];
    }
    float s = 0.f;
#pragma unroll
    for (int i = 0; i < 16; i++) s += v[i];
    float mean = wsum(s) * (1.0f / 512.0f);
    float q = 0.f;
#pragma unroll
    for (int i = 0; i < 16; i++) { float d = v[i] - mean; q += d * d; }
    float inv = rsqrtf(wsum(q) * (1.0f / 512.0f) + EPSLN);
    const float* gm = g_ptrs.node_g + node * DIM;
    const float* bt = g_ptrs.node_beta + node * DIM;
#pragma unroll
    for (int i = 0; i < 16; i++) {
        int c = lane + i * 32;
        out[c] = r.aw * ((v[i] - mean) * inv * gm[c] + bt[c]);
    }
}

// final: sum unprocessed + LN ; warp-per-row, grid 512
__global__ void final_k(float* dout) {
    int warp = threadIdx.x >> 5, lane = threadIdx.x & 31;
    int row = blockIdx.x * 8 + warp;
    size_t rb = (size_t)row * DIM;
    float v[16];
#pragma unroll
    for (int i = 0; i < 16; i++) v[i] = 0.f;
    for (int c = 0; c < 8; c++) {
        if (!g_processed[c]) {
            const float* o = g_outs + (size_t)c * MS + rb;
#pragma unroll
            for (int i = 0; i < 16; i++) v[i] += o[lane + i * 32];
        }
    }
    float s = 0.f;
#pragma unroll
    for (int i = 0; i < 16; i++) s += v[i];
    float mean = wsum(s) * (1.0f / 512.0f);
    float q = 0.f;
#pragma unroll
    for (int i = 0; i < 16; i++) { float d = v[i] - mean; q += d * d; }
    float inv = rsqrtf(wsum(q) * (1.0f / 512.0f) + EPSLN);
#pragma unroll
    for (int i = 0; i < 16; i++) {
        int c = lane + i * 32;
        dout[rb + c] = (v[i] - mean) * inv * g_ptrs.out_g[c] + g_ptrs.out_beta[c];
    }
}

// ---------------------------------------------------------------------------
// Launch
// ---------------------------------------------------------------------------
extern "C" void kernel_launch(void* const* d_in, const int* in_sizes, int n_in,
                              void* d_out, int out_size) {
    (void)in_sizes; (void)n_in; (void)out_size;
    cudaFuncSetAttribute(gemm_mma, cudaFuncAttributeMaxDynamicSharedMemorySize, GEMM_SMEM);
    cudaFuncSetAttribute(flash_k,  cudaFuncAttributeMaxDynamicSharedMemorySize, 65536);

    setup_k<<<1, 1>>>(
        (const float*)d_in[0],  (const float*)d_in[1],  (const float*)d_in[2],
        (const float*)d_in[3],  (const float*)d_in[4],  (const float*)d_in[5],
        (const float*)d_in[6],  (const float*)d_in[7],  (const float*)d_in[8],
        (const float*)d_in[9],  (const float*)d_in[10], (const float*)d_in[11],
        (const float*)d_in[12], (const float*)d_in[13]);
    routing_k<<<1, 1>>>();
    conv_w_all<<<dim3(16, 16, 56), dim3(32, 8)>>>();

    for (int c = 0; c < 8; c++) {
        edge_pre<<<dim3(512, 3), 256>>>(c);
        gemm_mma<<<dim3(8, 32, 3), 256, GEMM_SMEM>>>(c, 0);   // edge q/k/v
        node_prep<<<512, 256>>>(c);
        gemm_mma<<<dim3(8, 32, 3), 256, GEMM_SMEM>>>(c, 3);   // node j0/j1/j2
        flash_k<<<dim3(8, 32), 256, 65536>>>(c);
        combine_k<<<2048, 256>>>(c);
        gemm_mma<<<dim3(8, 32, 1), 256, GEMM_SMEM>>>(c, 6);   // node j3
        finish_k<<<512, 256>>>(c);
    }
    final_k<<<512, 256>>>((float*)d_out);
}

// round 8
// speedup vs baseline: 3.0120x; 1.1609x over previous
#include <cuda_runtime.h>
#include <cuda_fp16.h>
#include <math.h>
#include <stdint.h>

// ---------------------------------------------------------------------------
// Problem constants
// ---------------------------------------------------------------------------
#define NROWS 4096          // B*SLEN
#define DIM   512
#define MS    (4096*512)
#define NHEAD 8
#define DH    64
#define SLEN  1024
#define EPSLN 1e-6f

// ---------------------------------------------------------------------------
// Device-resident input pointer table + route table
// ---------------------------------------------------------------------------
struct Ptrs {
    const float *inpute, *inputo, *node_p, *edge_p;
    const float *edge_W, *edge_b, *edge_g, *edge_beta;
    const float *node_W, *node_b, *node_g, *node_beta;
    const float *out_g, *out_beta;
};
__device__ Ptrs g_ptrs;

struct NR {
    int act; float aw;
    int q_in, q_op, q_e; float q_w;
    int k_valid, k_in, k_op, k_e; float k_w;
    int v_valid, v_in, v_op, v_e; float v_w;
};
__device__ NR  g_nr[8];
__device__ int g_processed[8];

// ---------------------------------------------------------------------------
// Scratch
// ---------------------------------------------------------------------------
__device__ float g_outs[8 * MS];
__device__ float g_qv[MS], g_kv[MS], g_vv[MS];
__device__ float g_h0[MS], g_h1[MS], g_h2[MS];
__device__ __align__(16) __half g_EXh[3 * MS], g_EXl[3 * MS];   // edge GEMM A inputs (hi/lo fp16)
__device__ __align__(16) __half g_NXh[3 * MS], g_NXl[3 * MS];   // node GEMM A inputs
__device__ __align__(16) __half g_Wt[8 * 7 * DIM * DIM];        // W^T single fp16 [node][slot][n][k]

// ---------------------------------------------------------------------------
// Helpers
// ---------------------------------------------------------------------------
__device__ __forceinline__ const float* buf_in(int idx) {
    if (idx == 0) return g_ptrs.inpute;
    if (idx == 1) return g_ptrs.inputo;
    return g_outs + (size_t)(idx - 2) * MS;
}

__device__ __forceinline__ float geluf(float x) {
    float x3 = x * x * x;
    return 0.5f * x * (1.0f + tanhf(0.7978845608028654f * (x + 0.044715f * x3)));
}
__device__ __forceinline__ float sigmoidf_(float x) {
    return 1.0f / (1.0f + expf(-x));
}

__device__ __forceinline__ float wsum(float v) {
#pragma unroll
    for (int o = 16; o; o >>= 1) v += __shfl_xor_sync(0xffffffffu, v, o);
    return v;
}

__device__ __forceinline__ void split_h(float v, __half& h, __half& l) {
    h = __float2half_rn(v);
    l = __float2half_rn(v - __half2float(h));
}

// ---------------------------------------------------------------------------
// mma.sync / ldmatrix / cp.async helpers
// ---------------------------------------------------------------------------
__device__ __forceinline__ uint32_t smem_u32(const void* p) {
    uint32_t a;
    asm("{ .reg .u64 t; cvta.to.shared.u64 t, %1; cvt.u32.u64 %0, t; }" : "=r"(a) : "l"(p));
    return a;
}
__device__ __forceinline__ void ldm4(uint32_t addr, uint32_t r[4]) {
    asm volatile("ldmatrix.sync.aligned.m8n8.x4.shared.b16 {%0,%1,%2,%3}, [%4];"
                 : "=r"(r[0]), "=r"(r[1]), "=r"(r[2]), "=r"(r[3]) : "r"(addr));
}
__device__ __forceinline__ void ldm4t(uint32_t addr, uint32_t r[4]) {
    asm volatile("ldmatrix.sync.aligned.m8n8.x4.trans.shared.b16 {%0,%1,%2,%3}, [%4];"
                 : "=r"(r[0]), "=r"(r[1]), "=r"(r[2]), "=r"(r[3]) : "r"(addr));
}
__device__ __forceinline__ void mma16816(float c[4], const uint32_t a[4],
                                         uint32_t b0, uint32_t b1) {
    asm volatile(
        "mma.sync.aligned.m16n8k16.row.col.f32.f16.f16.f32 "
        "{%0,%1,%2,%3}, {%4,%5,%6,%7}, {%8,%9}, {%0,%1,%2,%3};"
        : "+f"(c[0]), "+f"(c[1]), "+f"(c[2]), "+f"(c[3])
        : "r"(a[0]), "r"(a[1]), "r"(a[2]), "r"(a[3]), "r"(b0), "r"(b1));
}
__device__ __forceinline__ void cpa16(uint32_t dst, const void* src) {
    asm volatile("cp.async.ca.shared.global [%0], [%1], 16;" :: "r"(dst), "l"(src));
}
#define CPA_COMMIT() asm volatile("cp.async.commit_group;" ::: "memory")
#define CPA_WAIT1()  asm volatile("cp.async.wait_group 1;" ::: "memory")
#define CPA_WAIT0()  asm volatile("cp.async.wait_group 0;" ::: "memory")

#define SW128(o) ((o) ^ (((o) >> 3) & 0x70))

__device__ __forceinline__ uint32_t pack_h2(float x, float y) {
    __half2 h = __float22half2_rn(make_float2(x, y));
    return *(uint32_t*)&h;
}
// fp32x4 -> fp16 hi uint2 / lo uint2
__device__ __forceinline__ void cvt_hilo(float4 v, uint2& hi, uint2& lo) {
    hi = make_uint2(pack_h2(v.x, v.y), pack_h2(v.z, v.w));
    __half2 h0 = *(__half2*)&hi.x;
    __half2 h1 = *(__half2*)&hi.y;
    float lx = v.x - __half2float(h0.x);
    float ly = v.y - __half2float(h0.y);
    float lz = v.z - __half2float(h1.x);
    float lw = v.w - __half2float(h1.y);
    lo = make_uint2(pack_h2(lx, ly), pack_h2(lz, lw));
}
// fp32x4 -> fp16 single uint2
__device__ __forceinline__ uint2 cvt_h(float4 v) {
    return make_uint2(pack_h2(v.x, v.y), pack_h2(v.z, v.w));
}

// ---------------------------------------------------------------------------
// Setup + routing
// ---------------------------------------------------------------------------
__global__ void setup_k(const float* a0, const float* a1, const float* a2, const float* a3,
                        const float* a4, const float* a5, const float* a6, const float* a7,
                        const float* a8, const float* a9, const float* a10, const float* a11,
                        const float* a12, const float* a13) {
    Ptrs p;
    p.inpute = a0; p.inputo = a1; p.node_p = a2; p.edge_p = a3;
    p.edge_W = a4; p.edge_b = a5; p.edge_g = a6; p.edge_beta = a7;
    p.node_W = a8; p.node_b = a9; p.node_g = a10; p.node_beta = a11;
    p.out_g = a12; p.out_beta = a13;
    g_ptrs = p;
}

__device__ int d_amax(const float* x, int n, int lo) {
    int bi = lo; float bv = x[lo];
    for (int i = lo + 1; i < n; i++) { if (x[i] > bv) { bv = x[i]; bi = i; } }
    return bi;
}
__device__ float d_smw(const float* x, int n, int lo, int sel) {
    float mx = x[lo];
    for (int i = lo + 1; i < n; i++) mx = fmaxf(mx, x[i]);
    float s = 0.f;
    for (int i = lo; i < n; i++) s += expf(x[i] - mx);
    return expf(x[sel] - mx) / s;
}

__global__ void routing_k() {
    if (threadIdx.x || blockIdx.x) return;
    const float* np = g_ptrs.node_p;
    const float* ep = g_ptrs.edge_p;
    for (int i = 0; i < 8; i++) g_processed[i] = 0;
    int lind = 0;
    for (int c = 0; c < 8; c++) {
        int nsrc = (c + 2 < 5) ? c + 2 : 5;
        int snode = c - nsrc;
        int n = nsrc * 5;
        const float* e0 = ep + 0 * 170 + lind * 5;
        const float* e1 = ep + 1 * 170 + lind * 5;
        const float* e2 = ep + 2 * 170 + lind * 5;
        NR r; r.k_valid = 0; r.v_valid = 0;
        r.k_in = 0; r.k_op = 4; r.k_e = 0; r.k_w = 0.f;
        r.v_in = 0; r.v_op = 4; r.v_e = 0; r.v_w = 0.f;

        int nact = d_amax(np + c * 8, 8, 0);
        r.act = nact;
        r.aw = d_smw(np + c * 8, 8, 0, nact);

        int qs = d_amax(e0, n, 5);
        int qse = qs / 5;
        r.q_in = (qse == 0) ? 0 : (snode + qse + 2);
        r.q_op = qs % 5; r.q_e = lind + qse;
        r.q_w = d_smw(e0, n, 5, qs);
        if (r.q_in >= 2) g_processed[r.q_in - 2] = 1;

        if (nact < 7) {
            int lo = (nact > 0) ? 5 : 0;
            int ks = d_amax(e1, n, lo);
            int kse = ks / 5;
            r.k_valid = 1;
            r.k_in = (kse == 0) ? 0 : (snode + kse + 2);
            r.k_op = ks % 5; r.k_e = lind + kse;
            r.k_w = d_smw(e1, n, lo, ks);
            if (r.k_in >= 2) g_processed[r.k_in - 2] = 1;
            int ktype = (kse == 0) ? -2 : -1;
            if (nact < 5) {
                r.v_valid = 1;
                int vs, vlo, vn;
                if (nact == 0 && ktype == -2) { vlo = 0; vn = 5; }
                else if (nact > 0)            { vlo = 5; vn = n; }
                else                          { vlo = 0; vn = n; }
                vs = d_amax(e2, vn, vlo);
                int vse = vs / 5;
                r.v_in = (vse == 0) ? 0 : (snode + vse + 2);
                r.v_op = vs % 5; r.v_e = lind + vse;
                r.v_w = d_smw(e2, vn, vlo, vs);
                if (r.v_in >= 2) g_processed[r.v_in - 2] = 1;
            }
        }
        g_nr[c] = r;
        lind += nsrc;
    }
}

// role r output feeds node GEMM slot 3+r?
__device__ __forceinline__ bool need_hilo_role(int act, int role) {
    if (role == 0) return act == 1 || act == 3;
    if (role == 1) return act == 0 || act == 1 || act == 3 || act == 5;
    return act == 0 || act == 3;
}

// ---------------------------------------------------------------------------
// Weight selection for slot 0..6
// ---------------------------------------------------------------------------
__device__ const float* resolve_w(int node, int slot) {
    NR r = g_nr[node];
    if (slot < 3) {
        int valid, op, e;
        if (slot == 0)      { valid = 1;         op = r.q_op; e = r.q_e; }
        else if (slot == 1) { valid = r.k_valid; op = r.k_op; e = r.k_e; }
        else                { valid = r.v_valid; op = r.v_op; e = r.v_e; }
        if (valid && op <= 3) return g_ptrs.edge_W + (size_t)e * DIM * DIM;
        return nullptr;
    }
    int a = r.act, j = slot - 3;
    bool need =
        (j == 0 && (a == 0 || a == 1 || a == 3)) ||
        (j == 1 && (a == 0 || a == 1 || a == 3 || a == 5)) ||
        (j == 2 && (a == 0 || a == 3)) ||
        (j == 3 && (a == 0 || a == 1 || a == 3));
    if (need) return g_ptrs.node_W + ((size_t)node * 4 + j) * DIM * DIM;
    return nullptr;
}

// Convert+transpose W -> single fp16.  grid (16,16,56) block (32,8)
__global__ void conv_w_all() {
    int z = blockIdx.z; int node = z / 7, slot = z % 7;
    const float* W = resolve_w(node, slot);
    if (!W) return;
    __shared__ float tile[32][33];
    int n0 = blockIdx.x * 32, k0 = blockIdx.y * 32;
    int tx = threadIdx.x, ty = threadIdx.y;
#pragma unroll
    for (int dy = 0; dy < 4; dy++)
        tile[ty * 4 + dy][tx] = W[(size_t)(k0 + ty * 4 + dy) * DIM + n0 + tx];
    __syncthreads();
    size_t base = (size_t)z * DIM * DIM;
#pragma unroll
    for (int dy = 0; dy < 4; dy++) {
        int n = n0 + ty * 4 + dy, k = k0 + tx;
        g_Wt[base + (size_t)n * DIM + k] = __float2half_rn(tile[tx][ty * 4 + dy]);
    }
}

// ---------------------------------------------------------------------------
// edge_pre: warp-per-row. grid (512, 3) block 256
// ---------------------------------------------------------------------------
__global__ void edge_pre(int node) {
    int role = blockIdx.y;
    NR r = g_nr[node];
    int valid, in, op, e; float w; float* out;
    if (role == 0)      { valid = 1;         in = r.q_in; op = r.q_op; e = r.q_e; w = r.q_w; out = g_qv; }
    else if (role == 1) { valid = r.k_valid; in = r.k_in; op = r.k_op; e = r.k_e; w = r.k_w; out = g_kv; }
    else                { valid = r.v_valid; in = r.v_in; op = r.v_op; e = r.v_e; w = r.v_w; out = g_vv; }
    if (!valid) return;
    int warp = threadIdx.x >> 5, lane = threadIdx.x & 31;
    int row = blockIdx.x * 8 + warp;
    size_t rb = (size_t)row * DIM;
    const float* x = buf_in(in) + rb;
    float v[16];
#pragma unroll
    for (int i = 0; i < 16; i++) v[i] = x[lane + i * 32];

    __half* exh = g_EXh + (size_t)role * MS + rb;
    __half* exl = g_EXl + (size_t)role * MS + rb;
    if (op <= 2) {
        const float* gm = g_ptrs.edge_g + e * DIM;
        const float* bt = g_ptrs.edge_beta + e * DIM;
        float s = 0.f;
#pragma unroll
        for (int i = 0; i < 16; i++) s += v[i];
        float mean = wsum(s) * (1.0f / 512.0f);
        float q = 0.f;
#pragma unroll
        for (int i = 0; i < 16; i++) { float d = v[i] - mean; q += d * d; }
        float inv = rsqrtf(wsum(q) * (1.0f / 512.0f) + EPSLN);
#pragma unroll
        for (int i = 0; i < 16; i++) {
            int c = lane + i * 32;
            float y = (v[i] - mean) * inv * gm[c] + bt[c];
            __half h, l; split_h(y, h, l);
            exh[c] = h; exl[c] = l;
        }
    } else if (op == 3) {
#pragma unroll
        for (int i = 0; i < 16; i++) {
            int c = lane + i * 32;
            __half h, l; split_h(v[i], h, l);
            exh[c] = h; exl[c] = l;
        }
    } else { // op == 4
        bool nh = need_hilo_role(r.act, role);
        __half* nxh = g_NXh + (size_t)role * MS + rb;
        __half* nxl = g_NXl + (size_t)role * MS + rb;
#pragma unroll
        for (int i = 0; i < 16; i++) {
            int c = lane + i * 32;
            float y = w * v[i];
            out[rb + c] = y;
            if (nh) {
                __half h, l; split_h(y, h, l);
                nxh[c] = h; nxl[c] = l;
            }
        }
    }
}

// node prep (act0): NX0 = LN(qv) hi/lo ; warp-per-row, grid 512
__global__ void node_prep(int node) {
    NR r = g_nr[node];
    if (r.act != 0) return;
    int warp = threadIdx.x >> 5, lane = threadIdx.x & 31;
    int row = blockIdx.x * 8 + warp;
    size_t rb = (size_t)row * DIM;
    const float* gm = g_ptrs.node_g + node * DIM;
    const float* bt = g_ptrs.node_beta + node * DIM;
    float v[16];
#pragma unroll
    for (int i = 0; i < 16; i++) v[i] = g_qv[rb + lane + i * 32];
    float s = 0.f;
#pragma unroll
    for (int i = 0; i < 16; i++) s += v[i];
    float mean = wsum(s) * (1.0f / 512.0f);
    float q = 0.f;
#pragma unroll
    for (int i = 0; i < 16; i++) { float d = v[i] - mean; q += d * d; }
    float inv = rsqrtf(wsum(q) * (1.0f / 512.0f) + EPSLN);
#pragma unroll
    for (int i = 0; i < 16; i++) {
        int c = lane + i * 32;
        float y = (v[i] - mean) * inv * gm[c] + bt[c];
        __half h, l; split_h(y, h, l);
        g_NXh[rb + c] = h; g_NXl[rb + c] = l;
    }
}

// ---------------------------------------------------------------------------
// GEMM config
// ---------------------------------------------------------------------------
struct GemmCfg {
    const __half *Xh, *Xl, *W;
    const float* Bv;
    int act;            // 0 none, 1 relu, 2 gelu
    float scale;
    const float* res;
    float* out;
    __half *oh, *ol;
};

__device__ bool resolve_gemm(int node, int slot, GemmCfg& g) {
    NR r = g_nr[node];
    g.oh = nullptr; g.ol = nullptr; g.res = nullptr;
    g.W = g_Wt + ((size_t)node * 7 + slot) * DIM * DIM;
    if (slot < 3) {
        int valid, op, e; float w; float* out;
        if (slot == 0)      { valid = 1;         op = r.q_op; e = r.q_e; w = r.q_w; out = g_qv; }
        else if (slot == 1) { valid = r.k_valid; op = r.k_op; e = r.k_e; w = r.k_w; out = g_kv; }
        else                { valid = r.v_valid; op = r.v_op; e = r.v_e; w = r.v_w; out = g_vv; }
        if (!valid || op == 4) return false;
        g.Xh = g_EXh + (size_t)slot * MS;
        g.Xl = g_EXl + (size_t)slot * MS;
        g.Bv = g_ptrs.edge_b + e * DIM;
        g.act = (op == 0) ? 1 : (op == 1) ? 2 : 0;
        g.scale = w; g.out = out;
        if (need_hilo_role(r.act, slot)) {
            g.oh = g_NXh + (size_t)slot * MS;
            g.ol = g_NXl + (size_t)slot * MS;
        }
        return true;
    }
    int a = r.act;
    int j = slot - 3;
    const float* Bv = g_ptrs.node_b + (node * 4 + j) * DIM;
    if (j == 0) {
        if (a != 0 && a != 1 && a != 3) return false;
        g.Xh = g_NXh; g.Xl = g_NXl;
        g.Bv = (a == 3) ? nullptr : Bv;
        g.act = (a == 1) ? 2 : 0;
        g.scale = 1.f; g.out = g_h0;
        return true;
    }
    if (j == 1) {
        if (a != 0 && a != 1 && a != 3 && a != 5) return false;
        g.Xh = g_NXh + (size_t)1 * MS; g.Xl = g_NXl + (size_t)1 * MS;
        g.Bv = (a == 3) ? nullptr : Bv;
        g.act = (a == 5) ? 2 : 0;
        g.scale = 1.f; g.out = g_h1;
        return true;
    }
    if (j == 2) {
        if (a != 0 && a != 3) return false;
        g.Xh = g_NXh + (size_t)2 * MS; g.Xl = g_NXl + (size_t)2 * MS;
        g.Bv = (a == 3) ? nullptr : Bv;
        g.act = 0; g.scale = 1.f; g.out = g_h2;
        return true;
    }
    if (a != 0 && a != 1 && a != 3) return false;
    g.Xh = g_NXh; g.Xl = g_NXl;
    g.Bv = Bv; g.act = 0; g.scale = r.aw;
    g.res = g_qv; g.out = g_outs + (size_t)node * MS;
    return true;
}

// ---------------------------------------------------------------------------
// Pipelined mma GEMM (2-product fp16): CTA 128x128, warp 32x64, K-chunk 64
// stage: A_h 16K | A_l 16K | B 16K = 48K ; 2 stages = 96KB ; 2 CTAs/SM
// grid (4, 32, nz) block 256
// ---------------------------------------------------------------------------
#define GEMM_SMEM 98304
#define STAGE_STRIDE 49152

__global__ void __launch_bounds__(256, 2) gemm_mma(int node, int base_slot) {
    int slot = base_slot + blockIdx.z;
    GemmCfg g;
    if (!resolve_gemm(node, slot, g)) return;

    extern __shared__ char smem[];
    uint32_t sbase = smem_u32(smem);
    int t = threadIdx.x, lane = t & 31, wid = t >> 5;
    int m0 = blockIdx.y * 128, n0 = blockIdx.x * 128;
    int wm = (wid & 3) * 32, wn = (wid >> 2) * 64;

    float acc[2][8][4];
#pragma unroll
    for (int i = 0; i < 2; i++)
#pragma unroll
        for (int j = 0; j < 8; j++)
#pragma unroll
            for (int l = 0; l < 4; l++) acc[i][j][l] = 0.f;

    // loaders: 2 threads/row (128 rows), 32 fp16 each
    int lrow = t >> 1, lcb = (t & 1) * 32;
    const __half* pAh = g.Xh + (size_t)(m0 + lrow) * DIM + lcb;
    const __half* pAl = g.Xl + (size_t)(m0 + lrow) * DIM + lcb;
    const __half* pB  = g.W  + (size_t)(n0 + lrow) * DIM + lcb;
    uint32_t doff[4];
#pragma unroll
    for (int i = 0; i < 4; i++)
        doff[i] = SW128((uint32_t)(lrow * 128 + (lcb + i * 8) * 2));

    // ldmatrix lane addressing
    int a_r = (lane & 15), a_k8 = (lane >> 4) << 3;
    int b_n = ((lane & 16) >> 1) + (lane & 7), b_k8 = (lane & 8);

    // prologue: stage 0 <- chunk 0
    {
        uint32_t sb = sbase;
#pragma unroll
        for (int i = 0; i < 4; i++) {
            cpa16(sb + doff[i],         pAh + i * 8);
            cpa16(sb + 16384 + doff[i], pAl + i * 8);
            cpa16(sb + 32768 + doff[i], pB  + i * 8);
        }
        CPA_COMMIT();
    }

    for (int c = 0; c < 8; c++) {
        if (c < 7) {
            int k0 = (c + 1) * 64;
            uint32_t sb = sbase + ((c + 1) & 1) * STAGE_STRIDE;
#pragma unroll
            for (int i = 0; i < 4; i++) {
                cpa16(sb + doff[i],         pAh + k0 + i * 8);
                cpa16(sb + 16384 + doff[i], pAl + k0 + i * 8);
                cpa16(sb + 32768 + doff[i], pB  + k0 + i * 8);
            }
            CPA_COMMIT();
            CPA_WAIT1();
        } else {
            CPA_WAIT0();
        }
        __syncthreads();

        uint32_t sA_H = sbase + (c & 1) * STAGE_STRIDE;
        uint32_t sA_L = sA_H + 16384, sB = sA_H + 32768;
#pragma unroll
        for (int kt = 0; kt < 4; kt++) {
            int kb = kt * 16;
            uint32_t ah[2][4], al[2][4];
#pragma unroll
            for (int mt = 0; mt < 2; mt++) {
                uint32_t off = SW128((uint32_t)((wm + mt * 16 + a_r) * 128 + (kb + a_k8) * 2));
                ldm4(sA_H + off, ah[mt]);
                ldm4(sA_L + off, al[mt]);
            }
#pragma unroll
            for (int ng = 0; ng < 4; ng++) {
                uint32_t boff = SW128((uint32_t)((wn + ng * 16 + b_n) * 128 + (kb + b_k8) * 2));
                uint32_t b4[4];
                ldm4(sB + boff, b4);
#pragma unroll
                for (int mt = 0; mt < 2; mt++) {
                    mma16816(acc[mt][2 * ng],     ah[mt], b4[0], b4[1]);
                    mma16816(acc[mt][2 * ng + 1], ah[mt], b4[2], b4[3]);
                    mma16816(acc[mt][2 * ng],     al[mt], b4[0], b4[1]);
                    mma16816(acc[mt][2 * ng + 1], al[mt], b4[2], b4[3]);
                }
            }
        }
        __syncthreads();
    }

    // epilogue
#pragma unroll
    for (int mt = 0; mt < 2; mt++) {
        int r0 = m0 + wm + mt * 16 + (lane >> 2);
#pragma unroll
        for (int nt = 0; nt < 8; nt++) {
            int col = n0 + wn + nt * 8 + (lane & 3) * 2;
#pragma unroll
            for (int h = 0; h < 2; h++) {
                int row = r0 + h * 8;
                float v0 = acc[mt][nt][h * 2], v1 = acc[mt][nt][h * 2 + 1];
                if (g.Bv) { v0 += g.Bv[col]; v1 += g.Bv[col + 1]; }
                if (g.act == 1)      { v0 = fmaxf(v0, 0.f); v1 = fmaxf(v1, 0.f); }
                else if (g.act == 2) { v0 = geluf(v0); v1 = geluf(v1); }
                if (g.res) {
                    v0 += g.res[(size_t)row * DIM + col];
                    v1 += g.res[(size_t)row * DIM + col + 1];
                }
                v0 *= g.scale; v1 *= g.scale;
                size_t p = (size_t)row * DIM + col;
                *(float2*)(g.out + p) = make_float2(v0, v1);
                if (g.oh) {
                    __half h0, l0, h1, l1;
                    split_h(v0, h0, l0); split_h(v1, h1, l1);
                    *(uint32_t*)(g.oh + p) =
                        (uint32_t)__half_as_ushort(h0) | ((uint32_t)__half_as_ushort(h1) << 16);
                    *(uint32_t*)(g.ol + p) =
                        (uint32_t)__half_as_ushort(l0) | ((uint32_t)__half_as_ushort(l1) << 16);
                }
            }
        }
    }
}

// ---------------------------------------------------------------------------
// Flash attention (act0): O = softmax(QK^T/8) V  -> NX0 hi/lo
// grid (8, 32), 256 thr (8 warps), warp w owns rows w*16..w*16+15
// smem: Qh 16K | Ql 16K | K 8K | V 8K = 48KB
// ---------------------------------------------------------------------------
__global__ void __launch_bounds__(256) flash_k(int node) {
    if (g_nr[node].act != 0) return;
    extern __shared__ char smem[];
    uint32_t sQ_H = smem_u32(smem);
    uint32_t sQ_L = sQ_H + 16384;
    uint32_t sK = sQ_H + 32768, sV = sQ_H + 40960;

    int t = threadIdx.x, lane = t & 31, wid = t >> 5;
    int bh = blockIdx.y, b = bh >> 3, head = bh & 7;
    int i0 = blockIdx.x * 128;

    const float* Q = g_h0 + (size_t)b * SLEN * DIM + head * DH;
    const float* K = g_h1 + (size_t)b * SLEN * DIM + head * DH;
    const float* V = g_h2 + (size_t)b * SLEN * DIM + head * DH;

    // load Q tile 128x64 -> hi/lo (once)
    {
        int lrow = t >> 1, lcb = (t & 1) * 32;
        const float* qr = Q + (size_t)(i0 + lrow) * DIM + lcb;
#pragma unroll
        for (int i = 0; i < 8; i++) {
            uint2 hi, lo; cvt_hilo(*(const float4*)(qr + i * 4), hi, lo);
            uint32_t off = SW128((uint32_t)(lrow * 128 + (lcb + i * 4) * 2));
            *(uint2*)(smem + off) = hi;
            *(uint2*)(smem + 16384 + off) = lo;
        }
    }

    float O[8][4];
#pragma unroll
    for (int d = 0; d < 8; d++)
#pragma unroll
        for (int l = 0; l < 4; l++) O[d][l] = 0.f;
    float mrow[2] = {-3.4e38f, -3.4e38f};
    float lrow_[2] = {0.f, 0.f};

    int a_r = (lane & 15), a_k8 = (lane >> 4) << 3;
    int b_n = ((lane & 16) >> 1) + (lane & 7), b_k8 = (lane & 8);
    int v_k = (lane & 15), v_n8 = (lane & 16) >> 1;
    int kvrow = t >> 2, kvcb = (t & 3) * 16;

    for (int jc = 0; jc < 16; jc++) {
        int j0 = jc * 64;
        // load K,V chunk 64x64 -> single fp16
        {
            const float* kr = K + (size_t)(j0 + kvrow) * DIM + kvcb;
            const float* vr = V + (size_t)(j0 + kvrow) * DIM + kvcb;
#pragma unroll
            for (int i = 0; i < 4; i++) {
                uint32_t off = SW128((uint32_t)(kvrow * 128 + (kvcb + i * 4) * 2));
                *(uint2*)(smem + 32768 + off) = cvt_h(*(const float4*)(kr + i * 4));
                *(uint2*)(smem + 40960 + off) = cvt_h(*(const float4*)(vr + i * 4));
            }
        }
        __syncthreads();

        // S = Q K^T  (16 rows x 64 j per warp) ; 2 products
        float s[8][4];
#pragma unroll
        for (int j = 0; j < 8; j++)
#pragma unroll
            for (int l = 0; l < 4; l++) s[j][l] = 0.f;
#pragma unroll
        for (int kt = 0; kt < 4; kt++) {
            int kb = kt * 16;
            uint32_t qh[4], ql[4];
            uint32_t qoff = SW128((uint32_t)((wid * 16 + a_r) * 128 + (kb + a_k8) * 2));
            ldm4(sQ_H + qoff, qh);
            ldm4(sQ_L + qoff, ql);
#pragma unroll
            for (int ng = 0; ng < 4; ng++) {
                uint32_t boff = SW128((uint32_t)((ng * 16 + b_n) * 128 + (kb + b_k8) * 2));
                uint32_t k4[4];
                ldm4(sK + boff, k4);
                mma16816(s[2 * ng],     qh, k4[0], k4[1]);
                mma16816(s[2 * ng + 1], qh, k4[2], k4[3]);
                mma16816(s[2 * ng],     ql, k4[0], k4[1]);
                mma16816(s[2 * ng + 1], ql, k4[2], k4[3]);
            }
        }
        // scale
#pragma unroll
        for (int j = 0; j < 8; j++)
#pragma unroll
            for (int l = 0; l < 4; l++) s[j][l] *= 0.125f;

        // online softmax per row-half
#pragma unroll
        for (int h = 0; h < 2; h++) {
            float mj = -3.4e38f;
#pragma unroll
            for (int j = 0; j < 8; j++) mj = fmaxf(mj, fmaxf(s[j][h * 2], s[j][h * 2 + 1]));
            mj = fmaxf(mj, __shfl_xor_sync(0xffffffffu, mj, 1));
            mj = fmaxf(mj, __shfl_xor_sync(0xffffffffu, mj, 2));
            float mnew = fmaxf(mrow[h], mj);
            float alpha = expf(mrow[h] - mnew);
            float ps = 0.f;
#pragma unroll
            for (int j = 0; j < 8; j++) {
                s[j][h * 2]     = expf(s[j][h * 2] - mnew);
                s[j][h * 2 + 1] = expf(s[j][h * 2 + 1] - mnew);
                ps += s[j][h * 2] + s[j][h * 2 + 1];
            }
            ps += __shfl_xor_sync(0xffffffffu, ps, 1);
            ps += __shfl_xor_sync(0xffffffffu, ps, 2);
            lrow_[h] = lrow_[h] * alpha + ps;
            mrow[h] = mnew;
#pragma unroll
            for (int d = 0; d < 8; d++) {
                O[d][h * 2]     *= alpha;
                O[d][h * 2 + 1] *= alpha;
            }
        }

        // O += P V ; P split hi/lo, V single -> 2 products
#pragma unroll
        for (int g4 = 0; g4 < 4; g4++) {
            uint32_t ah[4], al[4];
            {
                uint2 hi, lo;
                cvt_hilo(make_float4(s[2 * g4][0], s[2 * g4][1], s[2 * g4][2], s[2 * g4][3]), hi, lo);
                ah[0] = hi.x; ah[1] = hi.y; al[0] = lo.x; al[1] = lo.y;
                cvt_hilo(make_float4(s[2 * g4 + 1][0], s[2 * g4 + 1][1], s[2 * g4 + 1][2], s[2 * g4 + 1][3]), hi, lo);
                ah[2] = hi.x; ah[3] = hi.y; al[2] = lo.x; al[3] = lo.y;
            }
            int kb = g4 * 16;
#pragma unroll
            for (int ng = 0; ng < 4; ng++) {
                uint32_t boff = SW128((uint32_t)((kb + v_k) * 128 + (ng * 16 + v_n8) * 2));
                uint32_t v4[4];
                ldm4t(sV + boff, v4);
                mma16816(O[2 * ng],     ah, v4[0], v4[1]);
                mma16816(O[2 * ng + 1], ah, v4[2], v4[3]);
                mma16816(O[2 * ng],     al, v4[0], v4[1]);
                mma16816(O[2 * ng + 1], al, v4[2], v4[3]);
            }
        }
        __syncthreads();
    }

    // normalize + write -> NX0 hi/lo
    float inv0 = 1.0f / lrow_[0], inv1 = 1.0f / lrow_[1];
    __half* Oh = g_NXh + ((size_t)b * SLEN) * DIM + head * DH;
    __half* Ol = g_NXl + ((size_t)b * SLEN) * DIM + head * DH;
    int r0 = i0 + wid * 16 + (lane >> 2);
#pragma unroll
    for (int d = 0; d < 8; d++) {
        int col = d * 8 + (lane & 3) * 2;
#pragma unroll
        for (int h = 0; h < 2; h++) {
            int row = r0 + h * 8;
            float inv = h ? inv1 : inv0;
            float v0 = O[d][h * 2] * inv, v1 = O[d][h * 2 + 1] * inv;
            __half h0, l0, h1, l1;
            split_h(v0, h0, l0); split_h(v1, h1, l1);
            size_t p = (size_t)row * DIM + col;
            *(uint32_t*)(Oh + p) =
                (uint32_t)__half_as_ushort(h0) | ((uint32_t)__half_as_ushort(h1) << 16);
            *(uint32_t*)(Ol + p) =
                (uint32_t)__half_as_ushort(l0) | ((uint32_t)__half_as_ushort(l1) << 16);
        }
    }
}

// combine (act1: h0*h1 ; act3: relu(h0+h1+h2)) -> NX0 hi/lo
__global__ void combine_k(int node) {
    int a = g_nr[node].act;
    if (a != 1 && a != 3) return;
    size_t stride = (size_t)gridDim.x * blockDim.x;
    for (size_t p = (size_t)blockIdx.x * blockDim.x + threadIdx.x; p < (size_t)MS; p += stride) {
        float v = (a == 1) ? g_h0[p] * g_h1[p]
                           : fmaxf(g_h0[p] + g_h1[p] + g_h2[p], 0.f);
        __half h, l; split_h(v, h, l);
        g_NXh[p] = h; g_NXl[p] = l;
    }
}

// finish (acts 2,4,5,6,7) warp-per-row ; grid 512
__global__ void finish_k(int node) {
    NR r = g_nr[node];
    int a = r.act;
    if (a == 0 || a == 1 || a == 3) return;
    int warp = threadIdx.x >> 5, lane = threadIdx.x & 31;
    int row = blockIdx.x * 8 + warp;
    size_t rb = (size_t)row * DIM;
    float* out = g_outs + (size_t)node * MS + rb;
    if (a == 4 || a == 5 || a == 6) {
#pragma unroll
        for (int i = 0; i < 16; i++) {
            int c = lane + i * 32;
            float y;
            if (a == 4)      y = g_qv[rb + c] * sigmoidf_(g_kv[rb + c]) + g_vv[rb + c];
            else if (a == 5) y = g_qv[rb + c] + g_h1[rb + c];
            else             y = g_qv[rb + c] + g_kv[rb + c];
            out[c] = r.aw * y;
        }
        return;
    }
    // a == 2 or 7: LN
    float v[16];
#pragma unroll
    for (int i = 0; i < 16; i++) {
        int c = lane + i * 32;
        v[i] = (a == 2) ? (g_qv[rb + c] + g_kv[rb + c] + g_vv[rb + c]) : g_qv[rb + c];
    }
    float s = 0.f;
#pragma unroll
    for (int i = 0; i < 16; i++) s += v[i];
    float mean = wsum(s) * (1.0f / 512.0f);
    float q = 0.f;
#pragma unroll
    for (int i = 0; i < 16; i++) { float d = v[i] - mean; q += d * d; }
    float inv = rsqrtf(wsum(q) * (1.0f / 512.0f) + EPSLN);
    const float* gm = g_ptrs.node_g + node * DIM;
    const float* bt = g_ptrs.node_beta + node * DIM;
#pragma unroll
    for (int i = 0; i < 16; i++) {
        int c = lane + i * 32;
        out[c] = r.aw * ((v[i] - mean) * inv * gm[c] + bt[c]);
    }
}

// final: sum unprocessed + LN ; warp-per-row, grid 512
__global__ void final_k(float* dout) {
    int warp = threadIdx.x >> 5, lane = threadIdx.x & 31;
    int row = blockIdx.x * 8 + warp;
    size_t rb = (size_t)row * DIM;
    float v[16];
#pragma unroll
    for (int i = 0; i < 16; i++) v[i] = 0.f;
    for (int c = 0; c < 8; c++) {
        if (!g_processed[c]) {
            const float* o = g_outs + (size_t)c * MS + rb;
#pragma unroll
            for (int i = 0; i < 16; i++) v[i] += o[lane + i * 32];
        }
    }
    float s = 0.f;
#pragma unroll
    for (int i = 0; i < 16; i++) s += v[i];
    float mean = wsum(s) * (1.0f / 512.0f);
    float q = 0.f;
#pragma unroll
    for (int i = 0; i < 16; i++) { float d = v[i] - mean; q += d * d; }
    float inv = rsqrtf(wsum(q) * (1.0f / 512.0f) + EPSLN);
#pragma unroll
    for (int i = 0; i < 16; i++) {
        int c = lane + i * 32;
        dout[rb + c] = (v[i] - mean) * inv * g_ptrs.out_g[c] + g_ptrs.out_beta[c];
    }
}

// ---------------------------------------------------------------------------
// Launch
// ---------------------------------------------------------------------------
extern "C" void kernel_launch(void* const* d_in, const int* in_sizes, int n_in,
                              void* d_out, int out_size) {
    (void)in_sizes; (void)n_in; (void)out_size;
    cudaFuncSetAttribute(gemm_mma, cudaFuncAttributeMaxDynamicSharedMemorySize, GEMM_SMEM);
    cudaFuncSetAttribute(flash_k,  cudaFuncAttributeMaxDynamicSharedMemorySize, 49152);

    setup_k<<<1, 1>>>(
        (const float*)d_in[0],  (const float*)d_in[1],  (const float*)d_in[2],
        (const float*)d_in[3],  (const float*)d_in[4],  (const float*)d_in[5],
        (const float*)d_in[6],  (const float*)d_in[7],  (const float*)d_in[8],
        (const float*)d_in[9],  (const float*)d_in[10], (const float*)d_in[11],
        (const float*)d_in[12], (const float*)d_in[13]);
    routing_k<<<1, 1>>>();
    conv_w_all<<<dim3(16, 16, 56), dim3(32, 8)>>>();

    for (int c = 0; c < 8; c++) {
        edge_pre<<<dim3(512, 3), 256>>>(c);
        gemm_mma<<<dim3(4, 32, 3), 256, GEMM_SMEM>>>(c, 0);   // edge q/k/v
        node_prep<<<512, 256>>>(c);
        gemm_mma<<<dim3(4, 32, 3), 256, GEMM_SMEM>>>(c, 3);   // node j0/j1/j2
        flash_k<<<dim3(8, 32), 256, 49152>>>(c);
        combine_k<<<2048, 256>>>(c);
        gemm_mma<<<dim3(4, 32, 1), 256, GEMM_SMEM>>>(c, 6);   // node j3
        finish_k<<<512, 256>>>(c);
    }
    final_k<<<512, 256>>>((float*)d_out);
}

// round 9
// speedup vs baseline: 3.5816x; 1.1891x over previous
#include <cuda_runtime.h>
#include <cuda_fp16.h>
#include <math.h>
#include <stdint.h>

// ---------------------------------------------------------------------------
// Problem constants
// ---------------------------------------------------------------------------
#define NROWS 4096          // B*SLEN
#define DIM   512
#define MS    (4096*512)
#define NHEAD 8
#define DH    64
#define SLEN  1024
#define EPSLN 1e-6f

// ---------------------------------------------------------------------------
// Device-resident input pointer table + route table
// ---------------------------------------------------------------------------
struct Ptrs {
    const float *inpute, *inputo, *node_p, *edge_p;
    const float *edge_W, *edge_b, *edge_g, *edge_beta;
    const float *node_W, *node_b, *node_g, *node_beta;
    const float *out_g, *out_beta;
};
__device__ Ptrs g_ptrs;

struct NR {
    int act; float aw;
    int q_in, q_op, q_e; float q_w;
    int k_valid, k_in, k_op, k_e; float k_w;
    int v_valid, v_in, v_op, v_e; float v_w;
};
__device__ NR  g_nr[8];
__device__ int g_processed[8];

// ---------------------------------------------------------------------------
// Scratch
// ---------------------------------------------------------------------------
__device__ float g_outs[8 * MS];
__device__ float g_qv[MS], g_kv[MS], g_vv[MS];
__device__ float g_h0[MS], g_h1[MS], g_h2[MS];
__device__ __align__(16) __half g_EXh[3 * MS], g_EXl[3 * MS];   // edge GEMM A inputs (hi/lo fp16)
__device__ __align__(16) __half g_NXh[3 * MS], g_NXl[3 * MS];   // node GEMM A inputs
__device__ __align__(16) __half g_Wt[8 * 7 * DIM * DIM];        // W^T single fp16 [node][slot][n][k]

// ---------------------------------------------------------------------------
// Helpers
// ---------------------------------------------------------------------------
__device__ __forceinline__ const float* buf_in(int idx) {
    if (idx == 0) return g_ptrs.inpute;
    if (idx == 1) return g_ptrs.inputo;
    return g_outs + (size_t)(idx - 2) * MS;
}

__device__ __forceinline__ float geluf(float x) {
    float x3 = x * x * x;
    return 0.5f * x * (1.0f + tanhf(0.7978845608028654f * (x + 0.044715f * x3)));
}
__device__ __forceinline__ float sigmoidf_(float x) {
    return 1.0f / (1.0f + expf(-x));
}

__device__ __forceinline__ float wsum(float v) {
#pragma unroll
    for (int o = 16; o; o >>= 1) v += __shfl_xor_sync(0xffffffffu, v, o);
    return v;
}

__device__ __forceinline__ void split_h(float v, __half& h, __half& l) {
    h = __float2half_rn(v);
    l = __float2half_rn(v - __half2float(h));
}

// ---------------------------------------------------------------------------
// mma.sync / ldmatrix / cp.async helpers
// ---------------------------------------------------------------------------
__device__ __forceinline__ uint32_t smem_u32(const void* p) {
    uint32_t a;
    asm("{ .reg .u64 t; cvta.to.shared.u64 t, %1; cvt.u32.u64 %0, t; }" : "=r"(a) : "l"(p));
    return a;
}
__device__ __forceinline__ void ldm4(uint32_t addr, uint32_t r[4]) {
    asm volatile("ldmatrix.sync.aligned.m8n8.x4.shared.b16 {%0,%1,%2,%3}, [%4];"
                 : "=r"(r[0]), "=r"(r[1]), "=r"(r[2]), "=r"(r[3]) : "r"(addr));
}
__device__ __forceinline__ void ldm4t(uint32_t addr, uint32_t r[4]) {
    asm volatile("ldmatrix.sync.aligned.m8n8.x4.trans.shared.b16 {%0,%1,%2,%3}, [%4];"
                 : "=r"(r[0]), "=r"(r[1]), "=r"(r[2]), "=r"(r[3]) : "r"(addr));
}
__device__ __forceinline__ void mma16816(float c[4], const uint32_t a[4],
                                         uint32_t b0, uint32_t b1) {
    asm volatile(
        "mma.sync.aligned.m16n8k16.row.col.f32.f16.f16.f32 "
        "{%0,%1,%2,%3}, {%4,%5,%6,%7}, {%8,%9}, {%0,%1,%2,%3};"
        : "+f"(c[0]), "+f"(c[1]), "+f"(c[2]), "+f"(c[3])
        : "r"(a[0]), "r"(a[1]), "r"(a[2]), "r"(a[3]), "r"(b0), "r"(b1));
}
__device__ __forceinline__ void cpa16(uint32_t dst, const void* src) {
    asm volatile("cp.async.ca.shared.global [%0], [%1], 16;" :: "r"(dst), "l"(src));
}
#define CPA_COMMIT() asm volatile("cp.async.commit_group;" ::: "memory")
#define CPA_WAIT1()  asm volatile("cp.async.wait_group 1;" ::: "memory")
#define CPA_WAIT0()  asm volatile("cp.async.wait_group 0;" ::: "memory")

#define SW128(o) ((o) ^ (((o) >> 3) & 0x70))

__device__ __forceinline__ uint32_t pack_h2(float x, float y) {
    __half2 h = __float22half2_rn(make_float2(x, y));
    return *(uint32_t*)&h;
}
__device__ __forceinline__ void cvt_hilo(float4 v, uint2& hi, uint2& lo) {
    hi = make_uint2(pack_h2(v.x, v.y), pack_h2(v.z, v.w));
    __half2 h0 = *(__half2*)&hi.x;
    __half2 h1 = *(__half2*)&hi.y;
    float lx = v.x - __half2float(h0.x);
    float ly = v.y - __half2float(h0.y);
    float lz = v.z - __half2float(h1.x);
    float lw = v.w - __half2float(h1.y);
    lo = make_uint2(pack_h2(lx, ly), pack_h2(lz, lw));
}
__device__ __forceinline__ uint2 cvt_h(float4 v) {
    return make_uint2(pack_h2(v.x, v.y), pack_h2(v.z, v.w));
}

// ---------------------------------------------------------------------------
// Setup + routing
// ---------------------------------------------------------------------------
__global__ void setup_k(const float* a0, const float* a1, const float* a2, const float* a3,
                        const float* a4, const float* a5, const float* a6, const float* a7,
                        const float* a8, const float* a9, const float* a10, const float* a11,
                        const float* a12, const float* a13) {
    Ptrs p;
    p.inpute = a0; p.inputo = a1; p.node_p = a2; p.edge_p = a3;
    p.edge_W = a4; p.edge_b = a5; p.edge_g = a6; p.edge_beta = a7;
    p.node_W = a8; p.node_b = a9; p.node_g = a10; p.node_beta = a11;
    p.out_g = a12; p.out_beta = a13;
    g_ptrs = p;
}

__device__ int d_amax(const float* x, int n, int lo) {
    int bi = lo; float bv = x[lo];
    for (int i = lo + 1; i < n; i++) { if (x[i] > bv) { bv = x[i]; bi = i; } }
    return bi;
}
__device__ float d_smw(const float* x, int n, int lo, int sel) {
    float mx = x[lo];
    for (int i = lo + 1; i < n; i++) mx = fmaxf(mx, x[i]);
    float s = 0.f;
    for (int i = lo; i < n; i++) s += expf(x[i] - mx);
    return expf(x[sel] - mx) / s;
}

__global__ void routing_k() {
    if (threadIdx.x || blockIdx.x) return;
    const float* np = g_ptrs.node_p;
    const float* ep = g_ptrs.edge_p;
    for (int i = 0; i < 8; i++) g_processed[i] = 0;
    int lind = 0;
    for (int c = 0; c < 8; c++) {
        int nsrc = (c + 2 < 5) ? c + 2 : 5;
        int snode = c - nsrc;
        int n = nsrc * 5;
        const float* e0 = ep + 0 * 170 + lind * 5;
        const float* e1 = ep + 1 * 170 + lind * 5;
        const float* e2 = ep + 2 * 170 + lind * 5;
        NR r; r.k_valid = 0; r.v_valid = 0;
        r.k_in = 0; r.k_op = 4; r.k_e = 0; r.k_w = 0.f;
        r.v_in = 0; r.v_op = 4; r.v_e = 0; r.v_w = 0.f;

        int nact = d_amax(np + c * 8, 8, 0);
        r.act = nact;
        r.aw = d_smw(np + c * 8, 8, 0, nact);

        int qs = d_amax(e0, n, 5);
        int qse = qs / 5;
        r.q_in = (qse == 0) ? 0 : (snode + qse + 2);
        r.q_op = qs % 5; r.q_e = lind + qse;
        r.q_w = d_smw(e0, n, 5, qs);
        if (r.q_in >= 2) g_processed[r.q_in - 2] = 1;

        if (nact < 7) {
            int lo = (nact > 0) ? 5 : 0;
            int ks = d_amax(e1, n, lo);
            int kse = ks / 5;
            r.k_valid = 1;
            r.k_in = (kse == 0) ? 0 : (snode + kse + 2);
            r.k_op = ks % 5; r.k_e = lind + kse;
            r.k_w = d_smw(e1, n, lo, ks);
            if (r.k_in >= 2) g_processed[r.k_in - 2] = 1;
            int ktype = (kse == 0) ? -2 : -1;
            if (nact < 5) {
                r.v_valid = 1;
                int vs, vlo, vn;
                if (nact == 0 && ktype == -2) { vlo = 0; vn = 5; }
                else if (nact > 0)            { vlo = 5; vn = n; }
                else                          { vlo = 0; vn = n; }
                vs = d_amax(e2, vn, vlo);
                int vse = vs / 5;
                r.v_in = (vse == 0) ? 0 : (snode + vse + 2);
                r.v_op = vs % 5; r.v_e = lind + vse;
                r.v_w = d_smw(e2, vn, vlo, vs);
                if (r.v_in >= 2) g_processed[r.v_in - 2] = 1;
            }
        }
        g_nr[c] = r;
        lind += nsrc;
    }
}

// role r output feeds node GEMM slot 3+r?
__device__ __forceinline__ bool need_hilo_role(int act, int role) {
    if (role == 0) return act == 1 || act == 3;
    if (role == 1) return act == 0 || act == 1 || act == 3 || act == 5;
    return act == 0 || act == 3;
}

// ---------------------------------------------------------------------------
// Weight selection for slot 0..6
// ---------------------------------------------------------------------------
__device__ const float* resolve_w(int node, int slot) {
    NR r = g_nr[node];
    if (slot < 3) {
        int valid, op, e;
        if (slot == 0)      { valid = 1;         op = r.q_op; e = r.q_e; }
        else if (slot == 1) { valid = r.k_valid; op = r.k_op; e = r.k_e; }
        else                { valid = r.v_valid; op = r.v_op; e = r.v_e; }
        if (valid && op <= 3) return g_ptrs.edge_W + (size_t)e * DIM * DIM;
        return nullptr;
    }
    int a = r.act, j = slot - 3;
    bool need =
        (j == 0 && (a == 0 || a == 1 || a == 3)) ||
        (j == 1 && (a == 0 || a == 1 || a == 3 || a == 5)) ||
        (j == 2 && (a == 0 || a == 3)) ||
        (j == 3 && (a == 0 || a == 1 || a == 3));
    if (need) return g_ptrs.node_W + ((size_t)node * 4 + j) * DIM * DIM;
    return nullptr;
}

// Convert+transpose W -> single fp16.  grid (16,16,56) block (32,8)
__global__ void conv_w_all() {
    int z = blockIdx.z; int node = z / 7, slot = z % 7;
    const float* W = resolve_w(node, slot);
    if (!W) return;
    __shared__ float tile[32][33];
    int n0 = blockIdx.x * 32, k0 = blockIdx.y * 32;
    int tx = threadIdx.x, ty = threadIdx.y;
#pragma unroll
    for (int dy = 0; dy < 4; dy++)
        tile[ty * 4 + dy][tx] = W[(size_t)(k0 + ty * 4 + dy) * DIM + n0 + tx];
    __syncthreads();
    size_t base = (size_t)z * DIM * DIM;
#pragma unroll
    for (int dy = 0; dy < 4; dy++) {
        int n = n0 + ty * 4 + dy, k = k0 + tx;
        g_Wt[base + (size_t)n * DIM + k] = __float2half_rn(tile[tx][ty * 4 + dy]);
    }
}

// ---------------------------------------------------------------------------
// edge_pre: warp-per-row. grid (512, 3) block 256
// ---------------------------------------------------------------------------
__global__ void edge_pre(int node) {
    int role = blockIdx.y;
    NR r = g_nr[node];
    int valid, in, op, e; float w; float* out;
    if (role == 0)      { valid = 1;         in = r.q_in; op = r.q_op; e = r.q_e; w = r.q_w; out = g_qv; }
    else if (role == 1) { valid = r.k_valid; in = r.k_in; op = r.k_op; e = r.k_e; w = r.k_w; out = g_kv; }
    else                { valid = r.v_valid; in = r.v_in; op = r.v_op; e = r.v_e; w = r.v_w; out = g_vv; }
    if (!valid) return;
    int warp = threadIdx.x >> 5, lane = threadIdx.x & 31;
    int row = blockIdx.x * 8 + warp;
    size_t rb = (size_t)row * DIM;
    const float* x = buf_in(in) + rb;
    float v[16];
#pragma unroll
    for (int i = 0; i < 16; i++) v[i] = x[lane + i * 32];

    __half* exh = g_EXh + (size_t)role * MS + rb;
    __half* exl = g_EXl + (size_t)role * MS + rb;
    if (op <= 2) {
        const float* gm = g_ptrs.edge_g + e * DIM;
        const float* bt = g_ptrs.edge_beta + e * DIM;
        float s = 0.f;
#pragma unroll
        for (int i = 0; i < 16; i++) s += v[i];
        float mean = wsum(s) * (1.0f / 512.0f);
        float q = 0.f;
#pragma unroll
        for (int i = 0; i < 16; i++) { float d = v[i] - mean; q += d * d; }
        float inv = rsqrtf(wsum(q) * (1.0f / 512.0f) + EPSLN);
#pragma unroll
        for (int i = 0; i < 16; i++) {
            int c = lane + i * 32;
            float y = (v[i] - mean) * inv * gm[c] + bt[c];
            __half h, l; split_h(y, h, l);
            exh[c] = h; exl[c] = l;
        }
    } else if (op == 3) {
#pragma unroll
        for (int i = 0; i < 16; i++) {
            int c = lane + i * 32;
            __half h, l; split_h(v[i], h, l);
            exh[c] = h; exl[c] = l;
        }
    } else { // op == 4
        bool nh = need_hilo_role(r.act, role);
        __half* nxh = g_NXh + (size_t)role * MS + rb;
        __half* nxl = g_NXl + (size_t)role * MS + rb;
#pragma unroll
        for (int i = 0; i < 16; i++) {
            int c = lane + i * 32;
            float y = w * v[i];
            out[rb + c] = y;
            if (nh) {
                __half h, l; split_h(y, h, l);
                nxh[c] = h; nxl[c] = l;
            }
        }
    }
}

// node prep (act0): NX0 = LN(qv) hi/lo ; warp-per-row, grid 512
__global__ void node_prep(int node) {
    NR r = g_nr[node];
    if (r.act != 0) return;
    int warp = threadIdx.x >> 5, lane = threadIdx.x & 31;
    int row = blockIdx.x * 8 + warp;
    size_t rb = (size_t)row * DIM;
    const float* gm = g_ptrs.node_g + node * DIM;
    const float* bt = g_ptrs.node_beta + node * DIM;
    float v[16];
#pragma unroll
    for (int i = 0; i < 16; i++) v[i] = g_qv[rb + lane + i * 32];
    float s = 0.f;
#pragma unroll
    for (int i = 0; i < 16; i++) s += v[i];
    float mean = wsum(s) * (1.0f / 512.0f);
    float q = 0.f;
#pragma unroll
    for (int i = 0; i < 16; i++) { float d = v[i] - mean; q += d * d; }
    float inv = rsqrtf(wsum(q) * (1.0f / 512.0f) + EPSLN);
#pragma unroll
    for (int i = 0; i < 16; i++) {
        int c = lane + i * 32;
        float y = (v[i] - mean) * inv * gm[c] + bt[c];
        __half h, l; split_h(y, h, l);
        g_NXh[rb + c] = h; g_NXl[rb + c] = l;
    }
}

// ---------------------------------------------------------------------------
// GEMM config
// ---------------------------------------------------------------------------
struct GemmCfg {
    const __half *Xh, *Xl, *W;
    const float* Bv;
    int act;            // 0 none, 1 relu, 2 gelu
    float scale;
    const float* res;
    float* out;
    __half *oh, *ol;
};

__device__ bool resolve_gemm(int node, int slot, GemmCfg& g) {
    NR r = g_nr[node];
    g.oh = nullptr; g.ol = nullptr; g.res = nullptr;
    g.W = g_Wt + ((size_t)node * 7 + slot) * DIM * DIM;
    if (slot < 3) {
        int valid, op, e; float w; float* out;
        if (slot == 0)      { valid = 1;         op = r.q_op; e = r.q_e; w = r.q_w; out = g_qv; }
        else if (slot == 1) { valid = r.k_valid; op = r.k_op; e = r.k_e; w = r.k_w; out = g_kv; }
        else                { valid = r.v_valid; op = r.v_op; e = r.v_e; w = r.v_w; out = g_vv; }
        if (!valid || op == 4) return false;
        g.Xh = g_EXh + (size_t)slot * MS;
        g.Xl = g_EXl + (size_t)slot * MS;
        g.Bv = g_ptrs.edge_b + e * DIM;
        g.act = (op == 0) ? 1 : (op == 1) ? 2 : 0;
        g.scale = w; g.out = out;
        if (need_hilo_role(r.act, slot)) {
            g.oh = g_NXh + (size_t)slot * MS;
            g.ol = g_NXl + (size_t)slot * MS;
        }
        return true;
    }
    int a = r.act;
    int j = slot - 3;
    const float* Bv = g_ptrs.node_b + (node * 4 + j) * DIM;
    if (j == 0) {
        if (a != 0 && a != 1 && a != 3) return false;
        g.Xh = g_NXh; g.Xl = g_NXl;
        g.Bv = (a == 3) ? nullptr : Bv;
        g.act = (a == 1) ? 2 : 0;
        g.scale = 1.f; g.out = g_h0;
        return true;
    }
    if (j == 1) {
        if (a != 0 && a != 1 && a != 3 && a != 5) return false;
        g.Xh = g_NXh + (size_t)1 * MS; g.Xl = g_NXl + (size_t)1 * MS;
        g.Bv = (a == 3) ? nullptr : Bv;
        g.act = (a == 5) ? 2 : 0;
        g.scale = 1.f; g.out = g_h1;
        return true;
    }
    if (j == 2) {
        if (a != 0 && a != 3) return false;
        g.Xh = g_NXh + (size_t)2 * MS; g.Xl = g_NXl + (size_t)2 * MS;
        g.Bv = (a == 3) ? nullptr : Bv;
        g.act = 0; g.scale = 1.f; g.out = g_h2;
        return true;
    }
    if (a != 0 && a != 1 && a != 3) return false;
    g.Xh = g_NXh; g.Xl = g_NXl;
    g.Bv = Bv; g.act = 0; g.scale = r.aw;
    g.res = g_qv; g.out = g_outs + (size_t)node * MS;
    return true;
}

// ---------------------------------------------------------------------------
// Pipelined mma GEMM (2-product fp16): CTA 128x128, 16 warps (32x32 each),
// K-chunk 64 ; stage: A_h 16K | A_l 16K | B 16K = 48K ; 2 stages = 96KB
// block 512 (4 warps/SMSP), grid (4, 32, nz)
// ---------------------------------------------------------------------------
#define GEMM_SMEM 98304
#define STAGE_STRIDE 49152

__global__ void __launch_bounds__(512) gemm_mma(int node, int base_slot) {
    int slot = base_slot + blockIdx.z;
    GemmCfg g;
    if (!resolve_gemm(node, slot, g)) return;

    extern __shared__ char smem[];
    uint32_t sbase = smem_u32(smem);
    int t = threadIdx.x, lane = t & 31, wid = t >> 5;
    int m0 = blockIdx.y * 128, n0 = blockIdx.x * 128;
    int wm = (wid & 3) * 32, wn = (wid >> 2) * 32;

    float acc[2][4][4];
#pragma unroll
    for (int i = 0; i < 2; i++)
#pragma unroll
        for (int j = 0; j < 4; j++)
#pragma unroll
            for (int l = 0; l < 4; l++) acc[i][j][l] = 0.f;

    // loaders: 512 threads ; 4 threads/row (128 rows), 16 fp16 (32B) each
    int lrow = t >> 2, lcb = (t & 3) * 16;
    const __half* pAh = g.Xh + (size_t)(m0 + lrow) * DIM + lcb;
    const __half* pAl = g.Xl + (size_t)(m0 + lrow) * DIM + lcb;
    const __half* pB  = g.W  + (size_t)(n0 + lrow) * DIM + lcb;
    uint32_t doff[2];
#pragma unroll
    for (int i = 0; i < 2; i++)
        doff[i] = SW128((uint32_t)(lrow * 128 + (lcb + i * 8) * 2));

    // ldmatrix lane addressing
    int a_r = (lane & 15), a_k8 = (lane >> 4) << 3;
    int b_n = ((lane & 16) >> 1) + (lane & 7), b_k8 = (lane & 8);

    // prologue: stage 0 <- chunk 0
    {
        uint32_t sb = sbase;
#pragma unroll
        for (int i = 0; i < 2; i++) {
            cpa16(sb + doff[i],         pAh + i * 8);
            cpa16(sb + 16384 + doff[i], pAl + i * 8);
            cpa16(sb + 32768 + doff[i], pB  + i * 8);
        }
        CPA_COMMIT();
    }

    for (int c = 0; c < 8; c++) {
        if (c < 7) {
            int k0 = (c + 1) * 64;
            uint32_t sb = sbase + ((c + 1) & 1) * STAGE_STRIDE;
#pragma unroll
            for (int i = 0; i < 2; i++) {
                cpa16(sb + doff[i],         pAh + k0 + i * 8);
                cpa16(sb + 16384 + doff[i], pAl + k0 + i * 8);
                cpa16(sb + 32768 + doff[i], pB  + k0 + i * 8);
            }
            CPA_COMMIT();
            CPA_WAIT1();
        } else {
            CPA_WAIT0();
        }
        __syncthreads();

        uint32_t sA_H = sbase + (c & 1) * STAGE_STRIDE;
        uint32_t sA_L = sA_H + 16384, sB = sA_H + 32768;
#pragma unroll
        for (int kt = 0; kt < 4; kt++) {
            int kb = kt * 16;
            uint32_t ah[2][4], al[2][4];
#pragma unroll
            for (int mt = 0; mt < 2; mt++) {
                uint32_t off = SW128((uint32_t)((wm + mt * 16 + a_r) * 128 + (kb + a_k8) * 2));
                ldm4(sA_H + off, ah[mt]);
                ldm4(sA_L + off, al[mt]);
            }
#pragma unroll
            for (int ng = 0; ng < 2; ng++) {
                uint32_t boff = SW128((uint32_t)((wn + ng * 16 + b_n) * 128 + (kb + b_k8) * 2));
                uint32_t b4[4];
                ldm4(sB + boff, b4);
#pragma unroll
                for (int mt = 0; mt < 2; mt++) {
                    mma16816(acc[mt][2 * ng],     ah[mt], b4[0], b4[1]);
                    mma16816(acc[mt][2 * ng + 1], ah[mt], b4[2], b4[3]);
                    mma16816(acc[mt][2 * ng],     al[mt], b4[0], b4[1]);
                    mma16816(acc[mt][2 * ng + 1], al[mt], b4[2], b4[3]);
                }
            }
        }
        __syncthreads();
    }

    // epilogue
#pragma unroll
    for (int mt = 0; mt < 2; mt++) {
        int r0 = m0 + wm + mt * 16 + (lane >> 2);
#pragma unroll
        for (int nt = 0; nt < 4; nt++) {
            int col = n0 + wn + nt * 8 + (lane & 3) * 2;
#pragma unroll
            for (int h = 0; h < 2; h++) {
                int row = r0 + h * 8;
                float v0 = acc[mt][nt][h * 2], v1 = acc[mt][nt][h * 2 + 1];
                if (g.Bv) { v0 += g.Bv[col]; v1 += g.Bv[col + 1]; }
                if (g.act == 1)      { v0 = fmaxf(v0, 0.f); v1 = fmaxf(v1, 0.f); }
                else if (g.act == 2) { v0 = geluf(v0); v1 = geluf(v1); }
                if (g.res) {
                    v0 += g.res[(size_t)row * DIM + col];
                    v1 += g.res[(size_t)row * DIM + col + 1];
                }
                v0 *= g.scale; v1 *= g.scale;
                size_t p = (size_t)row * DIM + col;
                *(float2*)(g.out + p) = make_float2(v0, v1);
                if (g.oh) {
                    __half h0, l0, h1, l1;
                    split_h(v0, h0, l0); split_h(v1, h1, l1);
                    *(uint32_t*)(g.oh + p) =
                        (uint32_t)__half_as_ushort(h0) | ((uint32_t)__half_as_ushort(h1) << 16);
                    *(uint32_t*)(g.ol + p) =
                        (uint32_t)__half_as_ushort(l0) | ((uint32_t)__half_as_ushort(l1) << 16);
                }
            }
        }
    }
}

// ---------------------------------------------------------------------------
// Flash attention (act0): O = softmax(QK^T/8) V  -> NX0 hi/lo
// grid (8, 32), 256 thr (8 warps), warp w owns rows w*16..w*16+15
// smem: Qh 16K | Ql 16K | K 8K | V 8K = 48KB
// ---------------------------------------------------------------------------
__global__ void __launch_bounds__(256) flash_k(int node) {
    if (g_nr[node].act != 0) return;
    extern __shared__ char smem[];
    uint32_t sQ_H = smem_u32(smem);
    uint32_t sQ_L = sQ_H + 16384;
    uint32_t sK = sQ_H + 32768, sV = sQ_H + 40960;

    int t = threadIdx.x, lane = t & 31, wid = t >> 5;
    int bh = blockIdx.y, b = bh >> 3, head = bh & 7;
    int i0 = blockIdx.x * 128;

    const float* Q = g_h0 + (size_t)b * SLEN * DIM + head * DH;
    const float* K = g_h1 + (size_t)b * SLEN * DIM + head * DH;
    const float* V = g_h2 + (size_t)b * SLEN * DIM + head * DH;

    // load Q tile 128x64 -> hi/lo (once)
    {
        int lrow = t >> 1, lcb = (t & 1) * 32;
        const float* qr = Q + (size_t)(i0 + lrow) * DIM + lcb;
#pragma unroll
        for (int i = 0; i < 8; i++) {
            uint2 hi, lo; cvt_hilo(*(const float4*)(qr + i * 4), hi, lo);
            uint32_t off = SW128((uint32_t)(lrow * 128 + (lcb + i * 4) * 2));
            *(uint2*)(smem + off) = hi;
            *(uint2*)(smem + 16384 + off) = lo;
        }
    }

    float O[8][4];
#pragma unroll
    for (int d = 0; d < 8; d++)
#pragma unroll
        for (int l = 0; l < 4; l++) O[d][l] = 0.f;
    float mrow[2] = {-3.4e38f, -3.4e38f};
    float lrow_[2] = {0.f, 0.f};

    int a_r = (lane & 15), a_k8 = (lane >> 4) << 3;
    int b_n = ((lane & 16) >> 1) + (lane & 7), b_k8 = (lane & 8);
    int v_k = (lane & 15), v_n8 = (lane & 16) >> 1;
    int kvrow = t >> 2, kvcb = (t & 3) * 16;

    for (int jc = 0; jc < 16; jc++) {
        int j0 = jc * 64;
        {
            const float* kr = K + (size_t)(j0 + kvrow) * DIM + kvcb;
            const float* vr = V + (size_t)(j0 + kvrow) * DIM + kvcb;
#pragma unroll
            for (int i = 0; i < 4; i++) {
                uint32_t off = SW128((uint32_t)(kvrow * 128 + (kvcb + i * 4) * 2));
                *(uint2*)(smem + 32768 + off) = cvt_h(*(const float4*)(kr + i * 4));
                *(uint2*)(smem + 40960 + off) = cvt_h(*(const float4*)(vr + i * 4));
            }
        }
        __syncthreads();

        // S = Q K^T
        float s[8][4];
#pragma unroll
        for (int j = 0; j < 8; j++)
#pragma unroll
            for (int l = 0; l < 4; l++) s[j][l] = 0.f;
#pragma unroll
        for (int kt = 0; kt < 4; kt++) {
            int kb = kt * 16;
            uint32_t qh[4], ql[4];
            uint32_t qoff = SW128((uint32_t)((wid * 16 + a_r) * 128 + (kb + a_k8) * 2));
            ldm4(sQ_H + qoff, qh);
            ldm4(sQ_L + qoff, ql);
#pragma unroll
            for (int ng = 0; ng < 4; ng++) {
                uint32_t boff = SW128((uint32_t)((ng * 16 + b_n) * 128 + (kb + b_k8) * 2));
                uint32_t k4[4];
                ldm4(sK + boff, k4);
                mma16816(s[2 * ng],     qh, k4[0], k4[1]);
                mma16816(s[2 * ng + 1], qh, k4[2], k4[3]);
                mma16816(s[2 * ng],     ql, k4[0], k4[1]);
                mma16816(s[2 * ng + 1], ql, k4[2], k4[3]);
            }
        }
#pragma unroll
        for (int j = 0; j < 8; j++)
#pragma unroll
            for (int l = 0; l < 4; l++) s[j][l] *= 0.125f;

        // online softmax per row-half
#pragma unroll
        for (int h = 0; h < 2; h++) {
            float mj = -3.4e38f;
#pragma unroll
            for (int j = 0; j < 8; j++) mj = fmaxf(mj, fmaxf(s[j][h * 2], s[j][h * 2 + 1]));
            mj = fmaxf(mj, __shfl_xor_sync(0xffffffffu, mj, 1));
            mj = fmaxf(mj, __shfl_xor_sync(0xffffffffu, mj, 2));
            float mnew = fmaxf(mrow[h], mj);
            float alpha = expf(mrow[h] - mnew);
            float ps = 0.f;
#pragma unroll
            for (int j = 0; j < 8; j++) {
                s[j][h * 2]     = expf(s[j][h * 2] - mnew);
                s[j][h * 2 + 1] = expf(s[j][h * 2 + 1] - mnew);
                ps += s[j][h * 2] + s[j][h * 2 + 1];
            }
            ps += __shfl_xor_sync(0xffffffffu, ps, 1);
            ps += __shfl_xor_sync(0xffffffffu, ps, 2);
            lrow_[h] = lrow_[h] * alpha + ps;
            mrow[h] = mnew;
#pragma unroll
            for (int d = 0; d < 8; d++) {
                O[d][h * 2]     *= alpha;
                O[d][h * 2 + 1] *= alpha;
            }
        }

        // O += P V ; P split hi/lo, V single
#pragma unroll
        for (int g4 = 0; g4 < 4; g4++) {
            uint32_t ah[4], al[4];
            {
                uint2 hi, lo;
                cvt_hilo(make_float4(s[2 * g4][0], s[2 * g4][1], s[2 * g4][2], s[2 * g4][3]), hi, lo);
                ah[0] = hi.x; ah[1] = hi.y; al[0] = lo.x; al[1] = lo.y;
                cvt_hilo(make_float4(s[2 * g4 + 1][0], s[2 * g4 + 1][1], s[2 * g4 + 1][2], s[2 * g4 + 1][3]), hi, lo);
                ah[2] = hi.x; ah[3] = hi.y; al[2] = lo.x; al[3] = lo.y;
            }
            int kb = g4 * 16;
#pragma unroll
            for (int ng = 0; ng < 4; ng++) {
                uint32_t boff = SW128((uint32_t)((kb + v_k) * 128 + (ng * 16 + v_n8) * 2));
                uint32_t v4[4];
                ldm4t(sV + boff, v4);
                mma16816(O[2 * ng],     ah, v4[0], v4[1]);
                mma16816(O[2 * ng + 1], ah, v4[2], v4[3]);
                mma16816(O[2 * ng],     al, v4[0], v4[1]);
                mma16816(O[2 * ng + 1], al, v4[2], v4[3]);
            }
        }
        __syncthreads();
    }

    // normalize + write -> NX0 hi/lo
    float inv0 = 1.0f / lrow_[0], inv1 = 1.0f / lrow_[1];
    __half* Oh = g_NXh + ((size_t)b * SLEN) * DIM + head * DH;
    __half* Ol = g_NXl + ((size_t)b * SLEN) * DIM + head * DH;
    int r0 = i0 + wid * 16 + (lane >> 2);
#pragma unroll
    for (int d = 0; d < 8; d++) {
        int col = d * 8 + (lane & 3) * 2;
#pragma unroll
        for (int h = 0; h < 2; h++) {
            int row = r0 + h * 8;
            float inv = h ? inv1 : inv0;
            float v0 = O[d][h * 2] * inv, v1 = O[d][h * 2 + 1] * inv;
            __half h0, l0, h1, l1;
            split_h(v0, h0, l0); split_h(v1, h1, l1);
            size_t p = (size_t)row * DIM + col;
            *(uint32_t*)(Oh + p) =
                (uint32_t)__half_as_ushort(h0) | ((uint32_t)__half_as_ushort(h1) << 16);
            *(uint32_t*)(Ol + p) =
                (uint32_t)__half_as_ushort(l0) | ((uint32_t)__half_as_ushort(l1) << 16);
        }
    }
}

// combine (act1: h0*h1 ; act3: relu(h0+h1+h2)) -> NX0 hi/lo
__global__ void combine_k(int node) {
    int a = g_nr[node].act;
    if (a != 1 && a != 3) return;
    size_t stride = (size_t)gridDim.x * blockDim.x;
    for (size_t p = (size_t)blockIdx.x * blockDim.x + threadIdx.x; p < (size_t)MS; p += stride) {
        float v = (a == 1) ? g_h0[p] * g_h1[p]
                           : fmaxf(g_h0[p] + g_h1[p] + g_h2[p], 0.f);
        __half h, l; split_h(v, h, l);
        g_NXh[p] = h; g_NXl[p] = l;
    }
}

// finish (acts 2,4,5,6,7) warp-per-row ; grid 512
__global__ void finish_k(int node) {
    NR r = g_nr[node];
    int a = r.act;
    if (a == 0 || a == 1 || a == 3) return;
    int warp = threadIdx.x >> 5, lane = threadIdx.x & 31;
    int row = blockIdx.x * 8 + warp;
    size_t rb = (size_t)row * DIM;
    float* out = g_outs + (size_t)node * MS + rb;
    if (a == 4 || a == 5 || a == 6) {
#pragma unroll
        for (int i = 0; i < 16; i++) {
            int c = lane + i * 32;
            float y;
            if (a == 4)      y = g_qv[rb + c] * sigmoidf_(g_kv[rb + c]) + g_vv[rb + c];
            else if (a == 5) y = g_qv[rb + c] + g_h1[rb + c];
            else             y = g_qv[rb + c] + g_kv[rb + c];
            out[c] = r.aw * y;
        }
        return;
    }
    // a == 2 or 7: LN
    float v[16];
#pragma unroll
    for (int i = 0; i < 16; i++) {
        int c = lane + i * 32;
        v[i] = (a == 2) ? (g_qv[rb + c] + g_kv[rb + c] + g_vv[rb + c]) : g_qv[rb + c];
    }
    float s = 0.f;
#pragma unroll
    for (int i = 0; i < 16; i++) s += v[i];
    float mean = wsum(s) * (1.0f / 512.0f);
    float q = 0.f;
#pragma unroll
    for (int i = 0; i < 16; i++) { float d = v[i] - mean; q += d * d; }
    float inv = rsqrtf(wsum(q) * (1.0f / 512.0f) + EPSLN);
    const float* gm = g_ptrs.node_g + node * DIM;
    const float* bt = g_ptrs.node_beta + node * DIM;
#pragma unroll
    for (int i = 0; i < 16; i++) {
        int c = lane + i * 32;
        out[c] = r.aw * ((v[i] - mean) * inv * gm[c] + bt[c]);
    }
}

// final: sum unprocessed + LN ; warp-per-row, grid 512
__global__ void final_k(float* dout) {
    int warp = threadIdx.x >> 5, lane = threadIdx.x & 31;
    int row = blockIdx.x * 8 + warp;
    size_t rb = (size_t)row * DIM;
    float v[16];
#pragma unroll
    for (int i = 0; i < 16; i++) v[i] = 0.f;
    for (int c = 0; c < 8; c++) {
        if (!g_processed[c]) {
            const float* o = g_outs + (size_t)c * MS + rb;
#pragma unroll
            for (int i = 0; i < 16; i++) v[i] += o[lane + i * 32];
        }
    }
    float s = 0.f;
#pragma unroll
    for (int i = 0; i < 16; i++) s += v[i];
    float mean = wsum(s) * (1.0f / 512.0f);
    float q = 0.f;
#pragma unroll
    for (int i = 0; i < 16; i++) { float d = v[i] - mean; q += d * d; }
    float inv = rsqrtf(wsum(q) * (1.0f / 512.0f) + EPSLN);
#pragma unroll
    for (int i = 0; i < 16; i++) {
        int c = lane + i * 32;
        dout[rb + c] = (v[i] - mean) * inv * g_ptrs.out_g[c] + g_ptrs.out_beta[c];
    }
}

// ---------------------------------------------------------------------------
// Launch
// ---------------------------------------------------------------------------
extern "C" void kernel_launch(void* const* d_in, const int* in_sizes, int n_in,
                              void* d_out, int out_size) {
    (void)in_sizes; (void)n_in; (void)out_size;
    cudaFuncSetAttribute(gemm_mma, cudaFuncAttributeMaxDynamicSharedMemorySize, GEMM_SMEM);
    cudaFuncSetAttribute(flash_k,  cudaFuncAttributeMaxDynamicSharedMemorySize, 49152);

    setup_k<<<1, 1>>>(
        (const float*)d_in[0],  (const float*)d_in[1],  (const float*)d_in[2],
        (const float*)d_in[3],  (const float*)d_in[4],  (const float*)d_in[5],
        (const float*)d_in[6],  (const float*)d_in[7],  (const float*)d_in[8],
        (const float*)d_in[9],  (const float*)d_in[10], (const float*)d_in[11],
        (const float*)d_in[12], (const float*)d_in[13]);
    routing_k<<<1, 1>>>();
    conv_w_all<<<dim3(16, 16, 56), dim3(32, 8)>>>();

    for (int c = 0; c < 8; c++) {
        edge_pre<<<dim3(512, 3), 256>>>(c);
        gemm_mma<<<dim3(4, 32, 3), 512, GEMM_SMEM>>>(c, 0);   // edge q/k/v
        node_prep<<<512, 256>>>(c);
        gemm_mma<<<dim3(4, 32, 3), 512, GEMM_SMEM>>>(c, 3);   // node j0/j1/j2
        flash_k<<<dim3(8, 32), 256, 49152>>>(c);
        combine_k<<<2048, 256>>>(c);
        gemm_mma<<<dim3(4, 32, 1), 512, GEMM_SMEM>>>(c, 6);   // node j3
        finish_k<<<512, 256>>>(c);
    }
    final_k<<<512, 256>>>((float*)d_out);
}

// round 10
// speedup vs baseline: 4.0139x; 1.1207x over previous
#include <cuda_runtime.h>
#include <cuda_fp16.h>
#include <math.h>
#include <stdint.h>

// ---------------------------------------------------------------------------
// Problem constants
// ---------------------------------------------------------------------------
#define NROWS 4096          // B*SLEN
#define DIM   512
#define MS    (4096*512)
#define NHEAD 8
#define DH    64
#define SLEN  1024
#define EPSLN 1e-6f

// ---------------------------------------------------------------------------
// Device-resident input pointer table + route table
// ---------------------------------------------------------------------------
struct Ptrs {
    const float *inpute, *inputo, *node_p, *edge_p;
    const float *edge_W, *edge_b, *edge_g, *edge_beta;
    const float *node_W, *node_b, *node_g, *node_beta;
    const float *out_g, *out_beta;
};
__device__ Ptrs g_ptrs;

struct NR {
    int act; float aw;
    int q_in, q_op, q_e; float q_w;
    int k_valid, k_in, k_op, k_e; float k_w;
    int v_valid, v_in, v_op, v_e; float v_w;
};
__device__ NR  g_nr[8];
__device__ int g_processed[8];

// ---------------------------------------------------------------------------
// Scratch
// ---------------------------------------------------------------------------
__device__ float g_outs[8 * MS];
__device__ float g_qv[MS], g_kv[MS], g_vv[MS];
__device__ float g_h0[MS], g_h1[MS], g_h2[MS];
__device__ __align__(16) __half g_EXh[3 * MS], g_EXl[3 * MS];   // edge GEMM A inputs (hi/lo fp16)
__device__ __align__(16) __half g_NXh[3 * MS], g_NXl[3 * MS];   // node GEMM A inputs
__device__ __align__(16) __half g_Wt[8 * 7 * DIM * DIM];        // W^T single fp16 [node][slot][n][k]

// ---------------------------------------------------------------------------
// Helpers
// ---------------------------------------------------------------------------
__device__ __forceinline__ const float* buf_in(int idx) {
    if (idx == 0) return g_ptrs.inpute;
    if (idx == 1) return g_ptrs.inputo;
    return g_outs + (size_t)(idx - 2) * MS;
}

__device__ __forceinline__ float geluf(float x) {
    float x3 = x * x * x;
    return 0.5f * x * (1.0f + tanhf(0.7978845608028654f * (x + 0.044715f * x3)));
}
__device__ __forceinline__ float sigmoidf_(float x) {
    return 1.0f / (1.0f + expf(-x));
}

__device__ __forceinline__ float wsum(float v) {
#pragma unroll
    for (int o = 16; o; o >>= 1) v += __shfl_xor_sync(0xffffffffu, v, o);
    return v;
}

__device__ __forceinline__ void split_h(float v, __half& h, __half& l) {
    h = __float2half_rn(v);
    l = __float2half_rn(v - __half2float(h));
}

// ---------------------------------------------------------------------------
// mma.sync / ldmatrix / cp.async helpers
// ---------------------------------------------------------------------------
__device__ __forceinline__ uint32_t smem_u32(const void* p) {
    uint32_t a;
    asm("{ .reg .u64 t; cvta.to.shared.u64 t, %1; cvt.u32.u64 %0, t; }" : "=r"(a) : "l"(p));
    return a;
}
__device__ __forceinline__ void ldm4(uint32_t addr, uint32_t r[4]) {
    asm volatile("ldmatrix.sync.aligned.m8n8.x4.shared.b16 {%0,%1,%2,%3}, [%4];"
                 : "=r"(r[0]), "=r"(r[1]), "=r"(r[2]), "=r"(r[3]) : "r"(addr));
}
__device__ __forceinline__ void ldm4t(uint32_t addr, uint32_t r[4]) {
    asm volatile("ldmatrix.sync.aligned.m8n8.x4.trans.shared.b16 {%0,%1,%2,%3}, [%4];"
                 : "=r"(r[0]), "=r"(r[1]), "=r"(r[2]), "=r"(r[3]) : "r"(addr));
}
__device__ __forceinline__ void mma16816(float c[4], const uint32_t a[4],
                                         uint32_t b0, uint32_t b1) {
    asm volatile(
        "mma.sync.aligned.m16n8k16.row.col.f32.f16.f16.f32 "
        "{%0,%1,%2,%3}, {%4,%5,%6,%7}, {%8,%9}, {%0,%1,%2,%3};"
        : "+f"(c[0]), "+f"(c[1]), "+f"(c[2]), "+f"(c[3])
        : "r"(a[0]), "r"(a[1]), "r"(a[2]), "r"(a[3]), "r"(b0), "r"(b1));
}
__device__ __forceinline__ void cpa16(uint32_t dst, const void* src) {
    asm volatile("cp.async.ca.shared.global [%0], [%1], 16;" :: "r"(dst), "l"(src));
}
#define CPA_COMMIT() asm volatile("cp.async.commit_group;" ::: "memory")
#define CPA_WAIT2()  asm volatile("cp.async.wait_group 2;" ::: "memory")

#define SW128(o) ((o) ^ (((o) >> 3) & 0x70))

__device__ __forceinline__ uint32_t pack_h2(float x, float y) {
    __half2 h = __float22half2_rn(make_float2(x, y));
    return *(uint32_t*)&h;
}
__device__ __forceinline__ void cvt_hilo(float4 v, uint2& hi, uint2& lo) {
    hi = make_uint2(pack_h2(v.x, v.y), pack_h2(v.z, v.w));
    __half2 h0 = *(__half2*)&hi.x;
    __half2 h1 = *(__half2*)&hi.y;
    float lx = v.x - __half2float(h0.x);
    float ly = v.y - __half2float(h0.y);
    float lz = v.z - __half2float(h1.x);
    float lw = v.w - __half2float(h1.y);
    lo = make_uint2(pack_h2(lx, ly), pack_h2(lz, lw));
}
__device__ __forceinline__ uint2 cvt_h(float4 v) {
    return make_uint2(pack_h2(v.x, v.y), pack_h2(v.z, v.w));
}

// ---------------------------------------------------------------------------
// Setup + routing
// ---------------------------------------------------------------------------
__global__ void setup_k(const float* a0, const float* a1, const float* a2, const float* a3,
                        const float* a4, const float* a5, const float* a6, const float* a7,
                        const float* a8, const float* a9, const float* a10, const float* a11,
                        const float* a12, const float* a13) {
    Ptrs p;
    p.inpute = a0; p.inputo = a1; p.node_p = a2; p.edge_p = a3;
    p.edge_W = a4; p.edge_b = a5; p.edge_g = a6; p.edge_beta = a7;
    p.node_W = a8; p.node_b = a9; p.node_g = a10; p.node_beta = a11;
    p.out_g = a12; p.out_beta = a13;
    g_ptrs = p;
}

__device__ int d_amax(const float* x, int n, int lo) {
    int bi = lo; float bv = x[lo];
    for (int i = lo + 1; i < n; i++) { if (x[i] > bv) { bv = x[i]; bi = i; } }
    return bi;
}
__device__ float d_smw(const float* x, int n, int lo, int sel) {
    float mx = x[lo];
    for (int i = lo + 1; i < n; i++) mx = fmaxf(mx, x[i]);
    float s = 0.f;
    for (int i = lo; i < n; i++) s += expf(x[i] - mx);
    return expf(x[sel] - mx) / s;
}

__global__ void routing_k() {
    if (threadIdx.x || blockIdx.x) return;
    const float* np = g_ptrs.node_p;
    const float* ep = g_ptrs.edge_p;
    for (int i = 0; i < 8; i++) g_processed[i] = 0;
    int lind = 0;
    for (int c = 0; c < 8; c++) {
        int nsrc = (c + 2 < 5) ? c + 2 : 5;
        int snode = c - nsrc;
        int n = nsrc * 5;
        const float* e0 = ep + 0 * 170 + lind * 5;
        const float* e1 = ep + 1 * 170 + lind * 5;
        const float* e2 = ep + 2 * 170 + lind * 5;
        NR r; r.k_valid = 0; r.v_valid = 0;
        r.k_in = 0; r.k_op = 4; r.k_e = 0; r.k_w = 0.f;
        r.v_in = 0; r.v_op = 4; r.v_e = 0; r.v_w = 0.f;

        int nact = d_amax(np + c * 8, 8, 0);
        r.act = nact;
        r.aw = d_smw(np + c * 8, 8, 0, nact);

        int qs = d_amax(e0, n, 5);
        int qse = qs / 5;
        r.q_in = (qse == 0) ? 0 : (snode + qse + 2);
        r.q_op = qs % 5; r.q_e = lind + qse;
        r.q_w = d_smw(e0, n, 5, qs);
        if (r.q_in >= 2) g_processed[r.q_in - 2] = 1;

        if (nact < 7) {
            int lo = (nact > 0) ? 5 : 0;
            int ks = d_amax(e1, n, lo);
            int kse = ks / 5;
            r.k_valid = 1;
            r.k_in = (kse == 0) ? 0 : (snode + kse + 2);
            r.k_op = ks % 5; r.k_e = lind + kse;
            r.k_w = d_smw(e1, n, lo, ks);
            if (r.k_in >= 2) g_processed[r.k_in - 2] = 1;
            int ktype = (kse == 0) ? -2 : -1;
            if (nact < 5) {
                r.v_valid = 1;
                int vs, vlo, vn;
                if (nact == 0 && ktype == -2) { vlo = 0; vn = 5; }
                else if (nact > 0)            { vlo = 5; vn = n; }
                else                          { vlo = 0; vn = n; }
                vs = d_amax(e2, vn, vlo);
                int vse = vs / 5;
                r.v_in = (vse == 0) ? 0 : (snode + vse + 2);
                r.v_op = vs % 5; r.v_e = lind + vse;
                r.v_w = d_smw(e2, vn, vlo, vs);
                if (r.v_in >= 2) g_processed[r.v_in - 2] = 1;
            }
        }
        g_nr[c] = r;
        lind += nsrc;
    }
}

// role r output feeds node GEMM slot 3+r?
__device__ __forceinline__ bool need_hilo_role(int act, int role) {
    if (role == 0) return act == 1 || act == 3;
    if (role == 1) return act == 0 || act == 1 || act == 3 || act == 5;
    return act == 0 || act == 3;
}

// ---------------------------------------------------------------------------
// Weight selection for slot 0..6
// ---------------------------------------------------------------------------
__device__ const float* resolve_w(int node, int slot) {
    NR r = g_nr[node];
    if (slot < 3) {
        int valid, op, e;
        if (slot == 0)      { valid = 1;         op = r.q_op; e = r.q_e; }
        else if (slot == 1) { valid = r.k_valid; op = r.k_op; e = r.k_e; }
        else                { valid = r.v_valid; op = r.v_op; e = r.v_e; }
        if (valid && op <= 3) return g_ptrs.edge_W + (size_t)e * DIM * DIM;
        return nullptr;
    }
    int a = r.act, j = slot - 3;
    bool need =
        (j == 0 && (a == 0 || a == 1 || a == 3)) ||
        (j == 1 && (a == 0 || a == 1 || a == 3 || a == 5)) ||
        (j == 2 && (a == 0 || a == 3)) ||
        (j == 3 && (a == 0 || a == 1 || a == 3));
    if (need) return g_ptrs.node_W + ((size_t)node * 4 + j) * DIM * DIM;
    return nullptr;
}

// Convert+transpose W -> single fp16.  grid (16,16,56) block (32,8)
__global__ void conv_w_all() {
    int z = blockIdx.z; int node = z / 7, slot = z % 7;
    const float* W = resolve_w(node, slot);
    if (!W) return;
    __shared__ float tile[32][33];
    int n0 = blockIdx.x * 32, k0 = blockIdx.y * 32;
    int tx = threadIdx.x, ty = threadIdx.y;
#pragma unroll
    for (int dy = 0; dy < 4; dy++)
        tile[ty * 4 + dy][tx] = W[(size_t)(k0 + ty * 4 + dy) * DIM + n0 + tx];
    __syncthreads();
    size_t base = (size_t)z * DIM * DIM;
#pragma unroll
    for (int dy = 0; dy < 4; dy++) {
        int n = n0 + ty * 4 + dy, k = k0 + tx;
        g_Wt[base + (size_t)n * DIM + k] = __float2half_rn(tile[tx][ty * 4 + dy]);
    }
}

// ---------------------------------------------------------------------------
// edge_pre: warp-per-row, float4 vectorized. grid (512, 3) block 256
// ---------------------------------------------------------------------------
__global__ void edge_pre(int node) {
    int role = blockIdx.y;
    NR r = g_nr[node];
    int valid, in, op, e; float w; float* out;
    if (role == 0)      { valid = 1;         in = r.q_in; op = r.q_op; e = r.q_e; w = r.q_w; out = g_qv; }
    else if (role == 1) { valid = r.k_valid; in = r.k_in; op = r.k_op; e = r.k_e; w = r.k_w; out = g_kv; }
    else                { valid = r.v_valid; in = r.v_in; op = r.v_op; e = r.v_e; w = r.v_w; out = g_vv; }
    if (!valid) return;
    int warp = threadIdx.x >> 5, lane = threadIdx.x & 31;
    int row = blockIdx.x * 8 + warp;
    size_t rb = (size_t)row * DIM;
    int c0 = lane * 4;
    const float* x = buf_in(in) + rb;
    float4 v4[4];
#pragma unroll
    for (int i = 0; i < 4; i++) v4[i] = *(const float4*)(x + c0 + i * 128);

    __half* exh = g_EXh + (size_t)role * MS + rb;
    __half* exl = g_EXl + (size_t)role * MS + rb;
    if (op <= 2) {
        const float* gm = g_ptrs.edge_g + e * DIM;
        const float* bt = g_ptrs.edge_beta + e * DIM;
        float s = 0.f;
#pragma unroll
        for (int i = 0; i < 4; i++) s += v4[i].x + v4[i].y + v4[i].z + v4[i].w;
        float mean = wsum(s) * (1.0f / 512.0f);
        float q = 0.f;
#pragma unroll
        for (int i = 0; i < 4; i++) {
            float dx = v4[i].x - mean, dy = v4[i].y - mean, dz = v4[i].z - mean, dw = v4[i].w - mean;
            q += dx * dx + dy * dy + dz * dz + dw * dw;
        }
        float inv = rsqrtf(wsum(q) * (1.0f / 512.0f) + EPSLN);
#pragma unroll
        for (int i = 0; i < 4; i++) {
            float4 g4 = *(const float4*)(gm + c0 + i * 128);
            float4 b4 = *(const float4*)(bt + c0 + i * 128);
            float4 y4;
            y4.x = (v4[i].x - mean) * inv * g4.x + b4.x;
            y4.y = (v4[i].y - mean) * inv * g4.y + b4.y;
            y4.z = (v4[i].z - mean) * inv * g4.z + b4.z;
            y4.w = (v4[i].w - mean) * inv * g4.w + b4.w;
            uint2 hi, lo; cvt_hilo(y4, hi, lo);
            *(uint2*)(exh + c0 + i * 128) = hi;
            *(uint2*)(exl + c0 + i * 128) = lo;
        }
    } else if (op == 3) {
#pragma unroll
        for (int i = 0; i < 4; i++) {
            uint2 hi, lo; cvt_hilo(v4[i], hi, lo);
            *(uint2*)(exh + c0 + i * 128) = hi;
            *(uint2*)(exl + c0 + i * 128) = lo;
        }
    } else { // op == 4
        bool nh = need_hilo_role(r.act, role);
        __half* nxh = g_NXh + (size_t)role * MS + rb;
        __half* nxl = g_NXl + (size_t)role * MS + rb;
#pragma unroll
        for (int i = 0; i < 4; i++) {
            float4 y4 = make_float4(w * v4[i].x, w * v4[i].y, w * v4[i].z, w * v4[i].w);
            *(float4*)(out + rb + c0 + i * 128) = y4;
            if (nh) {
                uint2 hi, lo; cvt_hilo(y4, hi, lo);
                *(uint2*)(nxh + c0 + i * 128) = hi;
                *(uint2*)(nxl + c0 + i * 128) = lo;
            }
        }
    }
}

// node prep (act0): NX0 = LN(qv) hi/lo ; warp-per-row, float4 ; grid 512
__global__ void node_prep(int node) {
    NR r = g_nr[node];
    if (r.act != 0) return;
    int warp = threadIdx.x >> 5, lane = threadIdx.x & 31;
    int row = blockIdx.x * 8 + warp;
    size_t rb = (size_t)row * DIM;
    int c0 = lane * 4;
    const float* gm = g_ptrs.node_g + node * DIM;
    const float* bt = g_ptrs.node_beta + node * DIM;
    float4 v4[4];
#pragma unroll
    for (int i = 0; i < 4; i++) v4[i] = *(const float4*)(g_qv + rb + c0 + i * 128);
    float s = 0.f;
#pragma unroll
    for (int i = 0; i < 4; i++) s += v4[i].x + v4[i].y + v4[i].z + v4[i].w;
    float mean = wsum(s) * (1.0f / 512.0f);
    float q = 0.f;
#pragma unroll
    for (int i = 0; i < 4; i++) {
        float dx = v4[i].x - mean, dy = v4[i].y - mean, dz = v4[i].z - mean, dw = v4[i].w - mean;
        q += dx * dx + dy * dy + dz * dz + dw * dw;
    }
    float inv = rsqrtf(wsum(q) * (1.0f / 512.0f) + EPSLN);
#pragma unroll
    for (int i = 0; i < 4; i++) {
        float4 g4 = *(const float4*)(gm + c0 + i * 128);
        float4 b4 = *(const float4*)(bt + c0 + i * 128);
        float4 y4;
        y4.x = (v4[i].x - mean) * inv * g4.x + b4.x;
        y4.y = (v4[i].y - mean) * inv * g4.y + b4.y;
        y4.z = (v4[i].z - mean) * inv * g4.z + b4.z;
        y4.w = (v4[i].w - mean) * inv * g4.w + b4.w;
        uint2 hi, lo; cvt_hilo(y4, hi, lo);
        *(uint2*)(g_NXh + rb + c0 + i * 128) = hi;
        *(uint2*)(g_NXl + rb + c0 + i * 128) = lo;
    }
}

// ---------------------------------------------------------------------------
// GEMM config
// ---------------------------------------------------------------------------
struct GemmCfg {
    const __half *Xh, *Xl, *W;
    const float* Bv;
    int act;            // 0 none, 1 relu, 2 gelu
    float scale;
    const float* res;
    float* out;
    __half *oh, *ol;
};

__device__ bool resolve_gemm(int node, int slot, GemmCfg& g) {
    NR r = g_nr[node];
    g.oh = nullptr; g.ol = nullptr; g.res = nullptr;
    g.W = g_Wt + ((size_t)node * 7 + slot) * DIM * DIM;
    if (slot < 3) {
        int valid, op, e; float w; float* out;
        if (slot == 0)      { valid = 1;         op = r.q_op; e = r.q_e; w = r.q_w; out = g_qv; }
        else if (slot == 1) { valid = r.k_valid; op = r.k_op; e = r.k_e; w = r.k_w; out = g_kv; }
        else                { valid = r.v_valid; op = r.v_op; e = r.v_e; w = r.v_w; out = g_vv; }
        if (!valid || op == 4) return false;
        g.Xh = g_EXh + (size_t)slot * MS;
        g.Xl = g_EXl + (size_t)slot * MS;
        g.Bv = g_ptrs.edge_b + e * DIM;
        g.act = (op == 0) ? 1 : (op == 1) ? 2 : 0;
        g.scale = w; g.out = out;
        if (need_hilo_role(r.act, slot)) {
            g.oh = g_NXh + (size_t)slot * MS;
            g.ol = g_NXl + (size_t)slot * MS;
        }
        return true;
    }
    int a = r.act;
    int j = slot - 3;
    const float* Bv = g_ptrs.node_b + (node * 4 + j) * DIM;
    if (j == 0) {
        if (a != 0 && a != 1 && a != 3) return false;
        g.Xh = g_NXh; g.Xl = g_NXl;
        g.Bv = (a == 3) ? nullptr : Bv;
        g.act = (a == 1) ? 2 : 0;
        g.scale = 1.f; g.out = g_h0;
        return true;
    }
    if (j == 1) {
        if (a != 0 && a != 1 && a != 3 && a != 5) return false;
        g.Xh = g_NXh + (size_t)1 * MS; g.Xl = g_NXl + (size_t)1 * MS;
        g.Bv = (a == 3) ? nullptr : Bv;
        g.act = (a == 5) ? 2 : 0;
        g.scale = 1.f; g.out = g_h1;
        return true;
    }
    if (j == 2) {
        if (a != 0 && a != 3) return false;
        g.Xh = g_NXh + (size_t)2 * MS; g.Xl = g_NXl + (size_t)2 * MS;
        g.Bv = (a == 3) ? nullptr : Bv;
        g.act = 0; g.scale = 1.f; g.out = g_h2;
        return true;
    }
    if (a != 0 && a != 1 && a != 3) return false;
    g.Xh = g_NXh; g.Xl = g_NXl;
    g.Bv = Bv; g.act = 0; g.scale = r.aw;
    g.res = g_qv; g.out = g_outs + (size_t)node * MS;
    return true;
}

// ---------------------------------------------------------------------------
// Pipelined mma GEMM (2-product fp16): CTA 128x128, 16 warps (32x32 each),
// K-chunk 64 ; stage: A_h 16K | A_l 16K | B 16K = 48K ; 4-stage ring = 192KB
// block 512 (4 warps/SMSP), grid (4, 32, nz). One __syncthreads per chunk;
// prefetch depth 2; wait_group 2 (with empty commits at tail).
// ---------------------------------------------------------------------------
#define GEMM_SMEM 196608
#define STAGE_STRIDE 49152

__global__ void __launch_bounds__(512) gemm_mma(int node, int base_slot) {
    int slot = base_slot + blockIdx.z;
    GemmCfg g;
    if (!resolve_gemm(node, slot, g)) return;

    extern __shared__ char smem[];
    uint32_t sbase = smem_u32(smem);
    int t = threadIdx.x, lane = t & 31, wid = t >> 5;
    int m0 = blockIdx.y * 128, n0 = blockIdx.x * 128;
    int wm = (wid & 3) * 32, wn = (wid >> 2) * 32;

    float acc[2][4][4];
#pragma unroll
    for (int i = 0; i < 2; i++)
#pragma unroll
        for (int j = 0; j < 4; j++)
#pragma unroll
            for (int l = 0; l < 4; l++) acc[i][j][l] = 0.f;

    // loaders: 512 threads ; 4 threads/row (128 rows), 16 fp16 (32B) each
    int lrow = t >> 2, lcb = (t & 3) * 16;
    const __half* pAh = g.Xh + (size_t)(m0 + lrow) * DIM + lcb;
    const __half* pAl = g.Xl + (size_t)(m0 + lrow) * DIM + lcb;
    const __half* pB  = g.W  + (size_t)(n0 + lrow) * DIM + lcb;
    uint32_t doff[2];
#pragma unroll
    for (int i = 0; i < 2; i++)
        doff[i] = SW128((uint32_t)(lrow * 128 + (lcb + i * 8) * 2));

    // ldmatrix lane addressing
    int a_r = (lane & 15), a_k8 = (lane >> 4) << 3;
    int b_n = ((lane & 16) >> 1) + (lane & 7), b_k8 = (lane & 8);

    // prologue: stages 0,1 <- chunks 0,1
#pragma unroll
    for (int pc = 0; pc < 2; pc++) {
        uint32_t sb = sbase + pc * STAGE_STRIDE;
        int k0 = pc * 64;
#pragma unroll
        for (int i = 0; i < 2; i++) {
            cpa16(sb + doff[i],         pAh + k0 + i * 8);
            cpa16(sb + 16384 + doff[i], pAl + k0 + i * 8);
            cpa16(sb + 32768 + doff[i], pB  + k0 + i * 8);
        }
        CPA_COMMIT();
    }

    for (int c = 0; c < 8; c++) {
        if (c + 2 < 8) {
            int k0 = (c + 2) * 64;
            uint32_t sb = sbase + ((c + 2) & 3) * STAGE_STRIDE;
#pragma unroll
            for (int i = 0; i < 2; i++) {
                cpa16(sb + doff[i],         pAh + k0 + i * 8);
                cpa16(sb + 16384 + doff[i], pAl + k0 + i * 8);
                cpa16(sb + 32768 + doff[i], pB  + k0 + i * 8);
            }
        }
        CPA_COMMIT();   // (possibly empty group at tail — keeps wait_group math uniform)
        CPA_WAIT2();
        __syncthreads();

        uint32_t sA_H = sbase + (c & 3) * STAGE_STRIDE;
        uint32_t sA_L = sA_H + 16384, sB = sA_H + 32768;
#pragma unroll
        for (int kt = 0; kt < 4; kt++) {
            int kb = kt * 16;
            uint32_t ah[2][4], al[2][4];
#pragma unroll
            for (int mt = 0; mt < 2; mt++) {
                uint32_t off = SW128((uint32_t)((wm + mt * 16 + a_r) * 128 + (kb + a_k8) * 2));
                ldm4(sA_H + off, ah[mt]);
                ldm4(sA_L + off, al[mt]);
            }
#pragma unroll
            for (int ng = 0; ng < 2; ng++) {
                uint32_t boff = SW128((uint32_t)((wn + ng * 16 + b_n) * 128 + (kb + b_k8) * 2));
                uint32_t b4[4];
                ldm4(sB + boff, b4);
#pragma unroll
                for (int mt = 0; mt < 2; mt++) {
                    mma16816(acc[mt][2 * ng],     ah[mt], b4[0], b4[1]);
                    mma16816(acc[mt][2 * ng + 1], ah[mt], b4[2], b4[3]);
                    mma16816(acc[mt][2 * ng],     al[mt], b4[0], b4[1]);
                    mma16816(acc[mt][2 * ng + 1], al[mt], b4[2], b4[3]);
                }
            }
        }
    }

    // epilogue
#pragma unroll
    for (int mt = 0; mt < 2; mt++) {
        int r0 = m0 + wm + mt * 16 + (lane >> 2);
#pragma unroll
        for (int nt = 0; nt < 4; nt++) {
            int col = n0 + wn + nt * 8 + (lane & 3) * 2;
#pragma unroll
            for (int h = 0; h < 2; h++) {
                int row = r0 + h * 8;
                float v0 = acc[mt][nt][h * 2], v1 = acc[mt][nt][h * 2 + 1];
                if (g.Bv) { v0 += g.Bv[col]; v1 += g.Bv[col + 1]; }
                if (g.act == 1)      { v0 = fmaxf(v0, 0.f); v1 = fmaxf(v1, 0.f); }
                else if (g.act == 2) { v0 = geluf(v0); v1 = geluf(v1); }
                if (g.res) {
                    v0 += g.res[(size_t)row * DIM + col];
                    v1 += g.res[(size_t)row * DIM + col + 1];
                }
                v0 *= g.scale; v1 *= g.scale;
                size_t p = (size_t)row * DIM + col;
                *(float2*)(g.out + p) = make_float2(v0, v1);
                if (g.oh) {
                    __half h0, l0, h1, l1;
                    split_h(v0, h0, l0); split_h(v1, h1, l1);
                    *(uint32_t*)(g.oh + p) =
                        (uint32_t)__half_as_ushort(h0) | ((uint32_t)__half_as_ushort(h1) << 16);
                    *(uint32_t*)(g.ol + p) =
                        (uint32_t)__half_as_ushort(l0) | ((uint32_t)__half_as_ushort(l1) << 16);
                }
            }
        }
    }
}

// ---------------------------------------------------------------------------
// Flash attention (act0): O = softmax(QK^T/8) V  -> NX0 hi/lo
// grid (8, 32), 256 thr (8 warps), warp w owns rows w*16..w*16+15
// smem: Qh 16K | Ql 16K | K 8K | V 8K = 48KB
// ---------------------------------------------------------------------------
__global__ void __launch_bounds__(256) flash_k(int node) {
    if (g_nr[node].act != 0) return;
    extern __shared__ char smem[];
    uint32_t sQ_H = smem_u32(smem);
    uint32_t sQ_L = sQ_H + 16384;
    uint32_t sK = sQ_H + 32768, sV = sQ_H + 40960;

    int t = threadIdx.x, lane = t & 31, wid = t >> 5;
    int bh = blockIdx.y, b = bh >> 3, head = bh & 7;
    int i0 = blockIdx.x * 128;

    const float* Q = g_h0 + (size_t)b * SLEN * DIM + head * DH;
    const float* K = g_h1 + (size_t)b * SLEN * DIM + head * DH;
    const float* V = g_h2 + (size_t)b * SLEN * DIM + head * DH;

    // load Q tile 128x64 -> hi/lo (once)
    {
        int lrow = t >> 1, lcb = (t & 1) * 32;
        const float* qr = Q + (size_t)(i0 + lrow) * DIM + lcb;
#pragma unroll
        for (int i = 0; i < 8; i++) {
            uint2 hi, lo; cvt_hilo(*(const float4*)(qr + i * 4), hi, lo);
            uint32_t off = SW128((uint32_t)(lrow * 128 + (lcb + i * 4) * 2));
            *(uint2*)(smem + off) = hi;
            *(uint2*)(smem + 16384 + off) = lo;
        }
    }

    float O[8][4];
#pragma unroll
    for (int d = 0; d < 8; d++)
#pragma unroll
        for (int l = 0; l < 4; l++) O[d][l] = 0.f;
    float mrow[2] = {-3.4e38f, -3.4e38f};
    float lrow_[2] = {0.f, 0.f};

    int a_r = (lane & 15), a_k8 = (lane >> 4) << 3;
    int b_n = ((lane & 16) >> 1) + (lane & 7), b_k8 = (lane & 8);
    int v_k = (lane & 15), v_n8 = (lane & 16) >> 1;
    int kvrow = t >> 2, kvcb = (t & 3) * 16;

    for (int jc = 0; jc < 16; jc++) {
        int j0 = jc * 64;
        {
            const float* kr = K + (size_t)(j0 + kvrow) * DIM + kvcb;
            const float* vr = V + (size_t)(j0 + kvrow) * DIM + kvcb;
#pragma unroll
            for (int i = 0; i < 4; i++) {
                uint32_t off = SW128((uint32_t)(kvrow * 128 + (kvcb + i * 4) * 2));
                *(uint2*)(smem + 32768 + off) = cvt_h(*(const float4*)(kr + i * 4));
                *(uint2*)(smem + 40960 + off) = cvt_h(*(const float4*)(vr + i * 4));
            }
        }
        __syncthreads();

        // S = Q K^T
        float s[8][4];
#pragma unroll
        for (int j = 0; j < 8; j++)
#pragma unroll
            for (int l = 0; l < 4; l++) s[j][l] = 0.f;
#pragma unroll
        for (int kt = 0; kt < 4; kt++) {
            int kb = kt * 16;
            uint32_t qh[4], ql[4];
            uint32_t qoff = SW128((uint32_t)((wid * 16 + a_r) * 128 + (kb + a_k8) * 2));
            ldm4(sQ_H + qoff, qh);
            ldm4(sQ_L + qoff, ql);
#pragma unroll
            for (int ng = 0; ng < 4; ng++) {
                uint32_t boff = SW128((uint32_t)((ng * 16 + b_n) * 128 + (kb + b_k8) * 2));
                uint32_t k4[4];
                ldm4(sK + boff, k4);
                mma16816(s[2 * ng],     qh, k4[0], k4[1]);
                mma16816(s[2 * ng + 1], qh, k4[2], k4[3]);
                mma16816(s[2 * ng],     ql, k4[0], k4[1]);
                mma16816(s[2 * ng + 1], ql, k4[2], k4[3]);
            }
        }
#pragma unroll
        for (int j = 0; j < 8; j++)
#pragma unroll
            for (int l = 0; l < 4; l++) s[j][l] *= 0.125f;

        // online softmax per row-half
#pragma unroll
        for (int h = 0; h < 2; h++) {
            float mj = -3.4e38f;
#pragma unroll
            for (int j = 0; j < 8; j++) mj = fmaxf(mj, fmaxf(s[j][h * 2], s[j][h * 2 + 1]));
            mj = fmaxf(mj, __shfl_xor_sync(0xffffffffu, mj, 1));
            mj = fmaxf(mj, __shfl_xor_sync(0xffffffffu, mj, 2));
            float mnew = fmaxf(mrow[h], mj);
            float alpha = expf(mrow[h] - mnew);
            float ps = 0.f;
#pragma unroll
            for (int j = 0; j < 8; j++) {
                s[j][h * 2]     = expf(s[j][h * 2] - mnew);
                s[j][h * 2 + 1] = expf(s[j][h * 2 + 1] - mnew);
                ps += s[j][h * 2] + s[j][h * 2 + 1];
            }
            ps += __shfl_xor_sync(0xffffffffu, ps, 1);
            ps += __shfl_xor_sync(0xffffffffu, ps, 2);
            lrow_[h] = lrow_[h] * alpha + ps;
            mrow[h] = mnew;
#pragma unroll
            for (int d = 0; d < 8; d++) {
                O[d][h * 2]     *= alpha;
                O[d][h * 2 + 1] *= alpha;
            }
        }

        // O += P V ; P split hi/lo, V single
#pragma unroll
        for (int g4 = 0; g4 < 4; g4++) {
            uint32_t ah[4], al[4];
            {
                uint2 hi, lo;
                cvt_hilo(make_float4(s[2 * g4][0], s[2 * g4][1], s[2 * g4][2], s[2 * g4][3]), hi, lo);
                ah[0] = hi.x; ah[1] = hi.y; al[0] = lo.x; al[1] = lo.y;
                cvt_hilo(make_float4(s[2 * g4 + 1][0], s[2 * g4 + 1][1], s[2 * g4 + 1][2], s[2 * g4 + 1][3]), hi, lo);
                ah[2] = hi.x; ah[3] = hi.y; al[2] = lo.x; al[3] = lo.y;
            }
            int kb = g4 * 16;
#pragma unroll
            for (int ng = 0; ng < 4; ng++) {
                uint32_t boff = SW128((uint32_t)((kb + v_k) * 128 + (ng * 16 + v_n8) * 2));
                uint32_t v4[4];
                ldm4t(sV + boff, v4);
                mma16816(O[2 * ng],     ah, v4[0], v4[1]);
                mma16816(O[2 * ng + 1], ah, v4[2], v4[3]);
                mma16816(O[2 * ng],     al, v4[0], v4[1]);
                mma16816(O[2 * ng + 1], al, v4[2], v4[3]);
            }
        }
        __syncthreads();
    }

    // normalize + write -> NX0 hi/lo
    float inv0 = 1.0f / lrow_[0], inv1 = 1.0f / lrow_[1];
    __half* Oh = g_NXh + ((size_t)b * SLEN) * DIM + head * DH;
    __half* Ol = g_NXl + ((size_t)b * SLEN) * DIM + head * DH;
    int r0 = i0 + wid * 16 + (lane >> 2);
#pragma unroll
    for (int d = 0; d < 8; d++) {
        int col = d * 8 + (lane & 3) * 2;
#pragma unroll
        for (int h = 0; h < 2; h++) {
            int row = r0 + h * 8;
            float inv = h ? inv1 : inv0;
            float v0 = O[d][h * 2] * inv, v1 = O[d][h * 2 + 1] * inv;
            __half h0, l0, h1, l1;
            split_h(v0, h0, l0); split_h(v1, h1, l1);
            size_t p = (size_t)row * DIM + col;
            *(uint32_t*)(Oh + p) =
                (uint32_t)__half_as_ushort(h0) | ((uint32_t)__half_as_ushort(h1) << 16);
            *(uint32_t*)(Ol + p) =
                (uint32_t)__half_as_ushort(l0) | ((uint32_t)__half_as_ushort(l1) << 16);
        }
    }
}

// combine (act1: h0*h1 ; act3: relu(h0+h1+h2)) -> NX0 hi/lo ; float4
__global__ void combine_k(int node) {
    int a = g_nr[node].act;
    if (a != 1 && a != 3) return;
    size_t stride = (size_t)gridDim.x * blockDim.x;
    for (size_t p4 = (size_t)blockIdx.x * blockDim.x + threadIdx.x; p4 < (size_t)(MS / 4); p4 += stride) {
        size_t p = p4 * 4;
        float4 a4 = *(const float4*)(g_h0 + p);
        float4 b4 = *(const float4*)(g_h1 + p);
        float4 y4;
        if (a == 1) {
            y4 = make_float4(a4.x * b4.x, a4.y * b4.y, a4.z * b4.z, a4.w * b4.w);
        } else {
            float4 c4 = *(const float4*)(g_h2 + p);
            y4 = make_float4(fmaxf(a4.x + b4.x + c4.x, 0.f), fmaxf(a4.y + b4.y + c4.y, 0.f),
                             fmaxf(a4.z + b4.z + c4.z, 0.f), fmaxf(a4.w + b4.w + c4.w, 0.f));
        }
        uint2 hi, lo; cvt_hilo(y4, hi, lo);
        *(uint2*)(g_NXh + p) = hi;
        *(uint2*)(g_NXl + p) = lo;
    }
}

// finish (acts 2,4,5,6,7) warp-per-row, float4 ; grid 512
__global__ void finish_k(int node) {
    NR r = g_nr[node];
    int a = r.act;
    if (a == 0 || a == 1 || a == 3) return;
    int warp = threadIdx.x >> 5, lane = threadIdx.x & 31;
    int row = blockIdx.x * 8 + warp;
    size_t rb = (size_t)row * DIM;
    int c0 = lane * 4;
    float* out = g_outs + (size_t)node * MS + rb;
    if (a == 4 || a == 5 || a == 6) {
#pragma unroll
        for (int i = 0; i < 4; i++) {
            size_t p = rb + c0 + i * 128;
            float4 q4 = *(const float4*)(g_qv + p);
            float4 y4;
            if (a == 4) {
                float4 k4 = *(const float4*)(g_kv + p);
                float4 v4 = *(const float4*)(g_vv + p);
                y4 = make_float4(q4.x * sigmoidf_(k4.x) + v4.x, q4.y * sigmoidf_(k4.y) + v4.y,
                                 q4.z * sigmoidf_(k4.z) + v4.z, q4.w * sigmoidf_(k4.w) + v4.w);
            } else if (a == 5) {
                float4 h4 = *(const float4*)(g_h1 + p);
                y4 = make_float4(q4.x + h4.x, q4.y + h4.y, q4.z + h4.z, q4.w + h4.w);
            } else {
                float4 k4 = *(const float4*)(g_kv + p);
                y4 = make_float4(q4.x + k4.x, q4.y + k4.y, q4.z + k4.z, q4.w + k4.w);
            }
            *(float4*)(out + c0 + i * 128) =
                make_float4(r.aw * y4.x, r.aw * y4.y, r.aw * y4.z, r.aw * y4.w);
        }
        return;
    }
    // a == 2 or 7: LN
    float4 v4[4];
#pragma unroll
    for (int i = 0; i < 4; i++) {
        size_t p = rb + c0 + i * 128;
        float4 q4 = *(const float4*)(g_qv + p);
        if (a == 2) {
            float4 k4 = *(const float4*)(g_kv + p);
            float4 w4 = *(const float4*)(g_vv + p);
            v4[i] = make_float4(q4.x + k4.x + w4.x, q4.y + k4.y + w4.y,
                                q4.z + k4.z + w4.z, q4.w + k4.w + w4.w);
        } else {
            v4[i] = q4;
        }
    }
    float s = 0.f;
#pragma unroll
    for (int i = 0; i < 4; i++) s += v4[i].x + v4[i].y + v4[i].z + v4[i].w;
    float mean = wsum(s) * (1.0f / 512.0f);
    float q = 0.f;
#pragma unroll
    for (int i = 0; i < 4; i++) {
        float dx = v4[i].x - mean, dy = v4[i].y - mean, dz = v4[i].z - mean, dw = v4[i].w - mean;
        q += dx * dx + dy * dy + dz * dz + dw * dw;
    }
    float inv = rsqrtf(wsum(q) * (1.0f / 512.0f) + EPSLN);
    const float* gm = g_ptrs.node_g + node * DIM;
    const float* bt = g_ptrs.node_beta + node * DIM;
#pragma unroll
    for (int i = 0; i < 4; i++) {
        float4 g4 = *(const float4*)(gm + c0 + i * 128);
        float4 b4 = *(const float4*)(bt + c0 + i * 128);
        *(float4*)(out + c0 + i * 128) = make_float4(
            r.aw * ((v4[i].x - mean) * inv * g4.x + b4.x),
            r.aw * ((v4[i].y - mean) * inv * g4.y + b4.y),
            r.aw * ((v4[i].z - mean) * inv * g4.z + b4.z),
            r.aw * ((v4[i].w - mean) * inv * g4.w + b4.w));
    }
}

// final: sum unprocessed + LN ; warp-per-row, float4 ; grid 512
__global__ void final_k(float* dout) {
    int warp = threadIdx.x >> 5, lane = threadIdx.x & 31;
    int row = blockIdx.x * 8 + warp;
    size_t rb = (size_t)row * DIM;
    int c0 = lane * 4;
    float4 v4[4];
#pragma unroll
    for (int i = 0; i < 4; i++) v4[i] = make_float4(0.f, 0.f, 0.f, 0.f);
    for (int c = 0; c < 8; c++) {
        if (!g_processed[c]) {
            const float* o = g_outs + (size_t)c * MS + rb;
#pragma unroll
            for (int i = 0; i < 4; i++) {
                float4 t4 = *(const float4*)(o + c0 + i * 128);
                v4[i].x += t4.x; v4[i].y += t4.y; v4[i].z += t4.z; v4[i].w += t4.w;
            }
        }
    }
    float s = 0.f;
#pragma unroll
    for (int i = 0; i < 4; i++) s += v4[i].x + v4[i].y + v4[i].z + v4[i].w;
    float mean = wsum(s) * (1.0f / 512.0f);
    float q = 0.f;
#pragma unroll
    for (int i = 0; i < 4; i++) {
        float dx = v4[i].x - mean, dy = v4[i].y - mean, dz = v4[i].z - mean, dw = v4[i].w - mean;
        q += dx * dx + dy * dy + dz * dz + dw * dw;
    }
    float inv = rsqrtf(wsum(q) * (1.0f / 512.0f) + EPSLN);
#pragma unroll
    for (int i = 0; i < 4; i++) {
        float4 g4 = *(const float4*)(g_ptrs.out_g + c0 + i * 128);
        float4 b4 = *(const float4*)(g_ptrs.out_beta + c0 + i * 128);
        *(float4*)(dout + rb + c0 + i * 128) = make_float4(
            (v4[i].x - mean) * inv * g4.x + b4.x,
            (v4[i].y - mean) * inv * g4.y + b4.y,
            (v4[i].z - mean) * inv * g4.z + b4.z,
            (v4[i].w - mean) * inv * g4.w + b4.w);
    }
}

// ---------------------------------------------------------------------------
// Launch
// ---------------------------------------------------------------------------
extern "C" void kernel_launch(void* const* d_in, const int* in_sizes, int n_in,
                              void* d_out, int out_size) {
    (void)in_sizes; (void)n_in; (void)out_size;
    cudaFuncSetAttribute(gemm_mma, cudaFuncAttributeMaxDynamicSharedMemorySize, GEMM_SMEM);
    cudaFuncSetAttribute(flash_k,  cudaFuncAttributeMaxDynamicSharedMemorySize, 49152);

    setup_k<<<1, 1>>>(
        (const float*)d_in[0],  (const float*)d_in[1],  (const float*)d_in[2],
        (const float*)d_in[3],  (const float*)d_in[4],  (const float*)d_in[5],
        (const float*)d_in[6],  (const float*)d_in[7],  (const float*)d_in[8],
        (const float*)d_in[9],  (const float*)d_in[10], (const float*)d_in[11],
        (const float*)d_in[12], (const float*)d_in[13]);
    routing_k<<<1, 1>>>();
    conv_w_all<<<dim3(16, 16, 56), dim3(32, 8)>>>();

    for (int c = 0; c < 8; c++) {
        edge_pre<<<dim3(512, 3), 256>>>(c);
        gemm_mma<<<dim3(4, 32, 3), 512, GEMM_SMEM>>>(c, 0);   // edge q/k/v
        node_prep<<<512, 256>>>(c);
        gemm_mma<<<dim3(4, 32, 3), 512, GEMM_SMEM>>>(c, 3);   // node j0/j1/j2
        flash_k<<<dim3(8, 32), 256, 49152>>>(c);
        combine_k<<<2048, 256>>>(c);
        gemm_mma<<<dim3(4, 32, 1), 512, GEMM_SMEM>>>(c, 6);   // node j3
        finish_k<<<512, 256>>>(c);
    }
    final_k<<<512, 256>>>((float*)d_out);
}